// round 10
// baseline (speedup 1.0000x reference)
#include <cuda_runtime.h>
#include <cuda_bf16.h>
#include <mma.h>
#include <math.h>
#include <stdint.h>

using namespace nvcuda;

#define Bq   16
#define Nq   1024
#define Cq   768
#define Hq   12
#define HD   64
#define BH   (Bq*Hq)        // 192
#define MROWS (Bq*Nq)       // 16384

// ---- scratch (no allocs allowed) ----
__device__ float g_q[BH * Nq * HD];     // [bh][tok][d]
__device__ float g_k[BH * Nq * HD];
__device__ float g_v[BH * Nq * HD];
__device__ float g_att[MROWS * Cq];     // [b*N + tok][h*64 + d]

__device__ __forceinline__ void split_pack(float x0, float x1,
                                           uint32_t& hi, uint32_t& lo) {
    __nv_bfloat16 h0 = __float2bfloat16_rn(x0);
    __nv_bfloat16 h1 = __float2bfloat16_rn(x1);
    __nv_bfloat16 l0 = __float2bfloat16_rn(x0 - __bfloat162float(h0));
    __nv_bfloat16 l1 = __float2bfloat16_rn(x1 - __bfloat162float(h1));
    hi = (uint32_t)__bfloat16_as_ushort(h0) | ((uint32_t)__bfloat16_as_ushort(h1) << 16);
    lo = (uint32_t)__bfloat16_as_ushort(l0) | ((uint32_t)__bfloat16_as_ushort(l1) << 16);
}

// e^(x/8) on the FMA/ALU pipes (no MUFU). x <= 0 expected; clamped.
__device__ __forceinline__ float fexp8(float x) {
    const float L2E8 = 0.18033688f;           // log2(e)/8
    x = fmaxf(x, -640.0f);
    float t = fmaf(x, L2E8, 12582912.0f);     // round-to-nearest int (1.5*2^23)
    float i = t - 12582912.0f;
    float f = fmaf(x, L2E8, -i);              // frac in [-0.5, 0.5]
    float p =            1.3298820e-3f;
    p = fmaf(p, f, 9.6181291e-3f);
    p = fmaf(p, f, 5.5504109e-2f);
    p = fmaf(p, f, 2.4022650e-1f);
    p = fmaf(p, f, 6.9314718e-1f);
    p = fmaf(p, f, 1.0f);
    int r = __float_as_int(p) + ((__float_as_int(t) - 0x4B400000) << 23);
    return __int_as_float(r);
}

// =====================================================================
// bf16x3 WMMA GEMMs (non-templated) — unchanged from round 9 (passing)
// =====================================================================
#define KCH  32
#define PADK 40
#define T_M  (128 * PADK * 2)
#define OFF_AHI 0
#define OFF_ALO (T_M)
#define OFF_BHI (2 * T_M)
#define OFF_BLO (3 * T_M)
#define MM_SMEM (4 * T_M)               // 40960 bytes static

__global__ __launch_bounds__(256) void qkv_wmma(const float* __restrict__ A,
                                                const float* __restrict__ W,
                                                const float* __restrict__ bias)
{
    __shared__ __align__(16) char smem[MM_SMEM];
    const int NN = 3 * Cq;
    int tid  = threadIdx.x;
    int lane = tid & 31;
    int wid  = tid >> 5;
    int wm   = wid >> 2;
    int wn   = wid & 3;

    const int m0 = blockIdx.y * 128;
    const int n0 = blockIdx.x * 128;

    wmma::fragment<wmma::accumulator, 16, 16, 16, float> acc[4][2];
    #pragma unroll
    for (int mi = 0; mi < 4; mi++)
        #pragma unroll
        for (int ni = 0; ni < 2; ni++)
            wmma::fill_fragment(acc[mi][ni], 0.0f);

    const __nv_bfloat16* Ah = (const __nv_bfloat16*)(smem + OFF_AHI);
    const __nv_bfloat16* Bh = (const __nv_bfloat16*)(smem + OFF_BHI);

    for (int ch = 0; ch < 768 / KCH; ch++) {
        const int k0c = ch * KCH;
        if (ch) __syncthreads();

        #pragma unroll
        for (int it = 0; it < 8; it++) {
            int idx = tid + it * 256;
            int m  = idx >> 4;
            int kp = idx & 15;
            float2 v = *(const float2*)(A + (size_t)(m0 + m) * 768 + k0c + 2 * kp);
            uint32_t hi, lo;
            split_pack(v.x, v.y, hi, lo);
            uint32_t off = (uint32_t)(m * PADK + 2 * kp) * 2;
            *(uint32_t*)(smem + OFF_AHI + off) = hi;
            *(uint32_t*)(smem + OFF_ALO + off) = lo;
        }
        #pragma unroll
        for (int it = 0; it < 8; it++) {
            int idx = tid + it * 256;
            int n  = idx & 127;
            int kp = idx >> 7;
            float w0 = W[(size_t)(k0c + 2 * kp)     * NN + n0 + n];
            float w1 = W[(size_t)(k0c + 2 * kp + 1) * NN + n0 + n];
            uint32_t hi, lo;
            split_pack(w0, w1, hi, lo);
            uint32_t off = (uint32_t)(n * PADK + 2 * kp) * 2;
            *(uint32_t*)(smem + OFF_BHI + off) = hi;
            *(uint32_t*)(smem + OFF_BLO + off) = lo;
        }
        __syncthreads();

        #pragma unroll
        for (int ks = 0; ks < 2; ks++) {
            const int kk = ks * 16;
            wmma::fragment<wmma::matrix_b, 16, 16, 16, __nv_bfloat16, wmma::col_major> fbh[2], fbl[2];
            #pragma unroll
            for (int ni = 0; ni < 2; ni++) {
                const __nv_bfloat16* bp = Bh + (wn * 32 + ni * 16) * PADK + kk;
                wmma::load_matrix_sync(fbh[ni], bp, PADK);
                wmma::load_matrix_sync(fbl[ni], bp + (T_M / 2), PADK);
            }
            #pragma unroll
            for (int mi = 0; mi < 4; mi++) {
                wmma::fragment<wmma::matrix_a, 16, 16, 16, __nv_bfloat16, wmma::row_major> fah, fal;
                const __nv_bfloat16* ap = Ah + (wm * 64 + mi * 16) * PADK + kk;
                wmma::load_matrix_sync(fah, ap, PADK);
                wmma::load_matrix_sync(fal, ap + (T_M / 2), PADK);
                #pragma unroll
                for (int ni = 0; ni < 2; ni++) {
                    wmma::mma_sync(acc[mi][ni], fah, fbh[ni], acc[mi][ni]);
                    wmma::mma_sync(acc[mi][ni], fah, fbl[ni], acc[mi][ni]);
                    wmma::mma_sync(acc[mi][ni], fal, fbh[ni], acc[mi][ni]);
                }
            }
        }
    }

    __syncthreads();
    float* patch = (float*)smem + wid * (16 * 20);
    const int r_loc = lane >> 1;
    const int c_loc = (lane & 1) * 8;

    #pragma unroll
    for (int mi = 0; mi < 4; mi++) {
        #pragma unroll
        for (int ni = 0; ni < 2; ni++) {
            wmma::store_matrix_sync(patch, acc[mi][ni], 20, wmma::mem_row_major);
            __syncwarp();
            int r  = m0 + wm * 64 + mi * 16 + r_loc;
            int cb = n0 + wn * 32 + ni * 16 + c_loc;
            float vv[8];
            #pragma unroll
            for (int j = 0; j < 8; j++)
                vv[j] = patch[r_loc * 20 + c_loc + j] + bias[cb + j];

            int b_  = r >> 10, tok = r & 1023;
            int s   = cb / Cq;
            int rem = cb - s * Cq;
            int h   = rem >> 6, d = rem & 63;
            float* dst = (s == 0) ? g_q : ((s == 1) ? g_k : g_v);
            float* dbase = dst + (((b_ * Hq + h) << 16) + (tok << 6) + d);
            #pragma unroll
            for (int j = 0; j < 8; j += 2)
                *(float2*)(dbase + j) = make_float2(vv[j], vv[j + 1]);
            __syncwarp();
        }
    }
}

__global__ __launch_bounds__(256) void proj_wmma(const float* __restrict__ W,
                                                 const float* __restrict__ bias,
                                                 float* __restrict__ out)
{
    __shared__ __align__(16) char smem[MM_SMEM];
    const int NN = Cq;
    const float* A = g_att;
    int tid  = threadIdx.x;
    int lane = tid & 31;
    int wid  = tid >> 5;
    int wm   = wid >> 2;
    int wn   = wid & 3;

    const int m0 = blockIdx.y * 128;
    const int n0 = blockIdx.x * 128;

    wmma::fragment<wmma::accumulator, 16, 16, 16, float> acc[4][2];
    #pragma unroll
    for (int mi = 0; mi < 4; mi++)
        #pragma unroll
        for (int ni = 0; ni < 2; ni++)
            wmma::fill_fragment(acc[mi][ni], 0.0f);

    const __nv_bfloat16* Ah = (const __nv_bfloat16*)(smem + OFF_AHI);
    const __nv_bfloat16* Bh = (const __nv_bfloat16*)(smem + OFF_BHI);

    for (int ch = 0; ch < 768 / KCH; ch++) {
        const int k0c = ch * KCH;
        if (ch) __syncthreads();

        #pragma unroll
        for (int it = 0; it < 8; it++) {
            int idx = tid + it * 256;
            int m  = idx >> 4;
            int kp = idx & 15;
            float2 v = *(const float2*)(A + (size_t)(m0 + m) * 768 + k0c + 2 * kp);
            uint32_t hi, lo;
            split_pack(v.x, v.y, hi, lo);
            uint32_t off = (uint32_t)(m * PADK + 2 * kp) * 2;
            *(uint32_t*)(smem + OFF_AHI + off) = hi;
            *(uint32_t*)(smem + OFF_ALO + off) = lo;
        }
        #pragma unroll
        for (int it = 0; it < 8; it++) {
            int idx = tid + it * 256;
            int n  = idx & 127;
            int kp = idx >> 7;
            float w0 = W[(size_t)(k0c + 2 * kp)     * NN + n0 + n];
            float w1 = W[(size_t)(k0c + 2 * kp + 1) * NN + n0 + n];
            uint32_t hi, lo;
            split_pack(w0, w1, hi, lo);
            uint32_t off = (uint32_t)(n * PADK + 2 * kp) * 2;
            *(uint32_t*)(smem + OFF_BHI + off) = hi;
            *(uint32_t*)(smem + OFF_BLO + off) = lo;
        }
        __syncthreads();

        #pragma unroll
        for (int ks = 0; ks < 2; ks++) {
            const int kk = ks * 16;
            wmma::fragment<wmma::matrix_b, 16, 16, 16, __nv_bfloat16, wmma::col_major> fbh[2], fbl[2];
            #pragma unroll
            for (int ni = 0; ni < 2; ni++) {
                const __nv_bfloat16* bp = Bh + (wn * 32 + ni * 16) * PADK + kk;
                wmma::load_matrix_sync(fbh[ni], bp, PADK);
                wmma::load_matrix_sync(fbl[ni], bp + (T_M / 2), PADK);
            }
            #pragma unroll
            for (int mi = 0; mi < 4; mi++) {
                wmma::fragment<wmma::matrix_a, 16, 16, 16, __nv_bfloat16, wmma::row_major> fah, fal;
                const __nv_bfloat16* ap = Ah + (wm * 64 + mi * 16) * PADK + kk;
                wmma::load_matrix_sync(fah, ap, PADK);
                wmma::load_matrix_sync(fal, ap + (T_M / 2), PADK);
                #pragma unroll
                for (int ni = 0; ni < 2; ni++) {
                    wmma::mma_sync(acc[mi][ni], fah, fbh[ni], acc[mi][ni]);
                    wmma::mma_sync(acc[mi][ni], fah, fbl[ni], acc[mi][ni]);
                    wmma::mma_sync(acc[mi][ni], fal, fbh[ni], acc[mi][ni]);
                }
            }
        }
    }

    __syncthreads();
    float* patch = (float*)smem + wid * (16 * 20);
    const int r_loc = lane >> 1;
    const int c_loc = (lane & 1) * 8;

    #pragma unroll
    for (int mi = 0; mi < 4; mi++) {
        #pragma unroll
        for (int ni = 0; ni < 2; ni++) {
            wmma::store_matrix_sync(patch, acc[mi][ni], 20, wmma::mem_row_major);
            __syncwarp();
            int r  = m0 + wm * 64 + mi * 16 + r_loc;
            int cb = n0 + wn * 32 + ni * 16 + c_loc;
            float* obase = out + (size_t)r * NN + cb;
            #pragma unroll
            for (int j = 0; j < 8; j += 2) {
                float v0 = patch[r_loc * 20 + c_loc + j]     + bias[cb + j];
                float v1 = patch[r_loc * 20 + c_loc + j + 1] + bias[cb + j + 1];
                *(float2*)(obase + j) = make_float2(v0, v1);
            }
            __syncwarp();
        }
    }
}

// =====================================================================
// RoPE — unchanged, passing.
// =====================================================================
__global__ void rope_kernel(const int* __restrict__ pos_h,
                            const int* __restrict__ pos_w)
{
    int idx = blockIdx.x * blockDim.x + threadIdx.x;
    int j    = idx & 15;
    int half = (idx >> 4) & 1;
    int tok  = (idx >> 5) & 1023;
    int rest = idx >> 15;           // 0..383
    if (rest >= 2 * BH) return;
    int bh   = rest % BH;
    int tens = rest / BH;           // 0=q, 1=k
    int b_ = bh / Hq;
    int pos = half ? pos_w[b_ * Nq + tok] : pos_h[b_ * Nq + tok];
    float fp = (float)pos;
    float* base = (tens ? g_k : g_q) + (bh << 16) + (tok << 6) + half * 32;
    float t0 = base[j], t1 = base[j + 16];
    float L = logf(10000.0f);
    float inv0 = expf(-(float)(j >> 1)       / 16.0f * L);
    float inv1 = expf(-(float)(8 + (j >> 1)) / 16.0f * L);
    float s0, c0, s1, c1;
    sincosf(fp * inv0, &s0, &c0);
    sincosf(fp * inv1, &s1, &c1);
    base[j]      = t0 * c0 - t1 * s0;
    base[j + 16] = t1 * c1 + t0 * s1;
}

// =====================================================================
// WMMA flash attention.  CTA = (128 q-rows, bh). 16 key-tiles of 64.
// bf16x3 for S = Q@K^T and O += P@V; fp32 softmax with FMA-pipe exp.
// 8 warps: 2(m: 64 rows) x 4(n: 16 cols). Dynamic smem 181,760 B.
// =====================================================================
#define PD     72                         // bf16 row pitch (Q/K/V/P)
#define SW     68                         // fp32 row pitch (S/O)
#define AOFF_QHI 0
#define AOFF_QLO (AOFF_QHI + 128*PD*2)    // 18432 each
#define AOFF_KHI (AOFF_QLO + 128*PD*2)    // K tile 64 x PD
#define AOFF_KLO (AOFF_KHI + 64*PD*2)
#define AOFF_VHI (AOFF_KLO + 64*PD*2)
#define AOFF_VLO (AOFF_VHI + 64*PD*2)
#define AOFF_PHI (AOFF_VLO + 64*PD*2)     // P 128 x PD
#define AOFF_PLO (AOFF_PHI + 128*PD*2)
#define AOFF_S   (AOFF_PLO + 128*PD*2)    // S / PV scratch: 128 x SW fp32
#define AOFF_O   (AOFF_S   + 128*SW*4)
#define AOFF_ST  (AOFF_O   + 128*SW*4)    // mrow, lrow, arow: 3 x 128 fp32
#define ATTN2_SMEM (AOFF_ST + 3*128*4)    // 181,760 bytes

__global__ __launch_bounds__(256) void attn_wmma()
{
    extern __shared__ char sm[];
    __nv_bfloat16* Qhi = (__nv_bfloat16*)(sm + AOFF_QHI);
    __nv_bfloat16* Qlo = (__nv_bfloat16*)(sm + AOFF_QLO);
    __nv_bfloat16* Khi = (__nv_bfloat16*)(sm + AOFF_KHI);
    __nv_bfloat16* Klo = (__nv_bfloat16*)(sm + AOFF_KLO);
    __nv_bfloat16* Vhi = (__nv_bfloat16*)(sm + AOFF_VHI);
    __nv_bfloat16* Vlo = (__nv_bfloat16*)(sm + AOFF_VLO);
    __nv_bfloat16* Phi = (__nv_bfloat16*)(sm + AOFF_PHI);
    __nv_bfloat16* Plo = (__nv_bfloat16*)(sm + AOFF_PLO);
    float* S    = (float*)(sm + AOFF_S);
    float* O    = (float*)(sm + AOFF_O);
    float* mrow = (float*)(sm + AOFF_ST);
    float* lrow = mrow + 128;
    float* arow = lrow + 128;

    const int tid = threadIdx.x;
    const int wid = tid >> 5;
    const int wm  = wid >> 2;       // 0..1
    const int wn  = wid & 3;        // 0..3
    const int bh  = blockIdx.y;
    const int q0  = blockIdx.x * 128;
    const float* Qg = g_q + ((size_t)bh << 16);
    const float* Kg = g_k + ((size_t)bh << 16);
    const float* Vg = g_v + ((size_t)bh << 16);

    // ---- load + split Q tile [128][64]
    #pragma unroll
    for (int it = 0; it < 16; it++) {
        int idx = tid + it * 256;       // 0..4095 float2 pairs
        int m  = idx >> 5;
        int kp = idx & 31;
        float2 v = *(const float2*)(Qg + (size_t)(q0 + m) * 64 + 2 * kp);
        uint32_t hi, lo;
        split_pack(v.x, v.y, hi, lo);
        *(uint32_t*)((char*)Qhi + (m * PD + 2 * kp) * 2) = hi;
        *(uint32_t*)((char*)Qlo + (m * PD + 2 * kp) * 2) = lo;
    }
    for (int idx = tid; idx < 128 * SW; idx += 256) O[idx] = 0.0f;
    if (tid < 128) { mrow[tid] = -INFINITY; lrow[tid] = 0.0f; }
    __syncthreads();

    for (int t = 0; t < 16; t++) {
        const int kt0 = t * 64;
        // ---- load + split K, V tiles [64][64]
        #pragma unroll
        for (int it = 0; it < 8; it++) {
            int idx = tid + it * 256;   // 0..2047 pairs
            int r  = idx >> 5;
            int kp = idx & 31;
            float2 v = *(const float2*)(Kg + (size_t)(kt0 + r) * 64 + 2 * kp);
            uint32_t hi, lo;
            split_pack(v.x, v.y, hi, lo);
            *(uint32_t*)((char*)Khi + (r * PD + 2 * kp) * 2) = hi;
            *(uint32_t*)((char*)Klo + (r * PD + 2 * kp) * 2) = lo;
        }
        #pragma unroll
        for (int it = 0; it < 8; it++) {
            int idx = tid + it * 256;
            int r  = idx >> 5;
            int kp = idx & 31;
            float2 v = *(const float2*)(Vg + (size_t)(kt0 + r) * 64 + 2 * kp);
            uint32_t hi, lo;
            split_pack(v.x, v.y, hi, lo);
            *(uint32_t*)((char*)Vhi + (r * PD + 2 * kp) * 2) = hi;
            *(uint32_t*)((char*)Vlo + (r * PD + 2 * kp) * 2) = lo;
        }
        __syncthreads();

        // ---- S = Q @ K^T (bf16x3), warp covers [wm*64..+64] x [wn*16..+16]
        {
            wmma::fragment<wmma::matrix_b, 16, 16, 16, __nv_bfloat16, wmma::col_major> kbh[4], kbl[4];
            #pragma unroll
            for (int ks = 0; ks < 4; ks++) {
                wmma::load_matrix_sync(kbh[ks], Khi + (wn * 16) * PD + ks * 16, PD);
                wmma::load_matrix_sync(kbl[ks], Klo + (wn * 16) * PD + ks * 16, PD);
            }
            #pragma unroll
            for (int mi = 0; mi < 4; mi++) {
                wmma::fragment<wmma::accumulator, 16, 16, 16, float> acc;
                wmma::fill_fragment(acc, 0.0f);
                #pragma unroll
                for (int ks = 0; ks < 4; ks++) {
                    wmma::fragment<wmma::matrix_a, 16, 16, 16, __nv_bfloat16, wmma::row_major> fah, fal;
                    const __nv_bfloat16* ap = Qhi + (wm * 64 + mi * 16) * PD + ks * 16;
                    wmma::load_matrix_sync(fah, ap, PD);
                    wmma::load_matrix_sync(fal, ap + (AOFF_QLO - AOFF_QHI) / 2, PD);
                    wmma::mma_sync(acc, fah, kbh[ks], acc);
                    wmma::mma_sync(acc, fah, kbl[ks], acc);
                    wmma::mma_sync(acc, fal, kbh[ks], acc);
                }
                wmma::store_matrix_sync(S + (wm * 64 + mi * 16) * SW + wn * 16,
                                        acc, SW, wmma::mem_row_major);
            }
        }
        __syncthreads();

        // ---- softmax (scale 1/8 folded into fexp8); write P hi/lo
        {
            const int r  = tid >> 1;
            const int hf = tid & 1;
            const float* Srow = S + r * SW + hf * 32;
            float mx = -INFINITY;
            #pragma unroll
            for (int j = 0; j < 32; j++) mx = fmaxf(mx, Srow[j]);
            mx = fmaxf(mx, __shfl_xor_sync(0xffffffffu, mx, 1));
            float mo = mrow[r];
            float mn = fmaxf(mo, mx);
            float al = fexp8(mo - mn);
            uint32_t* Ph = (uint32_t*)((char*)Phi + (r * PD + hf * 32) * 2);
            uint32_t* Pl = (uint32_t*)((char*)Plo + (r * PD + hf * 32) * 2);
            float sum = 0.0f;
            #pragma unroll
            for (int j = 0; j < 16; j++) {
                float p0 = fexp8(Srow[2 * j]     - mn);
                float p1 = fexp8(Srow[2 * j + 1] - mn);
                sum += p0 + p1;
                uint32_t hi, lo;
                split_pack(p0, p1, hi, lo);
                Ph[j] = hi;
                Pl[j] = lo;
            }
            sum += __shfl_xor_sync(0xffffffffu, sum, 1);
            if (hf == 0) {
                mrow[r] = mn;
                arow[r] = al;
                lrow[r] = fmaf(lrow[r], al, sum);
            }
        }
        __syncthreads();

        // ---- PV = P @ V (bf16x3), result into S scratch
        {
            wmma::fragment<wmma::matrix_b, 16, 16, 16, __nv_bfloat16, wmma::row_major> vbh[4], vbl[4];
            #pragma unroll
            for (int ks = 0; ks < 4; ks++) {
                wmma::load_matrix_sync(vbh[ks], Vhi + (ks * 16) * PD + wn * 16, PD);
                wmma::load_matrix_sync(vbl[ks], Vlo + (ks * 16) * PD + wn * 16, PD);
            }
            #pragma unroll
            for (int mi = 0; mi < 4; mi++) {
                wmma::fragment<wmma::accumulator, 16, 16, 16, float> acc;
                wmma::fill_fragment(acc, 0.0f);
                #pragma unroll
                for (int ks = 0; ks < 4; ks++) {
                    wmma::fragment<wmma::matrix_a, 16, 16, 16, __nv_bfloat16, wmma::row_major> pah, pal;
                    const __nv_bfloat16* pp = Phi + (wm * 64 + mi * 16) * PD + ks * 16;
                    wmma::load_matrix_sync(pah, pp, PD);
                    wmma::load_matrix_sync(pal, pp + (AOFF_PLO - AOFF_PHI) / 2, PD);
                    wmma::mma_sync(acc, pah, vbh[ks], acc);
                    wmma::mma_sync(acc, pah, vbl[ks], acc);
                    wmma::mma_sync(acc, pal, vbh[ks], acc);
                }
                wmma::store_matrix_sync(S + (wm * 64 + mi * 16) * SW + wn * 16,
                                        acc, SW, wmma::mem_row_major);
            }
        }
        __syncthreads();

        // ---- O = O * alpha + PV
        #pragma unroll
        for (int it = 0; it < 32; it++) {
            int idx = tid + it * 256;   // 0..8191
            int r = idx >> 6, c = idx & 63;
            O[r * SW + c] = fmaf(O[r * SW + c], arow[r], S[r * SW + c]);
        }
        __syncthreads();
    }

    // ---- normalize and write out
    const int b_ = bh / Hq, h = bh % Hq;
    #pragma unroll
    for (int it = 0; it < 32; it++) {
        int idx = tid + it * 256;
        int r = idx >> 6, c = idx & 63;
        g_att[(size_t)(b_ * Nq + q0 + r) * Cq + h * 64 + c] =
            O[r * SW + c] / lrow[r];
    }
}

// =====================================================================
extern "C" void kernel_launch(void* const* d_in, const int* in_sizes, int n_in,
                              void* d_out, int out_size)
{
    const float* x      = (const float*)d_in[0];
    const float* W_qkv  = (const float*)d_in[1];
    const float* b_qkv  = (const float*)d_in[2];
    const float* W_proj = (const float*)d_in[3];
    const float* b_proj = (const float*)d_in[4];
    const int*   pos_h  = (const int*)d_in[5];
    const int*   pos_w  = (const int*)d_in[6];
    float*       out    = (float*)d_out;

    cudaFuncSetAttribute(attn_wmma,
                         cudaFuncAttributeMaxDynamicSharedMemorySize,
                         (int)ATTN2_SMEM);

    qkv_wmma<<<dim3(18, 128), 256>>>(x, W_qkv, b_qkv);
    rope_kernel<<<(2 * BH * Nq * 32) / 256, 256>>>(pos_h, pos_w);
    attn_wmma<<<dim3(8, 192), 256, ATTN2_SMEM>>>();
    proj_wmma<<<dim3(6, 128), 256>>>(W_proj, b_proj, out);
}

// round 12
// speedup vs baseline: 1.4122x; 1.4122x over previous
#include <cuda_runtime.h>
#include <cuda_bf16.h>
#include <mma.h>
#include <math.h>
#include <stdint.h>

using namespace nvcuda;

#define Bq   16
#define Nq   1024
#define Cq   768
#define Hq   12
#define HD   64
#define BH   (Bq*Hq)        // 192
#define MROWS (Bq*Nq)       // 16384

// ---- scratch (no allocs allowed) ----
__device__ float g_q[BH * Nq * HD];     // [bh][tok][d]
__device__ float g_k[BH * Nq * HD];
__device__ float g_v[BH * Nq * HD];
__device__ float g_att[MROWS * Cq];     // [b*N + tok][h*64 + d]

__device__ __forceinline__ void split_pack(float x0, float x1,
                                           uint32_t& hi, uint32_t& lo) {
    __nv_bfloat16 h0 = __float2bfloat16_rn(x0);
    __nv_bfloat16 h1 = __float2bfloat16_rn(x1);
    __nv_bfloat16 l0 = __float2bfloat16_rn(x0 - __bfloat162float(h0));
    __nv_bfloat16 l1 = __float2bfloat16_rn(x1 - __bfloat162float(h1));
    hi = (uint32_t)__bfloat16_as_ushort(h0) | ((uint32_t)__bfloat16_as_ushort(h1) << 16);
    lo = (uint32_t)__bfloat16_as_ushort(l0) | ((uint32_t)__bfloat16_as_ushort(l1) << 16);
}

// =====================================================================
// bf16x3 WMMA GEMMs, DOUBLE-BUFFERED (dynamic smem 81920B, plain
// kernels + attribute opt-in — the proven-working pattern).
// CTA tile 128x128, K-chunk 32. 8 warps = 2(m) x 4(n).
// Pipeline: load chunk ch+1 to regs | mma chunk ch | store regs -> alt buf.
// =====================================================================
#define KCH  32
#define PADK 40
#define ST_M  (128 * PADK * 2)          // 10240 bytes per matrix
#define STAGE (4 * ST_M)                // 40960 per stage
#define OFF_AHI 0
#define OFF_ALO (ST_M)
#define OFF_BHI (2 * ST_M)
#define OFF_BLO (3 * ST_M)
#define MM2_SMEM (2 * STAGE)            // 81920 bytes dynamic

// ---------------- GEMM 1: qkv (NN=2304), scatter epilogue --------------
__global__ __launch_bounds__(256) void qkv_wmma(const float* __restrict__ A,
                                                const float* __restrict__ W,
                                                const float* __restrict__ bias)
{
    extern __shared__ __align__(16) char smem[];
    const int NN = 3 * Cq;
    int tid  = threadIdx.x;
    int lane = tid & 31;
    int wid  = tid >> 5;
    int wm   = wid >> 2;
    int wn   = wid & 3;

    const int m0 = blockIdx.y * 128;
    const int n0 = blockIdx.x * 128;

    wmma::fragment<wmma::accumulator, 16, 16, 16, float> acc[4][2];
    #pragma unroll
    for (int mi = 0; mi < 4; mi++)
        #pragma unroll
        for (int ni = 0; ni < 2; ni++)
            wmma::fill_fragment(acc[mi][ni], 0.0f);

    // per-thread fixed load coords
    const int am  = tid >> 4;            // A: rows am, am+... (idx>>4 over it)
    // (recomputed per it below for clarity)

    // ---- preload chunk 0 into stage 0
    #pragma unroll
    for (int it = 0; it < 8; it++) {
        int idx = tid + it * 256;
        int m  = idx >> 4;
        int kp = idx & 15;
        float2 v = *(const float2*)(A + (size_t)(m0 + m) * 768 + 2 * kp);
        uint32_t hi, lo;
        split_pack(v.x, v.y, hi, lo);
        uint32_t off = (uint32_t)(m * PADK + 2 * kp) * 2;
        *(uint32_t*)(smem + OFF_AHI + off) = hi;
        *(uint32_t*)(smem + OFF_ALO + off) = lo;
    }
    #pragma unroll
    for (int it = 0; it < 8; it++) {
        int idx = tid + it * 256;
        int n  = idx & 127;
        int kp = idx >> 7;
        float w0 = W[(size_t)(2 * kp)     * NN + n0 + n];
        float w1 = W[(size_t)(2 * kp + 1) * NN + n0 + n];
        uint32_t hi, lo;
        split_pack(w0, w1, hi, lo);
        uint32_t off = (uint32_t)(n * PADK + 2 * kp) * 2;
        *(uint32_t*)(smem + OFF_BHI + off) = hi;
        *(uint32_t*)(smem + OFF_BLO + off) = lo;
    }
    __syncthreads();

    const int NCH = 768 / KCH;   // 24
    for (int ch = 0; ch < NCH; ch++) {
        char* cb_ = smem + (ch & 1) * STAGE;
        char* nb_ = smem + ((ch & 1) ^ 1) * STAGE;

        // ---- stage next chunk's globals into registers
        float2 avr[8];
        float  bw0[8], bw1[8];
        if (ch + 1 < NCH) {
            const int k0n = (ch + 1) * KCH;
            #pragma unroll
            for (int it = 0; it < 8; it++) {
                int idx = tid + it * 256;
                int m  = idx >> 4;
                int kp = idx & 15;
                avr[it] = *(const float2*)(A + (size_t)(m0 + m) * 768 + k0n + 2 * kp);
            }
            #pragma unroll
            for (int it = 0; it < 8; it++) {
                int idx = tid + it * 256;
                int n  = idx & 127;
                int kp = idx >> 7;
                bw0[it] = W[(size_t)(k0n + 2 * kp)     * NN + n0 + n];
                bw1[it] = W[(size_t)(k0n + 2 * kp + 1) * NN + n0 + n];
            }
        }

        // ---- mma on current stage
        const __nv_bfloat16* Ah = (const __nv_bfloat16*)(cb_ + OFF_AHI);
        const __nv_bfloat16* Bh = (const __nv_bfloat16*)(cb_ + OFF_BHI);
        #pragma unroll
        for (int ks = 0; ks < 2; ks++) {
            const int kk = ks * 16;
            wmma::fragment<wmma::matrix_b, 16, 16, 16, __nv_bfloat16, wmma::col_major> fbh[2], fbl[2];
            #pragma unroll
            for (int ni = 0; ni < 2; ni++) {
                const __nv_bfloat16* bp = Bh + (wn * 32 + ni * 16) * PADK + kk;
                wmma::load_matrix_sync(fbh[ni], bp, PADK);
                wmma::load_matrix_sync(fbl[ni], bp + (ST_M / 2), PADK);
            }
            #pragma unroll
            for (int mi = 0; mi < 4; mi++) {
                wmma::fragment<wmma::matrix_a, 16, 16, 16, __nv_bfloat16, wmma::row_major> fah, fal;
                const __nv_bfloat16* ap = Ah + (wm * 64 + mi * 16) * PADK + kk;
                wmma::load_matrix_sync(fah, ap, PADK);
                wmma::load_matrix_sync(fal, ap + (ST_M / 2), PADK);
                #pragma unroll
                for (int ni = 0; ni < 2; ni++) {
                    wmma::mma_sync(acc[mi][ni], fah, fbh[ni], acc[mi][ni]);
                    wmma::mma_sync(acc[mi][ni], fah, fbl[ni], acc[mi][ni]);
                    wmma::mma_sync(acc[mi][ni], fal, fbh[ni], acc[mi][ni]);
                }
            }
        }

        // ---- store staged registers into next buffer
        if (ch + 1 < NCH) {
            #pragma unroll
            for (int it = 0; it < 8; it++) {
                int idx = tid + it * 256;
                int m  = idx >> 4;
                int kp = idx & 15;
                uint32_t hi, lo;
                split_pack(avr[it].x, avr[it].y, hi, lo);
                uint32_t off = (uint32_t)(m * PADK + 2 * kp) * 2;
                *(uint32_t*)(nb_ + OFF_AHI + off) = hi;
                *(uint32_t*)(nb_ + OFF_ALO + off) = lo;
            }
            #pragma unroll
            for (int it = 0; it < 8; it++) {
                int idx = tid + it * 256;
                int n  = idx & 127;
                int kp = idx >> 7;
                uint32_t hi, lo;
                split_pack(bw0[it], bw1[it], hi, lo);
                uint32_t off = (uint32_t)(n * PADK + 2 * kp) * 2;
                *(uint32_t*)(nb_ + OFF_BHI + off) = hi;
                *(uint32_t*)(nb_ + OFF_BLO + off) = lo;
            }
        }
        __syncthreads();
    }

    // ---- epilogue (staged through smem patch)
    float* patch = (float*)smem + wid * (16 * 20);
    const int r_loc = lane >> 1;
    const int c_loc = (lane & 1) * 8;

    #pragma unroll
    for (int mi = 0; mi < 4; mi++) {
        #pragma unroll
        for (int ni = 0; ni < 2; ni++) {
            wmma::store_matrix_sync(patch, acc[mi][ni], 20, wmma::mem_row_major);
            __syncwarp();
            int r  = m0 + wm * 64 + mi * 16 + r_loc;
            int cb = n0 + wn * 32 + ni * 16 + c_loc;
            float vv[8];
            #pragma unroll
            for (int j = 0; j < 8; j++)
                vv[j] = patch[r_loc * 20 + c_loc + j] + bias[cb + j];

            int b_  = r >> 10, tok = r & 1023;
            int s   = cb / Cq;
            int rem = cb - s * Cq;
            int h   = rem >> 6, d = rem & 63;
            float* dst = (s == 0) ? g_q : ((s == 1) ? g_k : g_v);
            float* dbase = dst + (((b_ * Hq + h) << 16) + (tok << 6) + d);
            #pragma unroll
            for (int j = 0; j < 8; j += 2)
                *(float2*)(dbase + j) = make_float2(vv[j], vv[j + 1]);
            __syncwarp();
        }
    }
}

// ---------------- GEMM 2: proj (NN=768), dense epilogue ----------------
__global__ __launch_bounds__(256) void proj_wmma(const float* __restrict__ W,
                                                 const float* __restrict__ bias,
                                                 float* __restrict__ out)
{
    extern __shared__ __align__(16) char smem[];
    const int NN = Cq;
    const float* A = g_att;
    int tid  = threadIdx.x;
    int lane = tid & 31;
    int wid  = tid >> 5;
    int wm   = wid >> 2;
    int wn   = wid & 3;

    const int m0 = blockIdx.y * 128;
    const int n0 = blockIdx.x * 128;

    wmma::fragment<wmma::accumulator, 16, 16, 16, float> acc[4][2];
    #pragma unroll
    for (int mi = 0; mi < 4; mi++)
        #pragma unroll
        for (int ni = 0; ni < 2; ni++)
            wmma::fill_fragment(acc[mi][ni], 0.0f);

    #pragma unroll
    for (int it = 0; it < 8; it++) {
        int idx = tid + it * 256;
        int m  = idx >> 4;
        int kp = idx & 15;
        float2 v = *(const float2*)(A + (size_t)(m0 + m) * 768 + 2 * kp);
        uint32_t hi, lo;
        split_pack(v.x, v.y, hi, lo);
        uint32_t off = (uint32_t)(m * PADK + 2 * kp) * 2;
        *(uint32_t*)(smem + OFF_AHI + off) = hi;
        *(uint32_t*)(smem + OFF_ALO + off) = lo;
    }
    #pragma unroll
    for (int it = 0; it < 8; it++) {
        int idx = tid + it * 256;
        int n  = idx & 127;
        int kp = idx >> 7;
        float w0 = W[(size_t)(2 * kp)     * NN + n0 + n];
        float w1 = W[(size_t)(2 * kp + 1) * NN + n0 + n];
        uint32_t hi, lo;
        split_pack(w0, w1, hi, lo);
        uint32_t off = (uint32_t)(n * PADK + 2 * kp) * 2;
        *(uint32_t*)(smem + OFF_BHI + off) = hi;
        *(uint32_t*)(smem + OFF_BLO + off) = lo;
    }
    __syncthreads();

    const int NCH = 768 / KCH;
    for (int ch = 0; ch < NCH; ch++) {
        char* cb_ = smem + (ch & 1) * STAGE;
        char* nb_ = smem + ((ch & 1) ^ 1) * STAGE;

        float2 avr[8];
        float  bw0[8], bw1[8];
        if (ch + 1 < NCH) {
            const int k0n = (ch + 1) * KCH;
            #pragma unroll
            for (int it = 0; it < 8; it++) {
                int idx = tid + it * 256;
                int m  = idx >> 4;
                int kp = idx & 15;
                avr[it] = *(const float2*)(A + (size_t)(m0 + m) * 768 + k0n + 2 * kp);
            }
            #pragma unroll
            for (int it = 0; it < 8; it++) {
                int idx = tid + it * 256;
                int n  = idx & 127;
                int kp = idx >> 7;
                bw0[it] = W[(size_t)(k0n + 2 * kp)     * NN + n0 + n];
                bw1[it] = W[(size_t)(k0n + 2 * kp + 1) * NN + n0 + n];
            }
        }

        const __nv_bfloat16* Ah = (const __nv_bfloat16*)(cb_ + OFF_AHI);
        const __nv_bfloat16* Bh = (const __nv_bfloat16*)(cb_ + OFF_BHI);
        #pragma unroll
        for (int ks = 0; ks < 2; ks++) {
            const int kk = ks * 16;
            wmma::fragment<wmma::matrix_b, 16, 16, 16, __nv_bfloat16, wmma::col_major> fbh[2], fbl[2];
            #pragma unroll
            for (int ni = 0; ni < 2; ni++) {
                const __nv_bfloat16* bp = Bh + (wn * 32 + ni * 16) * PADK + kk;
                wmma::load_matrix_sync(fbh[ni], bp, PADK);
                wmma::load_matrix_sync(fbl[ni], bp + (ST_M / 2), PADK);
            }
            #pragma unroll
            for (int mi = 0; mi < 4; mi++) {
                wmma::fragment<wmma::matrix_a, 16, 16, 16, __nv_bfloat16, wmma::row_major> fah, fal;
                const __nv_bfloat16* ap = Ah + (wm * 64 + mi * 16) * PADK + kk;
                wmma::load_matrix_sync(fah, ap, PADK);
                wmma::load_matrix_sync(fal, ap + (ST_M / 2), PADK);
                #pragma unroll
                for (int ni = 0; ni < 2; ni++) {
                    wmma::mma_sync(acc[mi][ni], fah, fbh[ni], acc[mi][ni]);
                    wmma::mma_sync(acc[mi][ni], fah, fbl[ni], acc[mi][ni]);
                    wmma::mma_sync(acc[mi][ni], fal, fbh[ni], acc[mi][ni]);
                }
            }
        }

        if (ch + 1 < NCH) {
            #pragma unroll
            for (int it = 0; it < 8; it++) {
                int idx = tid + it * 256;
                int m  = idx >> 4;
                int kp = idx & 15;
                uint32_t hi, lo;
                split_pack(avr[it].x, avr[it].y, hi, lo);
                uint32_t off = (uint32_t)(m * PADK + 2 * kp) * 2;
                *(uint32_t*)(nb_ + OFF_AHI + off) = hi;
                *(uint32_t*)(nb_ + OFF_ALO + off) = lo;
            }
            #pragma unroll
            for (int it = 0; it < 8; it++) {
                int idx = tid + it * 256;
                int n  = idx & 127;
                int kp = idx >> 7;
                uint32_t hi, lo;
                split_pack(bw0[it], bw1[it], hi, lo);
                uint32_t off = (uint32_t)(n * PADK + 2 * kp) * 2;
                *(uint32_t*)(nb_ + OFF_BHI + off) = hi;
                *(uint32_t*)(nb_ + OFF_BLO + off) = lo;
            }
        }
        __syncthreads();
    }

    float* patch = (float*)smem + wid * (16 * 20);
    const int r_loc = lane >> 1;
    const int c_loc = (lane & 1) * 8;

    #pragma unroll
    for (int mi = 0; mi < 4; mi++) {
        #pragma unroll
        for (int ni = 0; ni < 2; ni++) {
            wmma::store_matrix_sync(patch, acc[mi][ni], 20, wmma::mem_row_major);
            __syncwarp();
            int r  = m0 + wm * 64 + mi * 16 + r_loc;
            int cb = n0 + wn * 32 + ni * 16 + c_loc;
            float* obase = out + (size_t)r * NN + cb;
            #pragma unroll
            for (int j = 0; j < 8; j += 2) {
                float v0 = patch[r_loc * 20 + c_loc + j]     + bias[cb + j];
                float v1 = patch[r_loc * 20 + c_loc + j + 1] + bias[cb + j + 1];
                *(float2*)(obase + j) = make_float2(v0, v1);
            }
            __syncwarp();
        }
    }
}

// =====================================================================
// RoPE — unchanged, passing.
// =====================================================================
__global__ void rope_kernel(const int* __restrict__ pos_h,
                            const int* __restrict__ pos_w)
{
    int idx = blockIdx.x * blockDim.x + threadIdx.x;
    int j    = idx & 15;
    int half = (idx >> 4) & 1;
    int tok  = (idx >> 5) & 1023;
    int rest = idx >> 15;           // 0..383
    if (rest >= 2 * BH) return;
    int bh   = rest % BH;
    int tens = rest / BH;           // 0=q, 1=k
    int b_ = bh / Hq;
    int pos = half ? pos_w[b_ * Nq + tok] : pos_h[b_ * Nq + tok];
    float fp = (float)pos;
    float* base = (tens ? g_k : g_q) + (bh << 16) + (tok << 6) + half * 32;
    float t0 = base[j], t1 = base[j + 16];
    float L = logf(10000.0f);
    float inv0 = expf(-(float)(j >> 1)       / 16.0f * L);
    float inv1 = expf(-(float)(8 + (j >> 1)) / 16.0f * L);
    float s0, c0, s1, c1;
    sincosf(fp * inv0, &s0, &c0);
    sincosf(fp * inv1, &s1, &c1);
    base[j]      = t0 * c0 - t1 * s0;
    base[j + 16] = t1 * c1 + t0 * s1;
}

// =====================================================================
// Flash attention: round-8 SIMT version (proven 1.35ms) — REVERTED.
// 128 q-rows x 64-key tiles, 256 threads, 8x4/thread. __expf softmax.
// =====================================================================
#define QW 132
#define VW 68
#define ATTN_F (64 * QW + 64 * QW + 64 * VW + 128 * 17 + 4 * 128)
#define ATTN_SMEM (ATTN_F * sizeof(float))   // 95744 bytes

__global__ __launch_bounds__(256) void attn_kernel()
{
    extern __shared__ float sm[];
    float* Qt   = sm;
    float* KP   = Qt + 64 * QW;
    float* Vs   = KP + 64 * QW;
    float* red  = Vs + 64 * VW;
    float* mrow = red + 128 * 17;
    float* lrow = mrow + 128;
    float* arow = lrow + 128;
    float* mnew = arow + 128;

    const int tid = threadIdx.x;
    const int bh  = blockIdx.y;
    const int q0  = blockIdx.x * 128;
    const float* Qg = g_q + ((size_t)bh << 16);
    const float* Kg = g_k + ((size_t)bh << 16);
    const float* Vg = g_v + ((size_t)bh << 16);
    const int ty = tid >> 4, tx = tid & 15;

    for (int idx = tid; idx < 8192; idx += 256) {
        int r = idx >> 6, k = idx & 63;
        Qt[k * QW + r] = Qg[(q0 + r) * 64 + k];
    }
    if (tid < 128) { mrow[tid] = -INFINITY; lrow[tid] = 0.0f; }
    __syncthreads();

    float o[8][4] = {};

    for (int t = 0; t < 16; t++) {
        const int kt0 = t * 64;
        for (int idx = tid; idx < 4096; idx += 256) {
            int c = idx >> 6, k = idx & 63;
            KP[k * QW + c] = Kg[(kt0 + c) * 64 + k];
        }
        for (int idx = tid; idx < 4096; idx += 256) {
            int c = idx >> 6, j = idx & 63;
            Vs[c * VW + j] = Vg[(kt0 + c) * 64 + j];
        }
        __syncthreads();

        float s_[8][4] = {};
        #pragma unroll 4
        for (int k = 0; k < 64; k++) {
            float a[8], b[4];
            *(float4*)(a)     = *(const float4*)&Qt[k * QW + ty * 8];
            *(float4*)(a + 4) = *(const float4*)&Qt[k * QW + ty * 8 + 4];
            *(float4*)(b)     = *(const float4*)&KP[k * QW + tx * 4];
            #pragma unroll
            for (int i = 0; i < 8; i++)
                #pragma unroll
                for (int j = 0; j < 4; j++)
                    s_[i][j] = fmaf(a[i], b[j], s_[i][j]);
        }
        #pragma unroll
        for (int i = 0; i < 8; i++) {
            float pm = -INFINITY;
            #pragma unroll
            for (int j = 0; j < 4; j++) {
                s_[i][j] *= 0.125f;
                pm = fmaxf(pm, s_[i][j]);
            }
            red[(ty * 8 + i) * 17 + tx] = pm;
        }
        __syncthreads();

        if (tid < 128) {
            float m = -INFINITY;
            #pragma unroll
            for (int u = 0; u < 16; u++) m = fmaxf(m, red[tid * 17 + u]);
            float mo = mrow[tid];
            float mn = fmaxf(mo, m);
            mnew[tid] = mn;
            arow[tid] = __expf(mo - mn);
            mrow[tid] = mn;
        }
        __syncthreads();

        #pragma unroll
        for (int i = 0; i < 8; i++) {
            int r = ty * 8 + i;
            float mn = mnew[r];
            float ps = 0.0f;
            #pragma unroll
            for (int j = 0; j < 4; j++) {
                float p = __expf(s_[i][j] - mn);
                s_[i][j] = p;
                ps += p;
            }
            red[r * 17 + tx] = ps;
        }
        #pragma unroll
        for (int j = 0; j < 4; j++) {
            int c = tx * 4 + j;
            *(float4*)&KP[c * QW + ty * 8] =
                make_float4(s_[0][j], s_[1][j], s_[2][j], s_[3][j]);
            *(float4*)&KP[c * QW + ty * 8 + 4] =
                make_float4(s_[4][j], s_[5][j], s_[6][j], s_[7][j]);
        }
        __syncthreads();

        if (tid < 128) {
            float s = 0.0f;
            #pragma unroll
            for (int u = 0; u < 16; u++) s += red[tid * 17 + u];
            lrow[tid] = lrow[tid] * arow[tid] + s;
        }

        #pragma unroll
        for (int i = 0; i < 8; i++) {
            float al = arow[ty * 8 + i];
            #pragma unroll
            for (int j = 0; j < 4; j++) o[i][j] *= al;
        }
        #pragma unroll 4
        for (int c = 0; c < 64; c++) {
            float a[8], b[4];
            *(float4*)(a)     = *(const float4*)&KP[c * QW + ty * 8];
            *(float4*)(a + 4) = *(const float4*)&KP[c * QW + ty * 8 + 4];
            *(float4*)(b)     = *(const float4*)&Vs[c * VW + tx * 4];
            #pragma unroll
            for (int i = 0; i < 8; i++)
                #pragma unroll
                for (int j = 0; j < 4; j++)
                    o[i][j] = fmaf(a[i], b[j], o[i][j]);
        }
        __syncthreads();
    }

    const int b_ = bh / Hq, h = bh % Hq;
    #pragma unroll
    for (int i = 0; i < 8; i++) {
        int r = ty * 8 + i;
        float linv = 1.0f / lrow[r];
        *(float4*)&g_att[(size_t)(b_ * Nq + q0 + r) * Cq + h * 64 + tx * 4] =
            make_float4(o[i][0] * linv, o[i][1] * linv,
                        o[i][2] * linv, o[i][3] * linv);
    }
}

// =====================================================================
extern "C" void kernel_launch(void* const* d_in, const int* in_sizes, int n_in,
                              void* d_out, int out_size)
{
    const float* x      = (const float*)d_in[0];
    const float* W_qkv  = (const float*)d_in[1];
    const float* b_qkv  = (const float*)d_in[2];
    const float* W_proj = (const float*)d_in[3];
    const float* b_proj = (const float*)d_in[4];
    const int*   pos_h  = (const int*)d_in[5];
    const int*   pos_w  = (const int*)d_in[6];
    float*       out    = (float*)d_out;

    cudaFuncSetAttribute(attn_kernel,
                         cudaFuncAttributeMaxDynamicSharedMemorySize,
                         (int)ATTN_SMEM);
    cudaFuncSetAttribute(qkv_wmma,
                         cudaFuncAttributeMaxDynamicSharedMemorySize,
                         (int)MM2_SMEM);
    cudaFuncSetAttribute(proj_wmma,
                         cudaFuncAttributeMaxDynamicSharedMemorySize,
                         (int)MM2_SMEM);

    qkv_wmma<<<dim3(18, 128), 256, MM2_SMEM>>>(x, W_qkv, b_qkv);
    rope_kernel<<<(2 * BH * Nq * 32) / 256, 256>>>(pos_h, pos_w);
    attn_kernel<<<dim3(8, 192), 256, ATTN_SMEM>>>();
    proj_wmma<<<dim3(6, 128), 256, MM2_SMEM>>>(W_proj, b_proj, out);
}

// round 13
// speedup vs baseline: 1.9886x; 1.4081x over previous
#include <cuda_runtime.h>
#include <cuda_bf16.h>
#include <mma.h>
#include <math.h>
#include <stdint.h>

using namespace nvcuda;

#define Bq   16
#define Nq   1024
#define Cq   768
#define Hq   12
#define HD   64
#define BH   (Bq*Hq)        // 192
#define MROWS (Bq*Nq)       // 16384

// ---- scratch (no allocs allowed) ----
__device__ float g_q[BH * Nq * HD];     // [bh][tok][d]
__device__ float g_k[BH * Nq * HD];
__device__ float g_v[BH * Nq * HD];
__device__ float g_att[MROWS * Cq];     // [b*N + tok][h*64 + d]

__device__ __forceinline__ void split_pack(float x0, float x1,
                                           uint32_t& hi, uint32_t& lo) {
    __nv_bfloat16 h0 = __float2bfloat16_rn(x0);
    __nv_bfloat16 h1 = __float2bfloat16_rn(x1);
    __nv_bfloat16 l0 = __float2bfloat16_rn(x0 - __bfloat162float(h0));
    __nv_bfloat16 l1 = __float2bfloat16_rn(x1 - __bfloat162float(h1));
    hi = (uint32_t)__bfloat16_as_ushort(h0) | ((uint32_t)__bfloat16_as_ushort(h1) << 16);
    lo = (uint32_t)__bfloat16_as_ushort(l0) | ((uint32_t)__bfloat16_as_ushort(l1) << 16);
}

// ---- raw mma / ldmatrix helpers (compile clean on this target) ----
__device__ __forceinline__ uint32_t smem_u32(const void* p) {
    uint32_t a;
    asm("{ .reg .u64 t; cvta.to.shared.u64 t, %1; cvt.u32.u64 %0, t; }"
        : "=r"(a) : "l"(p));
    return a;
}
__device__ __forceinline__ void ldsm4(uint32_t* r, uint32_t a) {
    asm volatile("ldmatrix.sync.aligned.m8n8.x4.shared.b16 {%0,%1,%2,%3}, [%4];"
                 : "=r"(r[0]), "=r"(r[1]), "=r"(r[2]), "=r"(r[3]) : "r"(a));
}
__device__ __forceinline__ void ldsm2(uint32_t* r, uint32_t a) {
    asm volatile("ldmatrix.sync.aligned.m8n8.x2.shared.b16 {%0,%1}, [%2];"
                 : "=r"(r[0]), "=r"(r[1]) : "r"(a));
}
__device__ __forceinline__ void ldsm2_t(uint32_t* r, uint32_t a) {
    asm volatile("ldmatrix.sync.aligned.m8n8.x2.trans.shared.b16 {%0,%1}, [%2];"
                 : "=r"(r[0]), "=r"(r[1]) : "r"(a));
}
__device__ __forceinline__ void mma_bf16(float* c, const uint32_t* a, const uint32_t* b) {
    asm volatile(
        "mma.sync.aligned.m16n8k16.row.col.f32.bf16.bf16.f32 "
        "{%0,%1,%2,%3}, {%4,%5,%6,%7}, {%8,%9}, {%0,%1,%2,%3};"
        : "+f"(c[0]), "+f"(c[1]), "+f"(c[2]), "+f"(c[3])
        : "r"(a[0]), "r"(a[1]), "r"(a[2]), "r"(a[3]), "r"(b[0]), "r"(b[1]));
}

// =====================================================================
// bf16x3 WMMA GEMMs, double-buffered (round 12, passing — unchanged)
// =====================================================================
#define KCH  32
#define PADK 40
#define ST_M  (128 * PADK * 2)
#define STAGE (4 * ST_M)
#define OFF_AHI 0
#define OFF_ALO (ST_M)
#define OFF_BHI (2 * ST_M)
#define OFF_BLO (3 * ST_M)
#define MM2_SMEM (2 * STAGE)            // 81920 bytes dynamic

__global__ __launch_bounds__(256) void qkv_wmma(const float* __restrict__ A,
                                                const float* __restrict__ W,
                                                const float* __restrict__ bias)
{
    extern __shared__ __align__(16) char smem[];
    const int NN = 3 * Cq;
    int tid  = threadIdx.x;
    int lane = tid & 31;
    int wid  = tid >> 5;
    int wm   = wid >> 2;
    int wn   = wid & 3;

    const int m0 = blockIdx.y * 128;
    const int n0 = blockIdx.x * 128;

    wmma::fragment<wmma::accumulator, 16, 16, 16, float> acc[4][2];
    #pragma unroll
    for (int mi = 0; mi < 4; mi++)
        #pragma unroll
        for (int ni = 0; ni < 2; ni++)
            wmma::fill_fragment(acc[mi][ni], 0.0f);

    #pragma unroll
    for (int it = 0; it < 8; it++) {
        int idx = tid + it * 256;
        int m  = idx >> 4;
        int kp = idx & 15;
        float2 v = *(const float2*)(A + (size_t)(m0 + m) * 768 + 2 * kp);
        uint32_t hi, lo;
        split_pack(v.x, v.y, hi, lo);
        uint32_t off = (uint32_t)(m * PADK + 2 * kp) * 2;
        *(uint32_t*)(smem + OFF_AHI + off) = hi;
        *(uint32_t*)(smem + OFF_ALO + off) = lo;
    }
    #pragma unroll
    for (int it = 0; it < 8; it++) {
        int idx = tid + it * 256;
        int n  = idx & 127;
        int kp = idx >> 7;
        float w0 = W[(size_t)(2 * kp)     * NN + n0 + n];
        float w1 = W[(size_t)(2 * kp + 1) * NN + n0 + n];
        uint32_t hi, lo;
        split_pack(w0, w1, hi, lo);
        uint32_t off = (uint32_t)(n * PADK + 2 * kp) * 2;
        *(uint32_t*)(smem + OFF_BHI + off) = hi;
        *(uint32_t*)(smem + OFF_BLO + off) = lo;
    }
    __syncthreads();

    const int NCH = 768 / KCH;   // 24
    for (int ch = 0; ch < NCH; ch++) {
        char* cb_ = smem + (ch & 1) * STAGE;
        char* nb_ = smem + ((ch & 1) ^ 1) * STAGE;

        float2 avr[8];
        float  bw0[8], bw1[8];
        if (ch + 1 < NCH) {
            const int k0n = (ch + 1) * KCH;
            #pragma unroll
            for (int it = 0; it < 8; it++) {
                int idx = tid + it * 256;
                int m  = idx >> 4;
                int kp = idx & 15;
                avr[it] = *(const float2*)(A + (size_t)(m0 + m) * 768 + k0n + 2 * kp);
            }
            #pragma unroll
            for (int it = 0; it < 8; it++) {
                int idx = tid + it * 256;
                int n  = idx & 127;
                int kp = idx >> 7;
                bw0[it] = W[(size_t)(k0n + 2 * kp)     * NN + n0 + n];
                bw1[it] = W[(size_t)(k0n + 2 * kp + 1) * NN + n0 + n];
            }
        }

        const __nv_bfloat16* Ah = (const __nv_bfloat16*)(cb_ + OFF_AHI);
        const __nv_bfloat16* Bh = (const __nv_bfloat16*)(cb_ + OFF_BHI);
        #pragma unroll
        for (int ks = 0; ks < 2; ks++) {
            const int kk = ks * 16;
            wmma::fragment<wmma::matrix_b, 16, 16, 16, __nv_bfloat16, wmma::col_major> fbh[2], fbl[2];
            #pragma unroll
            for (int ni = 0; ni < 2; ni++) {
                const __nv_bfloat16* bp = Bh + (wn * 32 + ni * 16) * PADK + kk;
                wmma::load_matrix_sync(fbh[ni], bp, PADK);
                wmma::load_matrix_sync(fbl[ni], bp + (ST_M / 2), PADK);
            }
            #pragma unroll
            for (int mi = 0; mi < 4; mi++) {
                wmma::fragment<wmma::matrix_a, 16, 16, 16, __nv_bfloat16, wmma::row_major> fah, fal;
                const __nv_bfloat16* ap = Ah + (wm * 64 + mi * 16) * PADK + kk;
                wmma::load_matrix_sync(fah, ap, PADK);
                wmma::load_matrix_sync(fal, ap + (ST_M / 2), PADK);
                #pragma unroll
                for (int ni = 0; ni < 2; ni++) {
                    wmma::mma_sync(acc[mi][ni], fah, fbh[ni], acc[mi][ni]);
                    wmma::mma_sync(acc[mi][ni], fah, fbl[ni], acc[mi][ni]);
                    wmma::mma_sync(acc[mi][ni], fal, fbh[ni], acc[mi][ni]);
                }
            }
        }

        if (ch + 1 < NCH) {
            #pragma unroll
            for (int it = 0; it < 8; it++) {
                int idx = tid + it * 256;
                int m  = idx >> 4;
                int kp = idx & 15;
                uint32_t hi, lo;
                split_pack(avr[it].x, avr[it].y, hi, lo);
                uint32_t off = (uint32_t)(m * PADK + 2 * kp) * 2;
                *(uint32_t*)(nb_ + OFF_AHI + off) = hi;
                *(uint32_t*)(nb_ + OFF_ALO + off) = lo;
            }
            #pragma unroll
            for (int it = 0; it < 8; it++) {
                int idx = tid + it * 256;
                int n  = idx & 127;
                int kp = idx >> 7;
                uint32_t hi, lo;
                split_pack(bw0[it], bw1[it], hi, lo);
                uint32_t off = (uint32_t)(n * PADK + 2 * kp) * 2;
                *(uint32_t*)(nb_ + OFF_BHI + off) = hi;
                *(uint32_t*)(nb_ + OFF_BLO + off) = lo;
            }
        }
        __syncthreads();
    }

    float* patch = (float*)smem + wid * (16 * 20);
    const int r_loc = lane >> 1;
    const int c_loc = (lane & 1) * 8;

    #pragma unroll
    for (int mi = 0; mi < 4; mi++) {
        #pragma unroll
        for (int ni = 0; ni < 2; ni++) {
            wmma::store_matrix_sync(patch, acc[mi][ni], 20, wmma::mem_row_major);
            __syncwarp();
            int r  = m0 + wm * 64 + mi * 16 + r_loc;
            int cb = n0 + wn * 32 + ni * 16 + c_loc;
            float vv[8];
            #pragma unroll
            for (int j = 0; j < 8; j++)
                vv[j] = patch[r_loc * 20 + c_loc + j] + bias[cb + j];

            int b_  = r >> 10, tok = r & 1023;
            int s   = cb / Cq;
            int rem = cb - s * Cq;
            int h   = rem >> 6, d = rem & 63;
            float* dst = (s == 0) ? g_q : ((s == 1) ? g_k : g_v);
            float* dbase = dst + (((b_ * Hq + h) << 16) + (tok << 6) + d);
            #pragma unroll
            for (int j = 0; j < 8; j += 2)
                *(float2*)(dbase + j) = make_float2(vv[j], vv[j + 1]);
            __syncwarp();
        }
    }
}

__global__ __launch_bounds__(256) void proj_wmma(const float* __restrict__ W,
                                                 const float* __restrict__ bias,
                                                 float* __restrict__ out)
{
    extern __shared__ __align__(16) char smem[];
    const int NN = Cq;
    const float* A = g_att;
    int tid  = threadIdx.x;
    int lane = tid & 31;
    int wid  = tid >> 5;
    int wm   = wid >> 2;
    int wn   = wid & 3;

    const int m0 = blockIdx.y * 128;
    const int n0 = blockIdx.x * 128;

    wmma::fragment<wmma::accumulator, 16, 16, 16, float> acc[4][2];
    #pragma unroll
    for (int mi = 0; mi < 4; mi++)
        #pragma unroll
        for (int ni = 0; ni < 2; ni++)
            wmma::fill_fragment(acc[mi][ni], 0.0f);

    #pragma unroll
    for (int it = 0; it < 8; it++) {
        int idx = tid + it * 256;
        int m  = idx >> 4;
        int kp = idx & 15;
        float2 v = *(const float2*)(A + (size_t)(m0 + m) * 768 + 2 * kp);
        uint32_t hi, lo;
        split_pack(v.x, v.y, hi, lo);
        uint32_t off = (uint32_t)(m * PADK + 2 * kp) * 2;
        *(uint32_t*)(smem + OFF_AHI + off) = hi;
        *(uint32_t*)(smem + OFF_ALO + off) = lo;
    }
    #pragma unroll
    for (int it = 0; it < 8; it++) {
        int idx = tid + it * 256;
        int n  = idx & 127;
        int kp = idx >> 7;
        float w0 = W[(size_t)(2 * kp)     * NN + n0 + n];
        float w1 = W[(size_t)(2 * kp + 1) * NN + n0 + n];
        uint32_t hi, lo;
        split_pack(w0, w1, hi, lo);
        uint32_t off = (uint32_t)(n * PADK + 2 * kp) * 2;
        *(uint32_t*)(smem + OFF_BHI + off) = hi;
        *(uint32_t*)(smem + OFF_BLO + off) = lo;
    }
    __syncthreads();

    const int NCH = 768 / KCH;
    for (int ch = 0; ch < NCH; ch++) {
        char* cb_ = smem + (ch & 1) * STAGE;
        char* nb_ = smem + ((ch & 1) ^ 1) * STAGE;

        float2 avr[8];
        float  bw0[8], bw1[8];
        if (ch + 1 < NCH) {
            const int k0n = (ch + 1) * KCH;
            #pragma unroll
            for (int it = 0; it < 8; it++) {
                int idx = tid + it * 256;
                int m  = idx >> 4;
                int kp = idx & 15;
                avr[it] = *(const float2*)(A + (size_t)(m0 + m) * 768 + k0n + 2 * kp);
            }
            #pragma unroll
            for (int it = 0; it < 8; it++) {
                int idx = tid + it * 256;
                int n  = idx & 127;
                int kp = idx >> 7;
                bw0[it] = W[(size_t)(k0n + 2 * kp)     * NN + n0 + n];
                bw1[it] = W[(size_t)(k0n + 2 * kp + 1) * NN + n0 + n];
            }
        }

        const __nv_bfloat16* Ah = (const __nv_bfloat16*)(cb_ + OFF_AHI);
        const __nv_bfloat16* Bh = (const __nv_bfloat16*)(cb_ + OFF_BHI);
        #pragma unroll
        for (int ks = 0; ks < 2; ks++) {
            const int kk = ks * 16;
            wmma::fragment<wmma::matrix_b, 16, 16, 16, __nv_bfloat16, wmma::col_major> fbh[2], fbl[2];
            #pragma unroll
            for (int ni = 0; ni < 2; ni++) {
                const __nv_bfloat16* bp = Bh + (wn * 32 + ni * 16) * PADK + kk;
                wmma::load_matrix_sync(fbh[ni], bp, PADK);
                wmma::load_matrix_sync(fbl[ni], bp + (ST_M / 2), PADK);
            }
            #pragma unroll
            for (int mi = 0; mi < 4; mi++) {
                wmma::fragment<wmma::matrix_a, 16, 16, 16, __nv_bfloat16, wmma::row_major> fah, fal;
                const __nv_bfloat16* ap = Ah + (wm * 64 + mi * 16) * PADK + kk;
                wmma::load_matrix_sync(fah, ap, PADK);
                wmma::load_matrix_sync(fal, ap + (ST_M / 2), PADK);
                #pragma unroll
                for (int ni = 0; ni < 2; ni++) {
                    wmma::mma_sync(acc[mi][ni], fah, fbh[ni], acc[mi][ni]);
                    wmma::mma_sync(acc[mi][ni], fah, fbl[ni], acc[mi][ni]);
                    wmma::mma_sync(acc[mi][ni], fal, fbh[ni], acc[mi][ni]);
                }
            }
        }

        if (ch + 1 < NCH) {
            #pragma unroll
            for (int it = 0; it < 8; it++) {
                int idx = tid + it * 256;
                int m  = idx >> 4;
                int kp = idx & 15;
                uint32_t hi, lo;
                split_pack(avr[it].x, avr[it].y, hi, lo);
                uint32_t off = (uint32_t)(m * PADK + 2 * kp) * 2;
                *(uint32_t*)(nb_ + OFF_AHI + off) = hi;
                *(uint32_t*)(nb_ + OFF_ALO + off) = lo;
            }
            #pragma unroll
            for (int it = 0; it < 8; it++) {
                int idx = tid + it * 256;
                int n  = idx & 127;
                int kp = idx >> 7;
                uint32_t hi, lo;
                split_pack(bw0[it], bw1[it], hi, lo);
                uint32_t off = (uint32_t)(n * PADK + 2 * kp) * 2;
                *(uint32_t*)(nb_ + OFF_BHI + off) = hi;
                *(uint32_t*)(nb_ + OFF_BLO + off) = lo;
            }
        }
        __syncthreads();
    }

    float* patch = (float*)smem + wid * (16 * 20);
    const int r_loc = lane >> 1;
    const int c_loc = (lane & 1) * 8;

    #pragma unroll
    for (int mi = 0; mi < 4; mi++) {
        #pragma unroll
        for (int ni = 0; ni < 2; ni++) {
            wmma::store_matrix_sync(patch, acc[mi][ni], 20, wmma::mem_row_major);
            __syncwarp();
            int r  = m0 + wm * 64 + mi * 16 + r_loc;
            int cb = n0 + wn * 32 + ni * 16 + c_loc;
            float* obase = out + (size_t)r * NN + cb;
            #pragma unroll
            for (int j = 0; j < 8; j += 2) {
                float v0 = patch[r_loc * 20 + c_loc + j]     + bias[cb + j];
                float v1 = patch[r_loc * 20 + c_loc + j + 1] + bias[cb + j + 1];
                *(float2*)(obase + j) = make_float2(v0, v1);
            }
            __syncwarp();
        }
    }
}

// =====================================================================
// RoPE — unchanged, passing.
// =====================================================================
__global__ void rope_kernel(const int* __restrict__ pos_h,
                            const int* __restrict__ pos_w)
{
    int idx = blockIdx.x * blockDim.x + threadIdx.x;
    int j    = idx & 15;
    int half = (idx >> 4) & 1;
    int tok  = (idx >> 5) & 1023;
    int rest = idx >> 15;           // 0..383
    if (rest >= 2 * BH) return;
    int bh   = rest % BH;
    int tens = rest / BH;           // 0=q, 1=k
    int b_ = bh / Hq;
    int pos = half ? pos_w[b_ * Nq + tok] : pos_h[b_ * Nq + tok];
    float fp = (float)pos;
    float* base = (tens ? g_k : g_q) + (bh << 16) + (tok << 6) + half * 32;
    float t0 = base[j], t1 = base[j + 16];
    float L = logf(10000.0f);
    float inv0 = expf(-(float)(j >> 1)       / 16.0f * L);
    float inv1 = expf(-(float)(8 + (j >> 1)) / 16.0f * L);
    float s0, c0, s1, c1;
    sincosf(fp * inv0, &s0, &c0);
    sincosf(fp * inv1, &s1, &c1);
    base[j]      = t0 * c0 - t1 * s0;
    base[j + 16] = t1 * c1 + t0 * s1;
}

// =====================================================================
// FA2-style flash attention on raw mma.sync (m16n8k16), bf16x3.
// CTA = (128 q-rows, bh); 8 warps, warp = 16 q-rows x full 64-key tile.
// S accumulators feed P a-fragments directly (register-resident softmax).
// smem: K hi/lo + V hi/lo, 64x72 bf16 each = 36864 B static.
// =====================================================================
#define APITCH 72

__global__ __launch_bounds__(256) void attn_mma()
{
    __shared__ __nv_bfloat16 sbuf[4 * 64 * APITCH];   // 36864 B

    const int tid  = threadIdx.x;
    const int lane = tid & 31;
    const int wid  = tid >> 5;
    const int bh   = blockIdx.y;
    const int q0   = blockIdx.x * 128;
    const float* Qg = g_q + ((size_t)bh << 16);
    const float* Kg = g_k + ((size_t)bh << 16);
    const float* Vg = g_v + ((size_t)bh << 16);

    const uint32_t sb = smem_u32(sbuf);
    // per-lane ldmatrix offsets (bytes)
    const uint32_t qa_off = (uint32_t)((lane & 15) * APITCH + 8 * (lane >> 4)) * 2;
    const uint32_t kb_off = (uint32_t)((lane & 7) * APITCH + 8 * ((lane >> 3) & 1)) * 2;
    const uint32_t vb_off = (uint32_t)(((lane & 7) + 8 * ((lane >> 3) & 1)) * APITCH) * 2;

    // ---- stage Q [128][64] hi->elems[0:9216), lo->elems[9216:18432)
    #pragma unroll
    for (int it = 0; it < 16; it++) {
        int idx = tid + it * 256;          // 0..4095 pairs
        int m = idx >> 5, dp = idx & 31;
        float2 v = *(const float2*)(Qg + (size_t)(q0 + m) * 64 + 2 * dp);
        uint32_t hi, lo;
        split_pack(v.x, v.y, hi, lo);
        *(uint32_t*)((char*)sbuf + (m * APITCH + 2 * dp) * 2) = hi;
        *(uint32_t*)((char*)sbuf + (9216 + m * APITCH + 2 * dp) * 2) = lo;
    }
    __syncthreads();

    // ---- extract per-warp Q fragments (rows wid*16 .. +15), 4 k-steps
    uint32_t qh[4][4], ql[4][4];
    {
        uint32_t qbase = sb + (uint32_t)(wid * 16 * APITCH) * 2 + qa_off;
        #pragma unroll
        for (int j = 0; j < 4; j++) {
            ldsm4(qh[j], qbase + (uint32_t)(16 * j) * 2);
            ldsm4(ql[j], qbase + (uint32_t)(9216 + 16 * j) * 2);
        }
    }
    __syncthreads();

    const uint32_t KhiB = sb;                    // elems 0
    const uint32_t VhiB = sb + 9216 * 2;         // elems 9216
    // lo planes at +4608 elems from each hi plane

    float o[8][4] = {};
    float m0 = -INFINITY, m1 = -INFINITY, l0 = 0.0f, l1 = 0.0f;

    for (int t = 0; t < 16; t++) {
        const int kt0 = t * 64;
        // ---- load + split K, V tiles [64][64]
        #pragma unroll
        for (int it = 0; it < 8; it++) {
            int idx = tid + it * 256;
            int c = idx >> 5, dp = idx & 31;
            float2 v = *(const float2*)(Kg + (size_t)(kt0 + c) * 64 + 2 * dp);
            uint32_t hi, lo;
            split_pack(v.x, v.y, hi, lo);
            *(uint32_t*)((char*)sbuf + (c * APITCH + 2 * dp) * 2) = hi;
            *(uint32_t*)((char*)sbuf + (4608 + c * APITCH + 2 * dp) * 2) = lo;
        }
        #pragma unroll
        for (int it = 0; it < 8; it++) {
            int idx = tid + it * 256;
            int c = idx >> 5, dp = idx & 31;
            float2 v = *(const float2*)(Vg + (size_t)(kt0 + c) * 64 + 2 * dp);
            uint32_t hi, lo;
            split_pack(v.x, v.y, hi, lo);
            *(uint32_t*)((char*)sbuf + (9216 + c * APITCH + 2 * dp) * 2) = hi;
            *(uint32_t*)((char*)sbuf + (13824 + c * APITCH + 2 * dp) * 2) = lo;
        }
        __syncthreads();

        // ---- S = Q @ K^T (16 x 64 per warp), bf16x3
        float s_[8][4];
        #pragma unroll
        for (int n = 0; n < 8; n++) {
            s_[n][0] = 0.0f; s_[n][1] = 0.0f; s_[n][2] = 0.0f; s_[n][3] = 0.0f;
        }
        #pragma unroll
        for (int j = 0; j < 4; j++) {
            #pragma unroll
            for (int n = 0; n < 8; n++) {
                uint32_t kbh[2], kbl[2];
                uint32_t addr = KhiB + (uint32_t)(n * 8 * APITCH + 16 * j) * 2 + kb_off;
                ldsm2(kbh, addr);
                ldsm2(kbl, addr + 4608 * 2);
                mma_bf16(s_[n], qh[j], kbh);
                mma_bf16(s_[n], qh[j], kbl);
                mma_bf16(s_[n], ql[j], kbh);
            }
        }

        // ---- online softmax (rows r=lane>>2 and r+8), scale 0.125
        float mx0 = -INFINITY, mx1 = -INFINITY;
        #pragma unroll
        for (int n = 0; n < 8; n++) {
            mx0 = fmaxf(mx0, fmaxf(s_[n][0], s_[n][1]));
            mx1 = fmaxf(mx1, fmaxf(s_[n][2], s_[n][3]));
        }
        mx0 = fmaxf(mx0, __shfl_xor_sync(0xffffffffu, mx0, 1));
        mx0 = fmaxf(mx0, __shfl_xor_sync(0xffffffffu, mx0, 2));
        mx1 = fmaxf(mx1, __shfl_xor_sync(0xffffffffu, mx1, 1));
        mx1 = fmaxf(mx1, __shfl_xor_sync(0xffffffffu, mx1, 2));
        float mn0 = fmaxf(m0, mx0), mn1 = fmaxf(m1, mx1);
        float al0 = __expf(0.125f * (m0 - mn0));
        float al1 = __expf(0.125f * (m1 - mn1));
        m0 = mn0; m1 = mn1;

        float sum0 = 0.0f, sum1 = 0.0f;
        #pragma unroll
        for (int n = 0; n < 8; n++) {
            s_[n][0] = __expf(0.125f * (s_[n][0] - mn0));
            s_[n][1] = __expf(0.125f * (s_[n][1] - mn0));
            s_[n][2] = __expf(0.125f * (s_[n][2] - mn1));
            s_[n][3] = __expf(0.125f * (s_[n][3] - mn1));
            sum0 += s_[n][0] + s_[n][1];
            sum1 += s_[n][2] + s_[n][3];
        }
        sum0 += __shfl_xor_sync(0xffffffffu, sum0, 1);
        sum0 += __shfl_xor_sync(0xffffffffu, sum0, 2);
        sum1 += __shfl_xor_sync(0xffffffffu, sum1, 1);
        sum1 += __shfl_xor_sync(0xffffffffu, sum1, 2);
        l0 = l0 * al0 + sum0;
        l1 = l1 * al1 + sum1;

        #pragma unroll
        for (int n = 0; n < 8; n++) {
            o[n][0] *= al0; o[n][1] *= al0;
            o[n][2] *= al1; o[n][3] *= al1;
        }

        // ---- O += P @ V.  P a-frags come straight from s_ registers.
        #pragma unroll
        for (int j = 0; j < 4; j++) {
            uint32_t pah[4], pal[4];
            split_pack(s_[2*j][0],     s_[2*j][1],     pah[0], pal[0]);
            split_pack(s_[2*j][2],     s_[2*j][3],     pah[1], pal[1]);
            split_pack(s_[2*j + 1][0], s_[2*j + 1][1], pah[2], pal[2]);
            split_pack(s_[2*j + 1][2], s_[2*j + 1][3], pah[3], pal[3]);
            #pragma unroll
            for (int n = 0; n < 8; n++) {
                uint32_t vbh[2], vbl[2];
                uint32_t addr = VhiB + (uint32_t)(16 * j * APITCH + 8 * n) * 2 + vb_off;
                ldsm2_t(vbh, addr);
                ldsm2_t(vbl, addr + 4608 * 2);
                mma_bf16(o[n], pah, vbh);
                mma_bf16(o[n], pah, vbl);
                mma_bf16(o[n], pal, vbh);
            }
        }
        __syncthreads();
    }

    // ---- normalize + write
    const int b_ = bh / Hq, h = bh % Hq;
    const int r0 = q0 + wid * 16 + (lane >> 2);
    const float inv0 = 1.0f / l0;
    const float inv1 = 1.0f / l1;
    #pragma unroll
    for (int n = 0; n < 8; n++) {
        int col = h * 64 + 8 * n + 2 * (lane & 3);
        *(float2*)&g_att[(size_t)(b_ * Nq + r0) * Cq + col] =
            make_float2(o[n][0] * inv0, o[n][1] * inv0);
        *(float2*)&g_att[(size_t)(b_ * Nq + r0 + 8) * Cq + col] =
            make_float2(o[n][2] * inv1, o[n][3] * inv1);
    }
}

// =====================================================================
extern "C" void kernel_launch(void* const* d_in, const int* in_sizes, int n_in,
                              void* d_out, int out_size)
{
    const float* x      = (const float*)d_in[0];
    const float* W_qkv  = (const float*)d_in[1];
    const float* b_qkv  = (const float*)d_in[2];
    const float* W_proj = (const float*)d_in[3];
    const float* b_proj = (const float*)d_in[4];
    const int*   pos_h  = (const int*)d_in[5];
    const int*   pos_w  = (const int*)d_in[6];
    float*       out    = (float*)d_out;

    cudaFuncSetAttribute(qkv_wmma,
                         cudaFuncAttributeMaxDynamicSharedMemorySize,
                         (int)MM2_SMEM);
    cudaFuncSetAttribute(proj_wmma,
                         cudaFuncAttributeMaxDynamicSharedMemorySize,
                         (int)MM2_SMEM);

    qkv_wmma<<<dim3(18, 128), 256, MM2_SMEM>>>(x, W_qkv, b_qkv);
    rope_kernel<<<(2 * BH * Nq * 32) / 256, 256>>>(pos_h, pos_w);
    attn_mma<<<dim3(8, 192), 256>>>();
    proj_wmma<<<dim3(6, 128), 256, MM2_SMEM>>>(W_proj, b_proj, out);
}

// round 14
// speedup vs baseline: 2.3775x; 1.1956x over previous
#include <cuda_runtime.h>
#include <cuda_bf16.h>
#include <mma.h>
#include <math.h>
#include <stdint.h>

using namespace nvcuda;

#define Bq   16
#define Nq   1024
#define Cq   768
#define Hq   12
#define HD   64
#define BH   (Bq*Hq)        // 192
#define MROWS (Bq*Nq)       // 16384

// ---- scratch (no allocs allowed): bf16 hi/lo planes everywhere ----
__device__ __nv_bfloat16 g_xh[MROWS * Cq], g_xl[MROWS * Cq];          // x planes
__device__ __nv_bfloat16 g_qh[BH*Nq*HD], g_ql[BH*Nq*HD];
__device__ __nv_bfloat16 g_kh[BH*Nq*HD], g_kl[BH*Nq*HD];
__device__ __nv_bfloat16 g_vh[BH*Nq*HD], g_vl[BH*Nq*HD];
__device__ __nv_bfloat16 g_ah[MROWS * Cq], g_al[MROWS * Cq];          // attn out planes
__device__ __nv_bfloat16 g_wqh[2304 * Cq], g_wql[2304 * Cq];          // W_qkv^T [n][k]
__device__ __nv_bfloat16 g_wph[Cq * Cq],   g_wpl[Cq * Cq];            // W_proj^T [n][k]

__device__ __forceinline__ void split_pack(float x0, float x1,
                                           uint32_t& hi, uint32_t& lo) {
    __nv_bfloat16 h0 = __float2bfloat16_rn(x0);
    __nv_bfloat16 h1 = __float2bfloat16_rn(x1);
    __nv_bfloat16 l0 = __float2bfloat16_rn(x0 - __bfloat162float(h0));
    __nv_bfloat16 l1 = __float2bfloat16_rn(x1 - __bfloat162float(h1));
    hi = (uint32_t)__bfloat16_as_ushort(h0) | ((uint32_t)__bfloat16_as_ushort(h1) << 16);
    lo = (uint32_t)__bfloat16_as_ushort(l0) | ((uint32_t)__bfloat16_as_ushort(l1) << 16);
}

// ---- raw mma / ldmatrix helpers ----
__device__ __forceinline__ uint32_t smem_u32(const void* p) {
    uint32_t a;
    asm("{ .reg .u64 t; cvta.to.shared.u64 t, %1; cvt.u32.u64 %0, t; }"
        : "=r"(a) : "l"(p));
    return a;
}
__device__ __forceinline__ void ldsm4(uint32_t* r, uint32_t a) {
    asm volatile("ldmatrix.sync.aligned.m8n8.x4.shared.b16 {%0,%1,%2,%3}, [%4];"
                 : "=r"(r[0]), "=r"(r[1]), "=r"(r[2]), "=r"(r[3]) : "r"(a));
}
__device__ __forceinline__ void ldsm2(uint32_t* r, uint32_t a) {
    asm volatile("ldmatrix.sync.aligned.m8n8.x2.shared.b16 {%0,%1}, [%2];"
                 : "=r"(r[0]), "=r"(r[1]) : "r"(a));
}
__device__ __forceinline__ void ldsm2_t(uint32_t* r, uint32_t a) {
    asm volatile("ldmatrix.sync.aligned.m8n8.x2.trans.shared.b16 {%0,%1}, [%2];"
                 : "=r"(r[0]), "=r"(r[1]) : "r"(a));
}
__device__ __forceinline__ void mma_bf16(float* c, const uint32_t* a, const uint32_t* b) {
    asm volatile(
        "mma.sync.aligned.m16n8k16.row.col.f32.bf16.bf16.f32 "
        "{%0,%1,%2,%3}, {%4,%5,%6,%7}, {%8,%9}, {%0,%1,%2,%3};"
        : "+f"(c[0]), "+f"(c[1]), "+f"(c[2]), "+f"(c[3])
        : "r"(a[0]), "r"(a[1]), "r"(a[2]), "r"(a[3]), "r"(b[0]), "r"(b[1]));
}

// =====================================================================
// Prologue converts
// =====================================================================
__global__ __launch_bounds__(256) void convert_x(const float* __restrict__ x)
{
    int idx = blockIdx.x * 256 + threadIdx.x;      // pair index
    float2 v = *(const float2*)(x + 2 * (size_t)idx);
    uint32_t hi, lo;
    split_pack(v.x, v.y, hi, lo);
    ((uint32_t*)g_xh)[idx] = hi;
    ((uint32_t*)g_xl)[idx] = lo;
}

// W[k][NN] -> Wt[n][768] hi/lo planes (smem tile transpose)
__global__ __launch_bounds__(256) void convert_w(const float* __restrict__ W,
                                                 int NN, int which)
{
    __shared__ float tile[32][33];
    int n0 = blockIdx.x * 32;
    int k0 = blockIdx.y * 32;
    int tx = threadIdx.x & 31;
    int ty = threadIdx.x >> 5;     // 0..7
    #pragma unroll
    for (int i = 0; i < 4; i++)
        tile[ty + 8 * i][tx] = W[(size_t)(k0 + ty + 8 * i) * NN + n0 + tx];
    __syncthreads();
    __nv_bfloat16* dh = which ? g_wph : g_wqh;
    __nv_bfloat16* dl = which ? g_wpl : g_wql;
    #pragma unroll
    for (int i = 0; i < 4; i++) {
        int n = ty + 8 * i;
        float v = tile[tx][n];
        __nv_bfloat16 h = __float2bfloat16_rn(v);
        __nv_bfloat16 l = __float2bfloat16_rn(v - __bfloat162float(h));
        size_t off = (size_t)(n0 + n) * 768 + k0 + tx;
        dh[off] = h;
        dl[off] = l;
    }
}

// =====================================================================
// bf16x3 WMMA GEMMs on pre-split planes. Tile 128x128, chunk 32,
// double-buffered dynamic smem (81920B). No conversions in mainloop.
// =====================================================================
#define KCH  32
#define PADK 40
#define ST_M  (128 * PADK * 2)
#define STAGE (4 * ST_M)
#define OFF_AHI 0
#define OFF_ALO (ST_M)
#define OFF_BHI (2 * ST_M)
#define OFF_BLO (3 * ST_M)
#define MM2_SMEM (2 * STAGE)            // 81920 bytes dynamic

__global__ __launch_bounds__(256) void qkv_mm(const float* __restrict__ bias)
{
    extern __shared__ __align__(16) char smem[];
    int tid  = threadIdx.x;
    int lane = tid & 31;
    int wid  = tid >> 5;
    int wm   = wid >> 2;
    int wn   = wid & 3;

    const int m0 = blockIdx.y * 128;
    const int n0 = blockIdx.x * 128;
    const __nv_bfloat16* Ah_g = g_xh;
    const __nv_bfloat16* Al_g = g_xl;
    const __nv_bfloat16* Bh_g = g_wqh;
    const __nv_bfloat16* Bl_g = g_wql;

    wmma::fragment<wmma::accumulator, 16, 16, 16, float> acc[4][2];
    #pragma unroll
    for (int mi = 0; mi < 4; mi++)
        #pragma unroll
        for (int ni = 0; ni < 2; ni++)
            wmma::fill_fragment(acc[mi][ni], 0.0f);

    // preload chunk 0
    #pragma unroll
    for (int it = 0; it < 2; it++) {
        int idx = tid + it * 256;      // 0..511
        int m = idx >> 2, kq = idx & 3;
        *(uint4*)(smem + OFF_AHI + m * 80 + kq * 16) =
            *(const uint4*)(Ah_g + (size_t)(m0 + m) * 768 + kq * 8);
        *(uint4*)(smem + OFF_ALO + m * 80 + kq * 16) =
            *(const uint4*)(Al_g + (size_t)(m0 + m) * 768 + kq * 8);
    }
    #pragma unroll
    for (int it = 0; it < 2; it++) {
        int idx = tid + it * 256;
        int n = idx >> 2, kq = idx & 3;
        *(uint4*)(smem + OFF_BHI + n * 80 + kq * 16) =
            *(const uint4*)(Bh_g + (size_t)(n0 + n) * 768 + kq * 8);
        *(uint4*)(smem + OFF_BLO + n * 80 + kq * 16) =
            *(const uint4*)(Bl_g + (size_t)(n0 + n) * 768 + kq * 8);
    }
    __syncthreads();

    const int NCH = 768 / KCH;   // 24
    for (int ch = 0; ch < NCH; ch++) {
        char* cb_ = smem + (ch & 1) * STAGE;
        char* nb_ = smem + ((ch & 1) ^ 1) * STAGE;

        uint4 ra[2], rla[2], rb[2], rlb[2];
        if (ch + 1 < NCH) {
            const int k0n = (ch + 1) * KCH;
            #pragma unroll
            for (int it = 0; it < 2; it++) {
                int idx = tid + it * 256;
                int m = idx >> 2, kq = idx & 3;
                ra[it]  = *(const uint4*)(Ah_g + (size_t)(m0 + m) * 768 + k0n + kq * 8);
                rla[it] = *(const uint4*)(Al_g + (size_t)(m0 + m) * 768 + k0n + kq * 8);
            }
            #pragma unroll
            for (int it = 0; it < 2; it++) {
                int idx = tid + it * 256;
                int n = idx >> 2, kq = idx & 3;
                rb[it]  = *(const uint4*)(Bh_g + (size_t)(n0 + n) * 768 + k0n + kq * 8);
                rlb[it] = *(const uint4*)(Bl_g + (size_t)(n0 + n) * 768 + k0n + kq * 8);
            }
        }

        const __nv_bfloat16* Ah = (const __nv_bfloat16*)(cb_ + OFF_AHI);
        const __nv_bfloat16* Bh = (const __nv_bfloat16*)(cb_ + OFF_BHI);
        #pragma unroll
        for (int ks = 0; ks < 2; ks++) {
            const int kk = ks * 16;
            wmma::fragment<wmma::matrix_b, 16, 16, 16, __nv_bfloat16, wmma::col_major> fbh[2], fbl[2];
            #pragma unroll
            for (int ni = 0; ni < 2; ni++) {
                const __nv_bfloat16* bp = Bh + (wn * 32 + ni * 16) * PADK + kk;
                wmma::load_matrix_sync(fbh[ni], bp, PADK);
                wmma::load_matrix_sync(fbl[ni], bp + (ST_M / 2), PADK);
            }
            #pragma unroll
            for (int mi = 0; mi < 4; mi++) {
                wmma::fragment<wmma::matrix_a, 16, 16, 16, __nv_bfloat16, wmma::row_major> fah, fal;
                const __nv_bfloat16* ap = Ah + (wm * 64 + mi * 16) * PADK + kk;
                wmma::load_matrix_sync(fah, ap, PADK);
                wmma::load_matrix_sync(fal, ap + (ST_M / 2), PADK);
                #pragma unroll
                for (int ni = 0; ni < 2; ni++) {
                    wmma::mma_sync(acc[mi][ni], fah, fbh[ni], acc[mi][ni]);
                    wmma::mma_sync(acc[mi][ni], fah, fbl[ni], acc[mi][ni]);
                    wmma::mma_sync(acc[mi][ni], fal, fbh[ni], acc[mi][ni]);
                }
            }
        }

        if (ch + 1 < NCH) {
            #pragma unroll
            for (int it = 0; it < 2; it++) {
                int idx = tid + it * 256;
                int m = idx >> 2, kq = idx & 3;
                *(uint4*)(nb_ + OFF_AHI + m * 80 + kq * 16) = ra[it];
                *(uint4*)(nb_ + OFF_ALO + m * 80 + kq * 16) = rla[it];
            }
            #pragma unroll
            for (int it = 0; it < 2; it++) {
                int idx = tid + it * 256;
                int n = idx >> 2, kq = idx & 3;
                *(uint4*)(nb_ + OFF_BHI + n * 80 + kq * 16) = rb[it];
                *(uint4*)(nb_ + OFF_BLO + n * 80 + kq * 16) = rlb[it];
            }
        }
        __syncthreads();
    }

    // epilogue: through smem patch, scatter to q/k/v hi/lo planes
    float* patch = (float*)smem + wid * (16 * 20);
    const int r_loc = lane >> 1;
    const int c_loc = (lane & 1) * 8;

    #pragma unroll
    for (int mi = 0; mi < 4; mi++) {
        #pragma unroll
        for (int ni = 0; ni < 2; ni++) {
            wmma::store_matrix_sync(patch, acc[mi][ni], 20, wmma::mem_row_major);
            __syncwarp();
            int r  = m0 + wm * 64 + mi * 16 + r_loc;
            int cb = n0 + wn * 32 + ni * 16 + c_loc;
            float vv[8];
            #pragma unroll
            for (int j = 0; j < 8; j++)
                vv[j] = patch[r_loc * 20 + c_loc + j] + bias[cb + j];

            int b_  = r >> 10, tok = r & 1023;
            int s   = cb / Cq;
            int rem = cb - s * Cq;
            int h   = rem >> 6, d = rem & 63;
            __nv_bfloat16* dh = (s == 0) ? g_qh : ((s == 1) ? g_kh : g_vh);
            __nv_bfloat16* dl = (s == 0) ? g_ql : ((s == 1) ? g_kl : g_vl);
            size_t off = (size_t)(((b_ * Hq + h) << 16) + (tok << 6) + d);
            #pragma unroll
            for (int j = 0; j < 8; j += 2) {
                uint32_t hi, lo;
                split_pack(vv[j], vv[j + 1], hi, lo);
                *(uint32_t*)(dh + off + j) = hi;
                *(uint32_t*)(dl + off + j) = lo;
            }
            __syncwarp();
        }
    }
}

__global__ __launch_bounds__(256) void proj_mm(const float* __restrict__ bias,
                                               float* __restrict__ out)
{
    extern __shared__ __align__(16) char smem[];
    int tid  = threadIdx.x;
    int lane = tid & 31;
    int wid  = tid >> 5;
    int wm   = wid >> 2;
    int wn   = wid & 3;

    const int m0 = blockIdx.y * 128;
    const int n0 = blockIdx.x * 128;
    const __nv_bfloat16* Ah_g = g_ah;
    const __nv_bfloat16* Al_g = g_al;
    const __nv_bfloat16* Bh_g = g_wph;
    const __nv_bfloat16* Bl_g = g_wpl;

    wmma::fragment<wmma::accumulator, 16, 16, 16, float> acc[4][2];
    #pragma unroll
    for (int mi = 0; mi < 4; mi++)
        #pragma unroll
        for (int ni = 0; ni < 2; ni++)
            wmma::fill_fragment(acc[mi][ni], 0.0f);

    #pragma unroll
    for (int it = 0; it < 2; it++) {
        int idx = tid + it * 256;
        int m = idx >> 2, kq = idx & 3;
        *(uint4*)(smem + OFF_AHI + m * 80 + kq * 16) =
            *(const uint4*)(Ah_g + (size_t)(m0 + m) * 768 + kq * 8);
        *(uint4*)(smem + OFF_ALO + m * 80 + kq * 16) =
            *(const uint4*)(Al_g + (size_t)(m0 + m) * 768 + kq * 8);
    }
    #pragma unroll
    for (int it = 0; it < 2; it++) {
        int idx = tid + it * 256;
        int n = idx >> 2, kq = idx & 3;
        *(uint4*)(smem + OFF_BHI + n * 80 + kq * 16) =
            *(const uint4*)(Bh_g + (size_t)(n0 + n) * 768 + kq * 8);
        *(uint4*)(smem + OFF_BLO + n * 80 + kq * 16) =
            *(const uint4*)(Bl_g + (size_t)(n0 + n) * 768 + kq * 8);
    }
    __syncthreads();

    const int NCH = 768 / KCH;
    for (int ch = 0; ch < NCH; ch++) {
        char* cb_ = smem + (ch & 1) * STAGE;
        char* nb_ = smem + ((ch & 1) ^ 1) * STAGE;

        uint4 ra[2], rla[2], rb[2], rlb[2];
        if (ch + 1 < NCH) {
            const int k0n = (ch + 1) * KCH;
            #pragma unroll
            for (int it = 0; it < 2; it++) {
                int idx = tid + it * 256;
                int m = idx >> 2, kq = idx & 3;
                ra[it]  = *(const uint4*)(Ah_g + (size_t)(m0 + m) * 768 + k0n + kq * 8);
                rla[it] = *(const uint4*)(Al_g + (size_t)(m0 + m) * 768 + k0n + kq * 8);
            }
            #pragma unroll
            for (int it = 0; it < 2; it++) {
                int idx = tid + it * 256;
                int n = idx >> 2, kq = idx & 3;
                rb[it]  = *(const uint4*)(Bh_g + (size_t)(n0 + n) * 768 + k0n + kq * 8);
                rlb[it] = *(const uint4*)(Bl_g + (size_t)(n0 + n) * 768 + k0n + kq * 8);
            }
        }

        const __nv_bfloat16* Ah = (const __nv_bfloat16*)(cb_ + OFF_AHI);
        const __nv_bfloat16* Bh = (const __nv_bfloat16*)(cb_ + OFF_BHI);
        #pragma unroll
        for (int ks = 0; ks < 2; ks++) {
            const int kk = ks * 16;
            wmma::fragment<wmma::matrix_b, 16, 16, 16, __nv_bfloat16, wmma::col_major> fbh[2], fbl[2];
            #pragma unroll
            for (int ni = 0; ni < 2; ni++) {
                const __nv_bfloat16* bp = Bh + (wn * 32 + ni * 16) * PADK + kk;
                wmma::load_matrix_sync(fbh[ni], bp, PADK);
                wmma::load_matrix_sync(fbl[ni], bp + (ST_M / 2), PADK);
            }
            #pragma unroll
            for (int mi = 0; mi < 4; mi++) {
                wmma::fragment<wmma::matrix_a, 16, 16, 16, __nv_bfloat16, wmma::row_major> fah, fal;
                const __nv_bfloat16* ap = Ah + (wm * 64 + mi * 16) * PADK + kk;
                wmma::load_matrix_sync(fah, ap, PADK);
                wmma::load_matrix_sync(fal, ap + (ST_M / 2), PADK);
                #pragma unroll
                for (int ni = 0; ni < 2; ni++) {
                    wmma::mma_sync(acc[mi][ni], fah, fbh[ni], acc[mi][ni]);
                    wmma::mma_sync(acc[mi][ni], fah, fbl[ni], acc[mi][ni]);
                    wmma::mma_sync(acc[mi][ni], fal, fbh[ni], acc[mi][ni]);
                }
            }
        }

        if (ch + 1 < NCH) {
            #pragma unroll
            for (int it = 0; it < 2; it++) {
                int idx = tid + it * 256;
                int m = idx >> 2, kq = idx & 3;
                *(uint4*)(nb_ + OFF_AHI + m * 80 + kq * 16) = ra[it];
                *(uint4*)(nb_ + OFF_ALO + m * 80 + kq * 16) = rla[it];
            }
            #pragma unroll
            for (int it = 0; it < 2; it++) {
                int idx = tid + it * 256;
                int n = idx >> 2, kq = idx & 3;
                *(uint4*)(nb_ + OFF_BHI + n * 80 + kq * 16) = rb[it];
                *(uint4*)(nb_ + OFF_BLO + n * 80 + kq * 16) = rlb[it];
            }
        }
        __syncthreads();
    }

    float* patch = (float*)smem + wid * (16 * 20);
    const int r_loc = lane >> 1;
    const int c_loc = (lane & 1) * 8;

    #pragma unroll
    for (int mi = 0; mi < 4; mi++) {
        #pragma unroll
        for (int ni = 0; ni < 2; ni++) {
            wmma::store_matrix_sync(patch, acc[mi][ni], 20, wmma::mem_row_major);
            __syncwarp();
            int r  = m0 + wm * 64 + mi * 16 + r_loc;
            int cb = n0 + wn * 32 + ni * 16 + c_loc;
            float* obase = out + (size_t)r * Cq + cb;
            #pragma unroll
            for (int j = 0; j < 8; j += 2) {
                float v0 = patch[r_loc * 20 + c_loc + j]     + bias[cb + j];
                float v1 = patch[r_loc * 20 + c_loc + j + 1] + bias[cb + j + 1];
                *(float2*)(obase + j) = make_float2(v0, v1);
            }
            __syncwarp();
        }
    }
}

// =====================================================================
// RoPE on q/k hi/lo planes (in place).
// =====================================================================
__global__ void rope_kernel(const int* __restrict__ pos_h,
                            const int* __restrict__ pos_w)
{
    int idx = blockIdx.x * blockDim.x + threadIdx.x;
    int j    = idx & 15;
    int half = (idx >> 4) & 1;
    int tok  = (idx >> 5) & 1023;
    int rest = idx >> 15;           // 0..383
    if (rest >= 2 * BH) return;
    int bh   = rest % BH;
    int tens = rest / BH;           // 0=q, 1=k
    int b_ = bh / Hq;
    int pos = half ? pos_w[b_ * Nq + tok] : pos_h[b_ * Nq + tok];
    float fp = (float)pos;
    size_t base = ((size_t)bh << 16) + (tok << 6) + half * 32;
    __nv_bfloat16* ph = (tens ? g_kh : g_qh) + base;
    __nv_bfloat16* pl = (tens ? g_kl : g_ql) + base;
    float t0 = __bfloat162float(ph[j])      + __bfloat162float(pl[j]);
    float t1 = __bfloat162float(ph[j + 16]) + __bfloat162float(pl[j + 16]);
    float L = logf(10000.0f);
    float inv0 = expf(-(float)(j >> 1)       / 16.0f * L);
    float inv1 = expf(-(float)(8 + (j >> 1)) / 16.0f * L);
    float s0, c0, s1, c1;
    sincosf(fp * inv0, &s0, &c0);
    sincosf(fp * inv1, &s1, &c1);
    float r0 = t0 * c0 - t1 * s0;
    float r1 = t1 * c1 + t0 * s1;
    __nv_bfloat16 h0 = __float2bfloat16_rn(r0);
    __nv_bfloat16 h1 = __float2bfloat16_rn(r1);
    ph[j]      = h0;
    pl[j]      = __float2bfloat16_rn(r0 - __bfloat162float(h0));
    ph[j + 16] = h1;
    pl[j + 16] = __float2bfloat16_rn(r1 - __bfloat162float(h1));
}

// =====================================================================
// FA2 flash attention on raw mma.sync, bf16 planes in = bf16 planes out.
// =====================================================================
#define APITCH 72

__global__ __launch_bounds__(256) void attn_mma()
{
    __shared__ __nv_bfloat16 sbuf[4 * 64 * APITCH];   // 36864 B

    const int tid  = threadIdx.x;
    const int lane = tid & 31;
    const int wid  = tid >> 5;
    const int bh   = blockIdx.y;
    const int q0   = blockIdx.x * 128;
    const size_t hb = (size_t)bh << 16;
    const __nv_bfloat16* Qh_g = g_qh + hb;
    const __nv_bfloat16* Ql_g = g_ql + hb;
    const __nv_bfloat16* Kh_g = g_kh + hb;
    const __nv_bfloat16* Kl_g = g_kl + hb;
    const __nv_bfloat16* Vh_g = g_vh + hb;
    const __nv_bfloat16* Vl_g = g_vl + hb;

    const uint32_t sb = smem_u32(sbuf);
    const uint32_t qa_off = (uint32_t)((lane & 15) * APITCH + 8 * (lane >> 4)) * 2;
    const uint32_t kb_off = (uint32_t)((lane & 7) * APITCH + 8 * ((lane >> 3) & 1)) * 2;
    const uint32_t vb_off = (uint32_t)(((lane & 7) + 8 * ((lane >> 3) & 1)) * APITCH) * 2;

    // ---- stage Q planes [128][64]
    #pragma unroll
    for (int it = 0; it < 4; it++) {
        int idx = tid + it * 256;          // 0..1023 uint4
        int m = idx >> 3, kq = idx & 7;
        *(uint4*)((char*)sbuf + (m * APITCH + kq * 8) * 2) =
            *(const uint4*)(Qh_g + (size_t)(q0 + m) * 64 + kq * 8);
        *(uint4*)((char*)sbuf + (9216 + m * APITCH + kq * 8) * 2) =
            *(const uint4*)(Ql_g + (size_t)(q0 + m) * 64 + kq * 8);
    }
    __syncthreads();

    uint32_t qh[4][4], ql[4][4];
    {
        uint32_t qbase = sb + (uint32_t)(wid * 16 * APITCH) * 2 + qa_off;
        #pragma unroll
        for (int j = 0; j < 4; j++) {
            ldsm4(qh[j], qbase + (uint32_t)(16 * j) * 2);
            ldsm4(ql[j], qbase + (uint32_t)(9216 + 16 * j) * 2);
        }
    }
    __syncthreads();

    const uint32_t KhiB = sb;
    const uint32_t VhiB = sb + 9216 * 2;

    float o[8][4] = {};
    float m0 = -INFINITY, m1 = -INFINITY, l0 = 0.0f, l1 = 0.0f;

    for (int t = 0; t < 16; t++) {
        const int kt0 = t * 64;
        // ---- copy K/V planes [64][64] (pure uint4 copies)
        #pragma unroll
        for (int it = 0; it < 2; it++) {
            int idx = tid + it * 256;      // 0..511
            int c = idx >> 3, kq = idx & 7;
            size_t src = (size_t)(kt0 + c) * 64 + kq * 8;
            uint32_t d0 = (uint32_t)(c * APITCH + kq * 8) * 2;
            *(uint4*)((char*)sbuf + d0)            = *(const uint4*)(Kh_g + src);
            *(uint4*)((char*)sbuf + d0 + 4608 * 2) = *(const uint4*)(Kl_g + src);
            *(uint4*)((char*)sbuf + d0 + 9216 * 2) = *(const uint4*)(Vh_g + src);
            *(uint4*)((char*)sbuf + d0 + 13824 * 2) = *(const uint4*)(Vl_g + src);
        }
        __syncthreads();

        // ---- S = Q @ K^T, bf16x3
        float s_[8][4];
        #pragma unroll
        for (int n = 0; n < 8; n++) {
            s_[n][0] = 0.0f; s_[n][1] = 0.0f; s_[n][2] = 0.0f; s_[n][3] = 0.0f;
        }
        #pragma unroll
        for (int j = 0; j < 4; j++) {
            #pragma unroll
            for (int n = 0; n < 8; n++) {
                uint32_t kbh[2], kbl[2];
                uint32_t addr = KhiB + (uint32_t)(n * 8 * APITCH + 16 * j) * 2 + kb_off;
                ldsm2(kbh, addr);
                ldsm2(kbl, addr + 4608 * 2);
                mma_bf16(s_[n], qh[j], kbh);
                mma_bf16(s_[n], qh[j], kbl);
                mma_bf16(s_[n], ql[j], kbh);
            }
        }

        // ---- online softmax
        float mx0 = -INFINITY, mx1 = -INFINITY;
        #pragma unroll
        for (int n = 0; n < 8; n++) {
            mx0 = fmaxf(mx0, fmaxf(s_[n][0], s_[n][1]));
            mx1 = fmaxf(mx1, fmaxf(s_[n][2], s_[n][3]));
        }
        mx0 = fmaxf(mx0, __shfl_xor_sync(0xffffffffu, mx0, 1));
        mx0 = fmaxf(mx0, __shfl_xor_sync(0xffffffffu, mx0, 2));
        mx1 = fmaxf(mx1, __shfl_xor_sync(0xffffffffu, mx1, 1));
        mx1 = fmaxf(mx1, __shfl_xor_sync(0xffffffffu, mx1, 2));
        float mn0 = fmaxf(m0, mx0), mn1 = fmaxf(m1, mx1);
        float al0 = __expf(0.125f * (m0 - mn0));
        float al1 = __expf(0.125f * (m1 - mn1));
        m0 = mn0; m1 = mn1;

        float sum0 = 0.0f, sum1 = 0.0f;
        #pragma unroll
        for (int n = 0; n < 8; n++) {
            s_[n][0] = __expf(0.125f * (s_[n][0] - mn0));
            s_[n][1] = __expf(0.125f * (s_[n][1] - mn0));
            s_[n][2] = __expf(0.125f * (s_[n][2] - mn1));
            s_[n][3] = __expf(0.125f * (s_[n][3] - mn1));
            sum0 += s_[n][0] + s_[n][1];
            sum1 += s_[n][2] + s_[n][3];
        }
        sum0 += __shfl_xor_sync(0xffffffffu, sum0, 1);
        sum0 += __shfl_xor_sync(0xffffffffu, sum0, 2);
        sum1 += __shfl_xor_sync(0xffffffffu, sum1, 1);
        sum1 += __shfl_xor_sync(0xffffffffu, sum1, 2);
        l0 = l0 * al0 + sum0;
        l1 = l1 * al1 + sum1;

        #pragma unroll
        for (int n = 0; n < 8; n++) {
            o[n][0] *= al0; o[n][1] *= al0;
            o[n][2] *= al1; o[n][3] *= al1;
        }

        // ---- O += P @ V
        #pragma unroll
        for (int j = 0; j < 4; j++) {
            uint32_t pah[4], pal[4];
            split_pack(s_[2*j][0],     s_[2*j][1],     pah[0], pal[0]);
            split_pack(s_[2*j][2],     s_[2*j][3],     pah[1], pal[1]);
            split_pack(s_[2*j + 1][0], s_[2*j + 1][1], pah[2], pal[2]);
            split_pack(s_[2*j + 1][2], s_[2*j + 1][3], pah[3], pal[3]);
            #pragma unroll
            for (int n = 0; n < 8; n++) {
                uint32_t vbh[2], vbl[2];
                uint32_t addr = VhiB + (uint32_t)(16 * j * APITCH + 8 * n) * 2 + vb_off;
                ldsm2_t(vbh, addr);
                ldsm2_t(vbl, addr + 4608 * 2);
                mma_bf16(o[n], pah, vbh);
                mma_bf16(o[n], pah, vbl);
                mma_bf16(o[n], pal, vbh);
            }
        }
        __syncthreads();
    }

    // ---- normalize + write hi/lo planes of attention output
    const int b_ = bh / Hq, h = bh % Hq;
    const int r0 = q0 + wid * 16 + (lane >> 2);
    const float inv0 = 1.0f / l0;
    const float inv1 = 1.0f / l1;
    #pragma unroll
    for (int n = 0; n < 8; n++) {
        int col = h * 64 + 8 * n + 2 * (lane & 3);
        size_t off0 = (size_t)(b_ * Nq + r0) * Cq + col;
        size_t off1 = (size_t)(b_ * Nq + r0 + 8) * Cq + col;
        uint32_t hi, lo;
        split_pack(o[n][0] * inv0, o[n][1] * inv0, hi, lo);
        *(uint32_t*)(g_ah + off0) = hi;
        *(uint32_t*)(g_al + off0) = lo;
        split_pack(o[n][2] * inv1, o[n][3] * inv1, hi, lo);
        *(uint32_t*)(g_ah + off1) = hi;
        *(uint32_t*)(g_al + off1) = lo;
    }
}

// =====================================================================
extern "C" void kernel_launch(void* const* d_in, const int* in_sizes, int n_in,
                              void* d_out, int out_size)
{
    const float* x      = (const float*)d_in[0];
    const float* W_qkv  = (const float*)d_in[1];
    const float* b_qkv  = (const float*)d_in[2];
    const float* W_proj = (const float*)d_in[3];
    const float* b_proj = (const float*)d_in[4];
    const int*   pos_h  = (const int*)d_in[5];
    const int*   pos_w  = (const int*)d_in[6];
    float*       out    = (float*)d_out;

    cudaFuncSetAttribute(qkv_mm,
                         cudaFuncAttributeMaxDynamicSharedMemorySize,
                         (int)MM2_SMEM);
    cudaFuncSetAttribute(proj_mm,
                         cudaFuncAttributeMaxDynamicSharedMemorySize,
                         (int)MM2_SMEM);

    convert_x<<<(MROWS * Cq / 2) / 256, 256>>>(x);
    convert_w<<<dim3(2304 / 32, 768 / 32), 256>>>(W_qkv, 3 * Cq, 0);
    convert_w<<<dim3(768 / 32, 768 / 32), 256>>>(W_proj, Cq, 1);
    qkv_mm<<<dim3(18, 128), 256, MM2_SMEM>>>(b_qkv);
    rope_kernel<<<(2 * BH * Nq * 32) / 256, 256>>>(pos_h, pos_w);
    attn_mma<<<dim3(8, 192), 256>>>();
    proj_mm<<<dim3(6, 128), 256, MM2_SMEM>>>(b_proj, out);
}

// round 15
// speedup vs baseline: 2.6333x; 1.1076x over previous
#include <cuda_runtime.h>
#include <cuda_bf16.h>
#include <mma.h>
#include <math.h>
#include <stdint.h>

using namespace nvcuda;

#define Bq   16
#define Nq   1024
#define Cq   768
#define Hq   12
#define HD   64
#define BH   (Bq*Hq)        // 192
#define MROWS (Bq*Nq)       // 16384

// ---- scratch (no allocs allowed): bf16 hi/lo planes everywhere ----
__device__ __nv_bfloat16 g_xh[MROWS * Cq], g_xl[MROWS * Cq];
__device__ __nv_bfloat16 g_qh[BH*Nq*HD], g_ql[BH*Nq*HD];
__device__ __nv_bfloat16 g_kh[BH*Nq*HD], g_kl[BH*Nq*HD];
__device__ __nv_bfloat16 g_vh[BH*Nq*HD], g_vl[BH*Nq*HD];
__device__ __nv_bfloat16 g_ah[MROWS * Cq], g_al[MROWS * Cq];
__device__ __nv_bfloat16 g_wqh[2304 * Cq], g_wql[2304 * Cq];
__device__ __nv_bfloat16 g_wph[Cq * Cq],   g_wpl[Cq * Cq];

__device__ __forceinline__ void split_pack(float x0, float x1,
                                           uint32_t& hi, uint32_t& lo) {
    __nv_bfloat16 h0 = __float2bfloat16_rn(x0);
    __nv_bfloat16 h1 = __float2bfloat16_rn(x1);
    __nv_bfloat16 l0 = __float2bfloat16_rn(x0 - __bfloat162float(h0));
    __nv_bfloat16 l1 = __float2bfloat16_rn(x1 - __bfloat162float(h1));
    hi = (uint32_t)__bfloat16_as_ushort(h0) | ((uint32_t)__bfloat16_as_ushort(h1) << 16);
    lo = (uint32_t)__bfloat16_as_ushort(l0) | ((uint32_t)__bfloat16_as_ushort(l1) << 16);
}

// ---- helpers ----
__device__ __forceinline__ uint32_t smem_u32(const void* p) {
    uint32_t a;
    asm("{ .reg .u64 t; cvta.to.shared.u64 t, %1; cvt.u32.u64 %0, t; }"
        : "=r"(a) : "l"(p));
    return a;
}
__device__ __forceinline__ void cp_async16(uint32_t dst, const void* src) {
    asm volatile("cp.async.cg.shared.global [%0], [%1], 16;"
                 :: "r"(dst), "l"(src));
}
#define CP_COMMIT() asm volatile("cp.async.commit_group;")
#define CP_WAIT0()  asm volatile("cp.async.wait_group 0;")

__device__ __forceinline__ void ldsm4(uint32_t* r, uint32_t a) {
    asm volatile("ldmatrix.sync.aligned.m8n8.x4.shared.b16 {%0,%1,%2,%3}, [%4];"
                 : "=r"(r[0]), "=r"(r[1]), "=r"(r[2]), "=r"(r[3]) : "r"(a));
}
__device__ __forceinline__ void ldsm2(uint32_t* r, uint32_t a) {
    asm volatile("ldmatrix.sync.aligned.m8n8.x2.shared.b16 {%0,%1}, [%2];"
                 : "=r"(r[0]), "=r"(r[1]) : "r"(a));
}
__device__ __forceinline__ void ldsm2_t(uint32_t* r, uint32_t a) {
    asm volatile("ldmatrix.sync.aligned.m8n8.x2.trans.shared.b16 {%0,%1}, [%2];"
                 : "=r"(r[0]), "=r"(r[1]) : "r"(a));
}
__device__ __forceinline__ void mma_bf16(float* c, const uint32_t* a, const uint32_t* b) {
    asm volatile(
        "mma.sync.aligned.m16n8k16.row.col.f32.bf16.bf16.f32 "
        "{%0,%1,%2,%3}, {%4,%5,%6,%7}, {%8,%9}, {%0,%1,%2,%3};"
        : "+f"(c[0]), "+f"(c[1]), "+f"(c[2]), "+f"(c[3])
        : "r"(a[0]), "r"(a[1]), "r"(a[2]), "r"(a[3]), "r"(b[0]), "r"(b[1]));
}

// =====================================================================
// Prologue converts
// =====================================================================
__global__ __launch_bounds__(256) void convert_x(const float* __restrict__ x)
{
    int idx = blockIdx.x * 256 + threadIdx.x;
    float2 v = *(const float2*)(x + 2 * (size_t)idx);
    uint32_t hi, lo;
    split_pack(v.x, v.y, hi, lo);
    ((uint32_t*)g_xh)[idx] = hi;
    ((uint32_t*)g_xl)[idx] = lo;
}

__global__ __launch_bounds__(256) void convert_w(const float* __restrict__ W,
                                                 int NN, int which)
{
    __shared__ float tile[32][33];
    int n0 = blockIdx.x * 32;
    int k0 = blockIdx.y * 32;
    int tx = threadIdx.x & 31;
    int ty = threadIdx.x >> 5;
    #pragma unroll
    for (int i = 0; i < 4; i++)
        tile[ty + 8 * i][tx] = W[(size_t)(k0 + ty + 8 * i) * NN + n0 + tx];
    __syncthreads();
    __nv_bfloat16* dh = which ? g_wph : g_wqh;
    __nv_bfloat16* dl = which ? g_wpl : g_wql;
    #pragma unroll
    for (int i = 0; i < 4; i++) {
        int n = ty + 8 * i;
        float v = tile[tx][n];
        __nv_bfloat16 h = __float2bfloat16_rn(v);
        __nv_bfloat16 l = __float2bfloat16_rn(v - __bfloat162float(h));
        size_t off = (size_t)(n0 + n) * 768 + k0 + tx;
        dh[off] = h;
        dl[off] = l;
    }
}

// =====================================================================
// bf16x3 WMMA GEMMs, cp.async double-buffered, 2 CTAs/SM target.
// =====================================================================
#define KCH  32
#define PADK 40
#define ST_M  (128 * PADK * 2)
#define STAGE (4 * ST_M)
#define OFF_AHI 0
#define OFF_ALO (ST_M)
#define OFF_BHI (2 * ST_M)
#define OFF_BLO (3 * ST_M)
#define MM2_SMEM (2 * STAGE)            // 81920 bytes dynamic

__global__ __launch_bounds__(256, 2) void qkv_mm(const float* __restrict__ bias)
{
    extern __shared__ __align__(16) char smem[];
    const uint32_t sb = smem_u32(smem);
    int tid  = threadIdx.x;
    int lane = tid & 31;
    int wid  = tid >> 5;
    int wm   = wid >> 2;
    int wn   = wid & 3;

    const int m0 = blockIdx.y * 128;
    const int n0 = blockIdx.x * 128;
    const __nv_bfloat16* Ah_g = g_xh;
    const __nv_bfloat16* Al_g = g_xl;
    const __nv_bfloat16* Bh_g = g_wqh;
    const __nv_bfloat16* Bl_g = g_wql;

    // per-thread load coords
    const int lm  = tid >> 2;          // 0..63 (A rows: lm, lm+64)
    const int lkq = tid & 3;

    wmma::fragment<wmma::accumulator, 16, 16, 16, float> acc[4][2];
    #pragma unroll
    for (int mi = 0; mi < 4; mi++)
        #pragma unroll
        for (int ni = 0; ni < 2; ni++)
            wmma::fill_fragment(acc[mi][ni], 0.0f);

    // issue chunk loads via cp.async
    #define QKV_LOAD(CH, BUF) do {                                            \
        const int _k0 = (CH) * KCH;                                           \
        uint32_t _d = sb + (BUF) * STAGE;                                     \
        cp_async16(_d + OFF_AHI + lm * 80 + lkq * 16,                         \
                   Ah_g + (size_t)(m0 + lm) * 768 + _k0 + lkq * 8);           \
        cp_async16(_d + OFF_AHI + (lm + 64) * 80 + lkq * 16,                  \
                   Ah_g + (size_t)(m0 + lm + 64) * 768 + _k0 + lkq * 8);      \
        cp_async16(_d + OFF_ALO + lm * 80 + lkq * 16,                         \
                   Al_g + (size_t)(m0 + lm) * 768 + _k0 + lkq * 8);           \
        cp_async16(_d + OFF_ALO + (lm + 64) * 80 + lkq * 16,                  \
                   Al_g + (size_t)(m0 + lm + 64) * 768 + _k0 + lkq * 8);      \
        cp_async16(_d + OFF_BHI + lm * 80 + lkq * 16,                         \
                   Bh_g + (size_t)(n0 + lm) * 768 + _k0 + lkq * 8);           \
        cp_async16(_d + OFF_BHI + (lm + 64) * 80 + lkq * 16,                  \
                   Bh_g + (size_t)(n0 + lm + 64) * 768 + _k0 + lkq * 8);      \
        cp_async16(_d + OFF_BLO + lm * 80 + lkq * 16,                         \
                   Bl_g + (size_t)(n0 + lm) * 768 + _k0 + lkq * 8);           \
        cp_async16(_d + OFF_BLO + (lm + 64) * 80 + lkq * 16,                  \
                   Bl_g + (size_t)(n0 + lm + 64) * 768 + _k0 + lkq * 8);      \
        CP_COMMIT();                                                          \
    } while (0)

    QKV_LOAD(0, 0);

    const int NCH = 768 / KCH;   // 24
    for (int ch = 0; ch < NCH; ch++) {
        CP_WAIT0();
        __syncthreads();
        if (ch + 1 < NCH) QKV_LOAD(ch + 1, (ch + 1) & 1);

        char* cb_ = smem + (ch & 1) * STAGE;
        const __nv_bfloat16* Ah = (const __nv_bfloat16*)(cb_ + OFF_AHI);
        const __nv_bfloat16* Bh = (const __nv_bfloat16*)(cb_ + OFF_BHI);
        #pragma unroll
        for (int ks = 0; ks < 2; ks++) {
            const int kk = ks * 16;
            wmma::fragment<wmma::matrix_b, 16, 16, 16, __nv_bfloat16, wmma::col_major> fbh[2], fbl[2];
            #pragma unroll
            for (int ni = 0; ni < 2; ni++) {
                const __nv_bfloat16* bp = Bh + (wn * 32 + ni * 16) * PADK + kk;
                wmma::load_matrix_sync(fbh[ni], bp, PADK);
                wmma::load_matrix_sync(fbl[ni], bp + (ST_M / 2), PADK);
            }
            #pragma unroll
            for (int mi = 0; mi < 4; mi++) {
                wmma::fragment<wmma::matrix_a, 16, 16, 16, __nv_bfloat16, wmma::row_major> fah, fal;
                const __nv_bfloat16* ap = Ah + (wm * 64 + mi * 16) * PADK + kk;
                wmma::load_matrix_sync(fah, ap, PADK);
                wmma::load_matrix_sync(fal, ap + (ST_M / 2), PADK);
                #pragma unroll
                for (int ni = 0; ni < 2; ni++) {
                    wmma::mma_sync(acc[mi][ni], fah, fbh[ni], acc[mi][ni]);
                    wmma::mma_sync(acc[mi][ni], fah, fbl[ni], acc[mi][ni]);
                    wmma::mma_sync(acc[mi][ni], fal, fbh[ni], acc[mi][ni]);
                }
            }
        }
    }
    __syncthreads();

    // epilogue: scatter to q/k/v hi/lo planes
    float* patch = (float*)smem + wid * (16 * 20);
    const int r_loc = lane >> 1;
    const int c_loc = (lane & 1) * 8;

    #pragma unroll
    for (int mi = 0; mi < 4; mi++) {
        #pragma unroll
        for (int ni = 0; ni < 2; ni++) {
            wmma::store_matrix_sync(patch, acc[mi][ni], 20, wmma::mem_row_major);
            __syncwarp();
            int r  = m0 + wm * 64 + mi * 16 + r_loc;
            int cb = n0 + wn * 32 + ni * 16 + c_loc;
            float vv[8];
            #pragma unroll
            for (int j = 0; j < 8; j++)
                vv[j] = patch[r_loc * 20 + c_loc + j] + bias[cb + j];

            int b_  = r >> 10, tok = r & 1023;
            int s   = cb / Cq;
            int rem = cb - s * Cq;
            int h   = rem >> 6, d = rem & 63;
            __nv_bfloat16* dh = (s == 0) ? g_qh : ((s == 1) ? g_kh : g_vh);
            __nv_bfloat16* dl = (s == 0) ? g_ql : ((s == 1) ? g_kl : g_vl);
            size_t off = (size_t)(((b_ * Hq + h) << 16) + (tok << 6) + d);
            #pragma unroll
            for (int j = 0; j < 8; j += 2) {
                uint32_t hi, lo;
                split_pack(vv[j], vv[j + 1], hi, lo);
                *(uint32_t*)(dh + off + j) = hi;
                *(uint32_t*)(dl + off + j) = lo;
            }
            __syncwarp();
        }
    }
}

__global__ __launch_bounds__(256, 2) void proj_mm(const float* __restrict__ bias,
                                                  float* __restrict__ out)
{
    extern __shared__ __align__(16) char smem[];
    const uint32_t sb = smem_u32(smem);
    int tid  = threadIdx.x;
    int lane = tid & 31;
    int wid  = tid >> 5;
    int wm   = wid >> 2;
    int wn   = wid & 3;

    const int m0 = blockIdx.y * 128;
    const int n0 = blockIdx.x * 128;
    const __nv_bfloat16* Ah_g = g_ah;
    const __nv_bfloat16* Al_g = g_al;
    const __nv_bfloat16* Bh_g = g_wph;
    const __nv_bfloat16* Bl_g = g_wpl;

    const int lm  = tid >> 2;
    const int lkq = tid & 3;

    wmma::fragment<wmma::accumulator, 16, 16, 16, float> acc[4][2];
    #pragma unroll
    for (int mi = 0; mi < 4; mi++)
        #pragma unroll
        for (int ni = 0; ni < 2; ni++)
            wmma::fill_fragment(acc[mi][ni], 0.0f);

    #define PROJ_LOAD(CH, BUF) do {                                           \
        const int _k0 = (CH) * KCH;                                           \
        uint32_t _d = sb + (BUF) * STAGE;                                     \
        cp_async16(_d + OFF_AHI + lm * 80 + lkq * 16,                         \
                   Ah_g + (size_t)(m0 + lm) * 768 + _k0 + lkq * 8);           \
        cp_async16(_d + OFF_AHI + (lm + 64) * 80 + lkq * 16,                  \
                   Ah_g + (size_t)(m0 + lm + 64) * 768 + _k0 + lkq * 8);      \
        cp_async16(_d + OFF_ALO + lm * 80 + lkq * 16,                         \
                   Al_g + (size_t)(m0 + lm) * 768 + _k0 + lkq * 8);           \
        cp_async16(_d + OFF_ALO + (lm + 64) * 80 + lkq * 16,                  \
                   Al_g + (size_t)(m0 + lm + 64) * 768 + _k0 + lkq * 8);      \
        cp_async16(_d + OFF_BHI + lm * 80 + lkq * 16,                         \
                   Bh_g + (size_t)(n0 + lm) * 768 + _k0 + lkq * 8);           \
        cp_async16(_d + OFF_BHI + (lm + 64) * 80 + lkq * 16,                  \
                   Bh_g + (size_t)(n0 + lm + 64) * 768 + _k0 + lkq * 8);      \
        cp_async16(_d + OFF_BLO + lm * 80 + lkq * 16,                         \
                   Bl_g + (size_t)(n0 + lm) * 768 + _k0 + lkq * 8);           \
        cp_async16(_d + OFF_BLO + (lm + 64) * 80 + lkq * 16,                  \
                   Bl_g + (size_t)(n0 + lm + 64) * 768 + _k0 + lkq * 8);      \
        CP_COMMIT();                                                          \
    } while (0)

    PROJ_LOAD(0, 0);

    const int NCH = 768 / KCH;
    for (int ch = 0; ch < NCH; ch++) {
        CP_WAIT0();
        __syncthreads();
        if (ch + 1 < NCH) PROJ_LOAD(ch + 1, (ch + 1) & 1);

        char* cb_ = smem + (ch & 1) * STAGE;
        const __nv_bfloat16* Ah = (const __nv_bfloat16*)(cb_ + OFF_AHI);
        const __nv_bfloat16* Bh = (const __nv_bfloat16*)(cb_ + OFF_BHI);
        #pragma unroll
        for (int ks = 0; ks < 2; ks++) {
            const int kk = ks * 16;
            wmma::fragment<wmma::matrix_b, 16, 16, 16, __nv_bfloat16, wmma::col_major> fbh[2], fbl[2];
            #pragma unroll
            for (int ni = 0; ni < 2; ni++) {
                const __nv_bfloat16* bp = Bh + (wn * 32 + ni * 16) * PADK + kk;
                wmma::load_matrix_sync(fbh[ni], bp, PADK);
                wmma::load_matrix_sync(fbl[ni], bp + (ST_M / 2), PADK);
            }
            #pragma unroll
            for (int mi = 0; mi < 4; mi++) {
                wmma::fragment<wmma::matrix_a, 16, 16, 16, __nv_bfloat16, wmma::row_major> fah, fal;
                const __nv_bfloat16* ap = Ah + (wm * 64 + mi * 16) * PADK + kk;
                wmma::load_matrix_sync(fah, ap, PADK);
                wmma::load_matrix_sync(fal, ap + (ST_M / 2), PADK);
                #pragma unroll
                for (int ni = 0; ni < 2; ni++) {
                    wmma::mma_sync(acc[mi][ni], fah, fbh[ni], acc[mi][ni]);
                    wmma::mma_sync(acc[mi][ni], fah, fbl[ni], acc[mi][ni]);
                    wmma::mma_sync(acc[mi][ni], fal, fbh[ni], acc[mi][ni]);
                }
            }
        }
    }
    __syncthreads();

    float* patch = (float*)smem + wid * (16 * 20);
    const int r_loc = lane >> 1;
    const int c_loc = (lane & 1) * 8;

    #pragma unroll
    for (int mi = 0; mi < 4; mi++) {
        #pragma unroll
        for (int ni = 0; ni < 2; ni++) {
            wmma::store_matrix_sync(patch, acc[mi][ni], 20, wmma::mem_row_major);
            __syncwarp();
            int r  = m0 + wm * 64 + mi * 16 + r_loc;
            int cb = n0 + wn * 32 + ni * 16 + c_loc;
            float* obase = out + (size_t)r * Cq + cb;
            #pragma unroll
            for (int j = 0; j < 8; j += 2) {
                float v0 = patch[r_loc * 20 + c_loc + j]     + bias[cb + j];
                float v1 = patch[r_loc * 20 + c_loc + j + 1] + bias[cb + j + 1];
                *(float2*)(obase + j) = make_float2(v0, v1);
            }
            __syncwarp();
        }
    }
}

// =====================================================================
// RoPE on q/k hi/lo planes (in place) — unchanged.
// =====================================================================
__global__ void rope_kernel(const int* __restrict__ pos_h,
                            const int* __restrict__ pos_w)
{
    int idx = blockIdx.x * blockDim.x + threadIdx.x;
    int j    = idx & 15;
    int half = (idx >> 4) & 1;
    int tok  = (idx >> 5) & 1023;
    int rest = idx >> 15;
    if (rest >= 2 * BH) return;
    int bh   = rest % BH;
    int tens = rest / BH;
    int b_ = bh / Hq;
    int pos = half ? pos_w[b_ * Nq + tok] : pos_h[b_ * Nq + tok];
    float fp = (float)pos;
    size_t base = ((size_t)bh << 16) + (tok << 6) + half * 32;
    __nv_bfloat16* ph = (tens ? g_kh : g_qh) + base;
    __nv_bfloat16* pl = (tens ? g_kl : g_ql) + base;
    float t0 = __bfloat162float(ph[j])      + __bfloat162float(pl[j]);
    float t1 = __bfloat162float(ph[j + 16]) + __bfloat162float(pl[j + 16]);
    float L = logf(10000.0f);
    float inv0 = expf(-(float)(j >> 1)       / 16.0f * L);
    float inv1 = expf(-(float)(8 + (j >> 1)) / 16.0f * L);
    float s0, c0, s1, c1;
    sincosf(fp * inv0, &s0, &c0);
    sincosf(fp * inv1, &s1, &c1);
    float r0 = t0 * c0 - t1 * s0;
    float r1 = t1 * c1 + t0 * s1;
    __nv_bfloat16 h0 = __float2bfloat16_rn(r0);
    __nv_bfloat16 h1 = __float2bfloat16_rn(r1);
    ph[j]      = h0;
    pl[j]      = __float2bfloat16_rn(r0 - __bfloat162float(h0));
    ph[j + 16] = h1;
    pl[j + 16] = __float2bfloat16_rn(r1 - __bfloat162float(h1));
}

// =====================================================================
// FA2 flash attention on raw mma.sync — unchanged from round 14.
// =====================================================================
#define APITCH 72

__global__ __launch_bounds__(256) void attn_mma()
{
    __shared__ __nv_bfloat16 sbuf[4 * 64 * APITCH];   // 36864 B

    const int tid  = threadIdx.x;
    const int lane = tid & 31;
    const int wid  = tid >> 5;
    const int bh   = blockIdx.y;
    const int q0   = blockIdx.x * 128;
    const size_t hb = (size_t)bh << 16;
    const __nv_bfloat16* Qh_g = g_qh + hb;
    const __nv_bfloat16* Ql_g = g_ql + hb;
    const __nv_bfloat16* Kh_g = g_kh + hb;
    const __nv_bfloat16* Kl_g = g_kl + hb;
    const __nv_bfloat16* Vh_g = g_vh + hb;
    const __nv_bfloat16* Vl_g = g_vl + hb;

    const uint32_t sb = smem_u32(sbuf);
    const uint32_t qa_off = (uint32_t)((lane & 15) * APITCH + 8 * (lane >> 4)) * 2;
    const uint32_t kb_off = (uint32_t)((lane & 7) * APITCH + 8 * ((lane >> 3) & 1)) * 2;
    const uint32_t vb_off = (uint32_t)(((lane & 7) + 8 * ((lane >> 3) & 1)) * APITCH) * 2;

    #pragma unroll
    for (int it = 0; it < 4; it++) {
        int idx = tid + it * 256;
        int m = idx >> 3, kq = idx & 7;
        *(uint4*)((char*)sbuf + (m * APITCH + kq * 8) * 2) =
            *(const uint4*)(Qh_g + (size_t)(q0 + m) * 64 + kq * 8);
        *(uint4*)((char*)sbuf + (9216 + m * APITCH + kq * 8) * 2) =
            *(const uint4*)(Ql_g + (size_t)(q0 + m) * 64 + kq * 8);
    }
    __syncthreads();

    uint32_t qh[4][4], ql[4][4];
    {
        uint32_t qbase = sb + (uint32_t)(wid * 16 * APITCH) * 2 + qa_off;
        #pragma unroll
        for (int j = 0; j < 4; j++) {
            ldsm4(qh[j], qbase + (uint32_t)(16 * j) * 2);
            ldsm4(ql[j], qbase + (uint32_t)(9216 + 16 * j) * 2);
        }
    }
    __syncthreads();

    const uint32_t KhiB = sb;
    const uint32_t VhiB = sb + 9216 * 2;

    float o[8][4] = {};
    float m0 = -INFINITY, m1 = -INFINITY, l0 = 0.0f, l1 = 0.0f;

    for (int t = 0; t < 16; t++) {
        const int kt0 = t * 64;
        #pragma unroll
        for (int it = 0; it < 2; it++) {
            int idx = tid + it * 256;
            int c = idx >> 3, kq = idx & 7;
            size_t src = (size_t)(kt0 + c) * 64 + kq * 8;
            uint32_t d0 = (uint32_t)(c * APITCH + kq * 8) * 2;
            *(uint4*)((char*)sbuf + d0)             = *(const uint4*)(Kh_g + src);
            *(uint4*)((char*)sbuf + d0 + 4608 * 2)  = *(const uint4*)(Kl_g + src);
            *(uint4*)((char*)sbuf + d0 + 9216 * 2)  = *(const uint4*)(Vh_g + src);
            *(uint4*)((char*)sbuf + d0 + 13824 * 2) = *(const uint4*)(Vl_g + src);
        }
        __syncthreads();

        float s_[8][4];
        #pragma unroll
        for (int n = 0; n < 8; n++) {
            s_[n][0] = 0.0f; s_[n][1] = 0.0f; s_[n][2] = 0.0f; s_[n][3] = 0.0f;
        }
        #pragma unroll
        for (int j = 0; j < 4; j++) {
            #pragma unroll
            for (int n = 0; n < 8; n++) {
                uint32_t kbh[2], kbl[2];
                uint32_t addr = KhiB + (uint32_t)(n * 8 * APITCH + 16 * j) * 2 + kb_off;
                ldsm2(kbh, addr);
                ldsm2(kbl, addr + 4608 * 2);
                mma_bf16(s_[n], qh[j], kbh);
                mma_bf16(s_[n], qh[j], kbl);
                mma_bf16(s_[n], ql[j], kbh);
            }
        }

        float mx0 = -INFINITY, mx1 = -INFINITY;
        #pragma unroll
        for (int n = 0; n < 8; n++) {
            mx0 = fmaxf(mx0, fmaxf(s_[n][0], s_[n][1]));
            mx1 = fmaxf(mx1, fmaxf(s_[n][2], s_[n][3]));
        }
        mx0 = fmaxf(mx0, __shfl_xor_sync(0xffffffffu, mx0, 1));
        mx0 = fmaxf(mx0, __shfl_xor_sync(0xffffffffu, mx0, 2));
        mx1 = fmaxf(mx1, __shfl_xor_sync(0xffffffffu, mx1, 1));
        mx1 = fmaxf(mx1, __shfl_xor_sync(0xffffffffu, mx1, 2));
        float mn0 = fmaxf(m0, mx0), mn1 = fmaxf(m1, mx1);
        float al0 = __expf(0.125f * (m0 - mn0));
        float al1 = __expf(0.125f * (m1 - mn1));
        m0 = mn0; m1 = mn1;

        float sum0 = 0.0f, sum1 = 0.0f;
        #pragma unroll
        for (int n = 0; n < 8; n++) {
            s_[n][0] = __expf(0.125f * (s_[n][0] - mn0));
            s_[n][1] = __expf(0.125f * (s_[n][1] - mn0));
            s_[n][2] = __expf(0.125f * (s_[n][2] - mn1));
            s_[n][3] = __expf(0.125f * (s_[n][3] - mn1));
            sum0 += s_[n][0] + s_[n][1];
            sum1 += s_[n][2] + s_[n][3];
        }
        sum0 += __shfl_xor_sync(0xffffffffu, sum0, 1);
        sum0 += __shfl_xor_sync(0xffffffffu, sum0, 2);
        sum1 += __shfl_xor_sync(0xffffffffu, sum1, 1);
        sum1 += __shfl_xor_sync(0xffffffffu, sum1, 2);
        l0 = l0 * al0 + sum0;
        l1 = l1 * al1 + sum1;

        #pragma unroll
        for (int n = 0; n < 8; n++) {
            o[n][0] *= al0; o[n][1] *= al0;
            o[n][2] *= al1; o[n][3] *= al1;
        }

        #pragma unroll
        for (int j = 0; j < 4; j++) {
            uint32_t pah[4], pal[4];
            split_pack(s_[2*j][0],     s_[2*j][1],     pah[0], pal[0]);
            split_pack(s_[2*j][2],     s_[2*j][3],     pah[1], pal[1]);
            split_pack(s_[2*j + 1][0], s_[2*j + 1][1], pah[2], pal[2]);
            split_pack(s_[2*j + 1][2], s_[2*j + 1][3], pah[3], pal[3]);
            #pragma unroll
            for (int n = 0; n < 8; n++) {
                uint32_t vbh[2], vbl[2];
                uint32_t addr = VhiB + (uint32_t)(16 * j * APITCH + 8 * n) * 2 + vb_off;
                ldsm2_t(vbh, addr);
                ldsm2_t(vbl, addr + 4608 * 2);
                mma_bf16(o[n], pah, vbh);
                mma_bf16(o[n], pah, vbl);
                mma_bf16(o[n], pal, vbh);
            }
        }
        __syncthreads();
    }

    const int b_ = bh / Hq, h = bh % Hq;
    const int r0 = q0 + wid * 16 + (lane >> 2);
    const float inv0 = 1.0f / l0;
    const float inv1 = 1.0f / l1;
    #pragma unroll
    for (int n = 0; n < 8; n++) {
        int col = h * 64 + 8 * n + 2 * (lane & 3);
        size_t off0 = (size_t)(b_ * Nq + r0) * Cq + col;
        size_t off1 = (size_t)(b_ * Nq + r0 + 8) * Cq + col;
        uint32_t hi, lo;
        split_pack(o[n][0] * inv0, o[n][1] * inv0, hi, lo);
        *(uint32_t*)(g_ah + off0) = hi;
        *(uint32_t*)(g_al + off0) = lo;
        split_pack(o[n][2] * inv1, o[n][3] * inv1, hi, lo);
        *(uint32_t*)(g_ah + off1) = hi;
        *(uint32_t*)(g_al + off1) = lo;
    }
}

// =====================================================================
extern "C" void kernel_launch(void* const* d_in, const int* in_sizes, int n_in,
                              void* d_out, int out_size)
{
    const float* x      = (const float*)d_in[0];
    const float* W_qkv  = (const float*)d_in[1];
    const float* b_qkv  = (const float*)d_in[2];
    const float* W_proj = (const float*)d_in[3];
    const float* b_proj = (const float*)d_in[4];
    const int*   pos_h  = (const int*)d_in[5];
    const int*   pos_w  = (const int*)d_in[6];
    float*       out    = (float*)d_out;

    cudaFuncSetAttribute(qkv_mm,
                         cudaFuncAttributeMaxDynamicSharedMemorySize,
                         (int)MM2_SMEM);
    cudaFuncSetAttribute(proj_mm,
                         cudaFuncAttributeMaxDynamicSharedMemorySize,
                         (int)MM2_SMEM);

    convert_x<<<(MROWS * Cq / 2) / 256, 256>>>(x);
    convert_w<<<dim3(2304 / 32, 768 / 32), 256>>>(W_qkv, 3 * Cq, 0);
    convert_w<<<dim3(768 / 32, 768 / 32), 256>>>(W_proj, Cq, 1);
    qkv_mm<<<dim3(18, 128), 256, MM2_SMEM>>>(b_qkv);
    rope_kernel<<<(2 * BH * Nq * 32) / 256, 256>>>(pos_h, pos_w);
    attn_mma<<<dim3(8, 192), 256>>>();
    proj_mm<<<dim3(6, 128), 256, MM2_SMEM>>>(b_proj, out);
}

// round 16
// speedup vs baseline: 2.8677x; 1.0890x over previous
#include <cuda_runtime.h>
#include <cuda_bf16.h>
#include <mma.h>
#include <math.h>
#include <stdint.h>

using namespace nvcuda;

#define Bq   16
#define Nq   1024
#define Cq   768
#define Hq   12
#define HD   64
#define BH   (Bq*Hq)        // 192
#define MROWS (Bq*Nq)       // 16384

// ---- scratch (no allocs allowed): bf16 hi/lo planes everywhere ----
__device__ __nv_bfloat16 g_xh[MROWS * Cq], g_xl[MROWS * Cq];
__device__ __nv_bfloat16 g_qh[BH*Nq*HD], g_ql[BH*Nq*HD];
__device__ __nv_bfloat16 g_kh[BH*Nq*HD], g_kl[BH*Nq*HD];
__device__ __nv_bfloat16 g_vh[BH*Nq*HD], g_vl[BH*Nq*HD];
__device__ __nv_bfloat16 g_ah[MROWS * Cq], g_al[MROWS * Cq];
__device__ __nv_bfloat16 g_wqh[2304 * Cq], g_wql[2304 * Cq];
__device__ __nv_bfloat16 g_wph[Cq * Cq],   g_wpl[Cq * Cq];

__device__ __forceinline__ void split_pack(float x0, float x1,
                                           uint32_t& hi, uint32_t& lo) {
    __nv_bfloat16 h0 = __float2bfloat16_rn(x0);
    __nv_bfloat16 h1 = __float2bfloat16_rn(x1);
    __nv_bfloat16 l0 = __float2bfloat16_rn(x0 - __bfloat162float(h0));
    __nv_bfloat16 l1 = __float2bfloat16_rn(x1 - __bfloat162float(h1));
    hi = (uint32_t)__bfloat16_as_ushort(h0) | ((uint32_t)__bfloat16_as_ushort(h1) << 16);
    lo = (uint32_t)__bfloat16_as_ushort(l0) | ((uint32_t)__bfloat16_as_ushort(l1) << 16);
}

// ---- helpers ----
__device__ __forceinline__ uint32_t smem_u32(const void* p) {
    uint32_t a;
    asm("{ .reg .u64 t; cvta.to.shared.u64 t, %1; cvt.u32.u64 %0, t; }"
        : "=r"(a) : "l"(p));
    return a;
}
__device__ __forceinline__ void cp_async16(uint32_t dst, const void* src) {
    asm volatile("cp.async.cg.shared.global [%0], [%1], 16;"
                 :: "r"(dst), "l"(src));
}
#define CP_COMMIT() asm volatile("cp.async.commit_group;")
#define CP_WAIT0()  asm volatile("cp.async.wait_group 0;")

__device__ __forceinline__ void ldsm4(uint32_t* r, uint32_t a) {
    asm volatile("ldmatrix.sync.aligned.m8n8.x4.shared.b16 {%0,%1,%2,%3}, [%4];"
                 : "=r"(r[0]), "=r"(r[1]), "=r"(r[2]), "=r"(r[3]) : "r"(a));
}
__device__ __forceinline__ void ldsm2(uint32_t* r, uint32_t a) {
    asm volatile("ldmatrix.sync.aligned.m8n8.x2.shared.b16 {%0,%1}, [%2];"
                 : "=r"(r[0]), "=r"(r[1]) : "r"(a));
}
__device__ __forceinline__ void ldsm2_t(uint32_t* r, uint32_t a) {
    asm volatile("ldmatrix.sync.aligned.m8n8.x2.trans.shared.b16 {%0,%1}, [%2];"
                 : "=r"(r[0]), "=r"(r[1]) : "r"(a));
}
__device__ __forceinline__ void mma_bf16(float* c, const uint32_t* a, const uint32_t* b) {
    asm volatile(
        "mma.sync.aligned.m16n8k16.row.col.f32.bf16.bf16.f32 "
        "{%0,%1,%2,%3}, {%4,%5,%6,%7}, {%8,%9}, {%0,%1,%2,%3};"
        : "+f"(c[0]), "+f"(c[1]), "+f"(c[2]), "+f"(c[3])
        : "r"(a[0]), "r"(a[1]), "r"(a[2]), "r"(a[3]), "r"(b[0]), "r"(b[1]));
}

// =====================================================================
// Prologue converts — unchanged.
// =====================================================================
__global__ __launch_bounds__(256) void convert_x(const float* __restrict__ x)
{
    int idx = blockIdx.x * 256 + threadIdx.x;
    float2 v = *(const float2*)(x + 2 * (size_t)idx);
    uint32_t hi, lo;
    split_pack(v.x, v.y, hi, lo);
    ((uint32_t*)g_xh)[idx] = hi;
    ((uint32_t*)g_xl)[idx] = lo;
}

__global__ __launch_bounds__(256) void convert_w(const float* __restrict__ W,
                                                 int NN, int which)
{
    __shared__ float tile[32][33];
    int n0 = blockIdx.x * 32;
    int k0 = blockIdx.y * 32;
    int tx = threadIdx.x & 31;
    int ty = threadIdx.x >> 5;
    #pragma unroll
    for (int i = 0; i < 4; i++)
        tile[ty + 8 * i][tx] = W[(size_t)(k0 + ty + 8 * i) * NN + n0 + tx];
    __syncthreads();
    __nv_bfloat16* dh = which ? g_wph : g_wqh;
    __nv_bfloat16* dl = which ? g_wpl : g_wql;
    #pragma unroll
    for (int i = 0; i < 4; i++) {
        int n = ty + 8 * i;
        float v = tile[tx][n];
        __nv_bfloat16 h = __float2bfloat16_rn(v);
        __nv_bfloat16 l = __float2bfloat16_rn(v - __bfloat162float(h));
        size_t off = (size_t)(n0 + n) * 768 + k0 + tx;
        dh[off] = h;
        dl[off] = l;
    }
}

// =====================================================================
// bf16x3 WMMA GEMMs, cp.async double-buffered — unchanged (round 15).
// =====================================================================
#define KCH  32
#define PADK 40
#define ST_M  (128 * PADK * 2)
#define STAGE (4 * ST_M)
#define OFF_AHI 0
#define OFF_ALO (ST_M)
#define OFF_BHI (2 * ST_M)
#define OFF_BLO (3 * ST_M)
#define MM2_SMEM (2 * STAGE)            // 81920 bytes dynamic

__global__ __launch_bounds__(256, 2) void qkv_mm(const float* __restrict__ bias)
{
    extern __shared__ __align__(16) char smem[];
    const uint32_t sb = smem_u32(smem);
    int tid  = threadIdx.x;
    int lane = tid & 31;
    int wid  = tid >> 5;
    int wm   = wid >> 2;
    int wn   = wid & 3;

    const int m0 = blockIdx.y * 128;
    const int n0 = blockIdx.x * 128;
    const __nv_bfloat16* Ah_g = g_xh;
    const __nv_bfloat16* Al_g = g_xl;
    const __nv_bfloat16* Bh_g = g_wqh;
    const __nv_bfloat16* Bl_g = g_wql;

    const int lm  = tid >> 2;
    const int lkq = tid & 3;

    wmma::fragment<wmma::accumulator, 16, 16, 16, float> acc[4][2];
    #pragma unroll
    for (int mi = 0; mi < 4; mi++)
        #pragma unroll
        for (int ni = 0; ni < 2; ni++)
            wmma::fill_fragment(acc[mi][ni], 0.0f);

    #define QKV_LOAD(CH, BUF) do {                                            \
        const int _k0 = (CH) * KCH;                                           \
        uint32_t _d = sb + (BUF) * STAGE;                                     \
        cp_async16(_d + OFF_AHI + lm * 80 + lkq * 16,                         \
                   Ah_g + (size_t)(m0 + lm) * 768 + _k0 + lkq * 8);           \
        cp_async16(_d + OFF_AHI + (lm + 64) * 80 + lkq * 16,                  \
                   Ah_g + (size_t)(m0 + lm + 64) * 768 + _k0 + lkq * 8);      \
        cp_async16(_d + OFF_ALO + lm * 80 + lkq * 16,                         \
                   Al_g + (size_t)(m0 + lm) * 768 + _k0 + lkq * 8);           \
        cp_async16(_d + OFF_ALO + (lm + 64) * 80 + lkq * 16,                  \
                   Al_g + (size_t)(m0 + lm + 64) * 768 + _k0 + lkq * 8);      \
        cp_async16(_d + OFF_BHI + lm * 80 + lkq * 16,                         \
                   Bh_g + (size_t)(n0 + lm) * 768 + _k0 + lkq * 8);           \
        cp_async16(_d + OFF_BHI + (lm + 64) * 80 + lkq * 16,                  \
                   Bh_g + (size_t)(n0 + lm + 64) * 768 + _k0 + lkq * 8);      \
        cp_async16(_d + OFF_BLO + lm * 80 + lkq * 16,                         \
                   Bl_g + (size_t)(n0 + lm) * 768 + _k0 + lkq * 8);           \
        cp_async16(_d + OFF_BLO + (lm + 64) * 80 + lkq * 16,                  \
                   Bl_g + (size_t)(n0 + lm + 64) * 768 + _k0 + lkq * 8);      \
        CP_COMMIT();                                                          \
    } while (0)

    QKV_LOAD(0, 0);

    const int NCH = 768 / KCH;   // 24
    for (int ch = 0; ch < NCH; ch++) {
        CP_WAIT0();
        __syncthreads();
        if (ch + 1 < NCH) QKV_LOAD(ch + 1, (ch + 1) & 1);

        char* cb_ = smem + (ch & 1) * STAGE;
        const __nv_bfloat16* Ah = (const __nv_bfloat16*)(cb_ + OFF_AHI);
        const __nv_bfloat16* Bh = (const __nv_bfloat16*)(cb_ + OFF_BHI);
        #pragma unroll
        for (int ks = 0; ks < 2; ks++) {
            const int kk = ks * 16;
            wmma::fragment<wmma::matrix_b, 16, 16, 16, __nv_bfloat16, wmma::col_major> fbh[2], fbl[2];
            #pragma unroll
            for (int ni = 0; ni < 2; ni++) {
                const __nv_bfloat16* bp = Bh + (wn * 32 + ni * 16) * PADK + kk;
                wmma::load_matrix_sync(fbh[ni], bp, PADK);
                wmma::load_matrix_sync(fbl[ni], bp + (ST_M / 2), PADK);
            }
            #pragma unroll
            for (int mi = 0; mi < 4; mi++) {
                wmma::fragment<wmma::matrix_a, 16, 16, 16, __nv_bfloat16, wmma::row_major> fah, fal;
                const __nv_bfloat16* ap = Ah + (wm * 64 + mi * 16) * PADK + kk;
                wmma::load_matrix_sync(fah, ap, PADK);
                wmma::load_matrix_sync(fal, ap + (ST_M / 2), PADK);
                #pragma unroll
                for (int ni = 0; ni < 2; ni++) {
                    wmma::mma_sync(acc[mi][ni], fah, fbh[ni], acc[mi][ni]);
                    wmma::mma_sync(acc[mi][ni], fah, fbl[ni], acc[mi][ni]);
                    wmma::mma_sync(acc[mi][ni], fal, fbh[ni], acc[mi][ni]);
                }
            }
        }
    }
    __syncthreads();

    float* patch = (float*)smem + wid * (16 * 20);
    const int r_loc = lane >> 1;
    const int c_loc = (lane & 1) * 8;

    #pragma unroll
    for (int mi = 0; mi < 4; mi++) {
        #pragma unroll
        for (int ni = 0; ni < 2; ni++) {
            wmma::store_matrix_sync(patch, acc[mi][ni], 20, wmma::mem_row_major);
            __syncwarp();
            int r  = m0 + wm * 64 + mi * 16 + r_loc;
            int cb = n0 + wn * 32 + ni * 16 + c_loc;
            float vv[8];
            #pragma unroll
            for (int j = 0; j < 8; j++)
                vv[j] = patch[r_loc * 20 + c_loc + j] + bias[cb + j];

            int b_  = r >> 10, tok = r & 1023;
            int s   = cb / Cq;
            int rem = cb - s * Cq;
            int h   = rem >> 6, d = rem & 63;
            __nv_bfloat16* dh = (s == 0) ? g_qh : ((s == 1) ? g_kh : g_vh);
            __nv_bfloat16* dl = (s == 0) ? g_ql : ((s == 1) ? g_kl : g_vl);
            size_t off = (size_t)(((b_ * Hq + h) << 16) + (tok << 6) + d);
            #pragma unroll
            for (int j = 0; j < 8; j += 2) {
                uint32_t hi, lo;
                split_pack(vv[j], vv[j + 1], hi, lo);
                *(uint32_t*)(dh + off + j) = hi;
                *(uint32_t*)(dl + off + j) = lo;
            }
            __syncwarp();
        }
    }
}

__global__ __launch_bounds__(256, 2) void proj_mm(const float* __restrict__ bias,
                                                  float* __restrict__ out)
{
    extern __shared__ __align__(16) char smem[];
    const uint32_t sb = smem_u32(smem);
    int tid  = threadIdx.x;
    int lane = tid & 31;
    int wid  = tid >> 5;
    int wm   = wid >> 2;
    int wn   = wid & 3;

    const int m0 = blockIdx.y * 128;
    const int n0 = blockIdx.x * 128;
    const __nv_bfloat16* Ah_g = g_ah;
    const __nv_bfloat16* Al_g = g_al;
    const __nv_bfloat16* Bh_g = g_wph;
    const __nv_bfloat16* Bl_g = g_wpl;

    const int lm  = tid >> 2;
    const int lkq = tid & 3;

    wmma::fragment<wmma::accumulator, 16, 16, 16, float> acc[4][2];
    #pragma unroll
    for (int mi = 0; mi < 4; mi++)
        #pragma unroll
        for (int ni = 0; ni < 2; ni++)
            wmma::fill_fragment(acc[mi][ni], 0.0f);

    #define PROJ_LOAD(CH, BUF) do {                                           \
        const int _k0 = (CH) * KCH;                                           \
        uint32_t _d = sb + (BUF) * STAGE;                                     \
        cp_async16(_d + OFF_AHI + lm * 80 + lkq * 16,                         \
                   Ah_g + (size_t)(m0 + lm) * 768 + _k0 + lkq * 8);           \
        cp_async16(_d + OFF_AHI + (lm + 64) * 80 + lkq * 16,                  \
                   Ah_g + (size_t)(m0 + lm + 64) * 768 + _k0 + lkq * 8);      \
        cp_async16(_d + OFF_ALO + lm * 80 + lkq * 16,                         \
                   Al_g + (size_t)(m0 + lm) * 768 + _k0 + lkq * 8);           \
        cp_async16(_d + OFF_ALO + (lm + 64) * 80 + lkq * 16,                  \
                   Al_g + (size_t)(m0 + lm + 64) * 768 + _k0 + lkq * 8);      \
        cp_async16(_d + OFF_BHI + lm * 80 + lkq * 16,                         \
                   Bh_g + (size_t)(n0 + lm) * 768 + _k0 + lkq * 8);           \
        cp_async16(_d + OFF_BHI + (lm + 64) * 80 + lkq * 16,                  \
                   Bh_g + (size_t)(n0 + lm + 64) * 768 + _k0 + lkq * 8);      \
        cp_async16(_d + OFF_BLO + lm * 80 + lkq * 16,                         \
                   Bl_g + (size_t)(n0 + lm) * 768 + _k0 + lkq * 8);           \
        cp_async16(_d + OFF_BLO + (lm + 64) * 80 + lkq * 16,                  \
                   Bl_g + (size_t)(n0 + lm + 64) * 768 + _k0 + lkq * 8);      \
        CP_COMMIT();                                                          \
    } while (0)

    PROJ_LOAD(0, 0);

    const int NCH = 768 / KCH;
    for (int ch = 0; ch < NCH; ch++) {
        CP_WAIT0();
        __syncthreads();
        if (ch + 1 < NCH) PROJ_LOAD(ch + 1, (ch + 1) & 1);

        char* cb_ = smem + (ch & 1) * STAGE;
        const __nv_bfloat16* Ah = (const __nv_bfloat16*)(cb_ + OFF_AHI);
        const __nv_bfloat16* Bh = (const __nv_bfloat16*)(cb_ + OFF_BHI);
        #pragma unroll
        for (int ks = 0; ks < 2; ks++) {
            const int kk = ks * 16;
            wmma::fragment<wmma::matrix_b, 16, 16, 16, __nv_bfloat16, wmma::col_major> fbh[2], fbl[2];
            #pragma unroll
            for (int ni = 0; ni < 2; ni++) {
                const __nv_bfloat16* bp = Bh + (wn * 32 + ni * 16) * PADK + kk;
                wmma::load_matrix_sync(fbh[ni], bp, PADK);
                wmma::load_matrix_sync(fbl[ni], bp + (ST_M / 2), PADK);
            }
            #pragma unroll
            for (int mi = 0; mi < 4; mi++) {
                wmma::fragment<wmma::matrix_a, 16, 16, 16, __nv_bfloat16, wmma::row_major> fah, fal;
                const __nv_bfloat16* ap = Ah + (wm * 64 + mi * 16) * PADK + kk;
                wmma::load_matrix_sync(fah, ap, PADK);
                wmma::load_matrix_sync(fal, ap + (ST_M / 2), PADK);
                #pragma unroll
                for (int ni = 0; ni < 2; ni++) {
                    wmma::mma_sync(acc[mi][ni], fah, fbh[ni], acc[mi][ni]);
                    wmma::mma_sync(acc[mi][ni], fah, fbl[ni], acc[mi][ni]);
                    wmma::mma_sync(acc[mi][ni], fal, fbh[ni], acc[mi][ni]);
                }
            }
        }
    }
    __syncthreads();

    float* patch = (float*)smem + wid * (16 * 20);
    const int r_loc = lane >> 1;
    const int c_loc = (lane & 1) * 8;

    #pragma unroll
    for (int mi = 0; mi < 4; mi++) {
        #pragma unroll
        for (int ni = 0; ni < 2; ni++) {
            wmma::store_matrix_sync(patch, acc[mi][ni], 20, wmma::mem_row_major);
            __syncwarp();
            int r  = m0 + wm * 64 + mi * 16 + r_loc;
            int cb = n0 + wn * 32 + ni * 16 + c_loc;
            float* obase = out + (size_t)r * Cq + cb;
            #pragma unroll
            for (int j = 0; j < 8; j += 2) {
                float v0 = patch[r_loc * 20 + c_loc + j]     + bias[cb + j];
                float v1 = patch[r_loc * 20 + c_loc + j + 1] + bias[cb + j + 1];
                *(float2*)(obase + j) = make_float2(v0, v1);
            }
            __syncwarp();
        }
    }
}

// =====================================================================
// RoPE on q/k hi/lo planes (in place) — unchanged.
// =====================================================================
__global__ void rope_kernel(const int* __restrict__ pos_h,
                            const int* __restrict__ pos_w)
{
    int idx = blockIdx.x * blockDim.x + threadIdx.x;
    int j    = idx & 15;
    int half = (idx >> 4) & 1;
    int tok  = (idx >> 5) & 1023;
    int rest = idx >> 15;
    if (rest >= 2 * BH) return;
    int bh   = rest % BH;
    int tens = rest / BH;
    int b_ = bh / Hq;
    int pos = half ? pos_w[b_ * Nq + tok] : pos_h[b_ * Nq + tok];
    float fp = (float)pos;
    size_t base = ((size_t)bh << 16) + (tok << 6) + half * 32;
    __nv_bfloat16* ph = (tens ? g_kh : g_qh) + base;
    __nv_bfloat16* pl = (tens ? g_kl : g_ql) + base;
    float t0 = __bfloat162float(ph[j])      + __bfloat162float(pl[j]);
    float t1 = __bfloat162float(ph[j + 16]) + __bfloat162float(pl[j + 16]);
    float L = logf(10000.0f);
    float inv0 = expf(-(float)(j >> 1)       / 16.0f * L);
    float inv1 = expf(-(float)(8 + (j >> 1)) / 16.0f * L);
    float s0, c0, s1, c1;
    sincosf(fp * inv0, &s0, &c0);
    sincosf(fp * inv1, &s1, &c1);
    float r0 = t0 * c0 - t1 * s0;
    float r1 = t1 * c1 + t0 * s1;
    __nv_bfloat16 h0 = __float2bfloat16_rn(r0);
    __nv_bfloat16 h1 = __float2bfloat16_rn(r1);
    ph[j]      = h0;
    pl[j]      = __float2bfloat16_rn(r0 - __bfloat162float(h0));
    ph[j + 16] = h1;
    pl[j + 16] = __float2bfloat16_rn(r1 - __bfloat162float(h1));
}

// =====================================================================
// FA2 flash attention, cp.async DOUBLE-BUFFERED K/V stages.
// Stage = Khi|Klo|Vhi|Vlo, 64x72 bf16 each = 36864 B; 2 stages dynamic.
// One barrier per tile. Q staged once through stage 0.
// =====================================================================
#define APITCH 72
#define AST_PLANE (64 * APITCH)           // 4608 elems per plane
#define AST_ELEMS (4 * AST_PLANE)         // 18432 elems per stage
#define ATTN_SMEM2 (2 * AST_ELEMS * 2)    // 73728 bytes

__global__ __launch_bounds__(256, 2) void attn_mma()
{
    extern __shared__ __align__(16) __nv_bfloat16 sbuf[];

    const int tid  = threadIdx.x;
    const int lane = tid & 31;
    const int wid  = tid >> 5;
    const int bh   = blockIdx.y;
    const int q0   = blockIdx.x * 128;
    const size_t hb = (size_t)bh << 16;
    const __nv_bfloat16* Qh_g = g_qh + hb;
    const __nv_bfloat16* Ql_g = g_ql + hb;
    const __nv_bfloat16* Kh_g = g_kh + hb;
    const __nv_bfloat16* Kl_g = g_kl + hb;
    const __nv_bfloat16* Vh_g = g_vh + hb;
    const __nv_bfloat16* Vl_g = g_vl + hb;

    const uint32_t sb = smem_u32(sbuf);
    const uint32_t qa_off = (uint32_t)((lane & 15) * APITCH + 8 * (lane >> 4)) * 2;
    const uint32_t kb_off = (uint32_t)((lane & 7) * APITCH + 8 * ((lane >> 3) & 1)) * 2;
    const uint32_t vb_off = (uint32_t)(((lane & 7) + 8 * ((lane >> 3) & 1)) * APITCH) * 2;

    // ---- stage Q planes [128][64] through stage-0 area (once)
    #pragma unroll
    for (int it = 0; it < 4; it++) {
        int idx = tid + it * 256;
        int m = idx >> 3, kq = idx & 7;
        *(uint4*)((char*)sbuf + (m * APITCH + kq * 8) * 2) =
            *(const uint4*)(Qh_g + (size_t)(q0 + m) * 64 + kq * 8);
        *(uint4*)((char*)sbuf + ((2 * AST_PLANE) + m * APITCH + kq * 8) * 2) =
            *(const uint4*)(Ql_g + (size_t)(q0 + m) * 64 + kq * 8);
    }
    __syncthreads();

    uint32_t qh[4][4], ql[4][4];
    {
        uint32_t qbase = sb + (uint32_t)(wid * 16 * APITCH) * 2 + qa_off;
        #pragma unroll
        for (int j = 0; j < 4; j++) {
            ldsm4(qh[j], qbase + (uint32_t)(16 * j) * 2);
            ldsm4(ql[j], qbase + (uint32_t)(2 * AST_PLANE + 16 * j) * 2);
        }
    }
    __syncthreads();

    // K/V cp.async load of one tile into stage BUF
    const int lc  = tid >> 3;          // 0..31 (rows lc, lc+32)
    const int lkq = tid & 7;
    #define KV_LOAD(T, BUF) do {                                              \
        const int _kt0 = (T) * 64;                                            \
        uint32_t _d = sb + (BUF) * (AST_ELEMS * 2);                           \
        size_t _s0 = (size_t)(_kt0 + lc) * 64 + lkq * 8;                      \
        size_t _s1 = (size_t)(_kt0 + lc + 32) * 64 + lkq * 8;                 \
        uint32_t _o0 = (uint32_t)(lc * APITCH + lkq * 8) * 2;                 \
        uint32_t _o1 = (uint32_t)((lc + 32) * APITCH + lkq * 8) * 2;          \
        cp_async16(_d + _o0,                      Kh_g + _s0);                \
        cp_async16(_d + _o1,                      Kh_g + _s1);                \
        cp_async16(_d + _o0 + AST_PLANE * 2,      Kl_g + _s0);                \
        cp_async16(_d + _o1 + AST_PLANE * 2,      Kl_g + _s1);                \
        cp_async16(_d + _o0 + 2 * AST_PLANE * 2,  Vh_g + _s0);                \
        cp_async16(_d + _o1 + 2 * AST_PLANE * 2,  Vh_g + _s1);                \
        cp_async16(_d + _o0 + 3 * AST_PLANE * 2,  Vl_g + _s0);                \
        cp_async16(_d + _o1 + 3 * AST_PLANE * 2,  Vl_g + _s1);                \
        CP_COMMIT();                                                          \
    } while (0)

    KV_LOAD(0, 0);

    float o[8][4] = {};
    float m0 = -INFINITY, m1 = -INFINITY, l0 = 0.0f, l1 = 0.0f;

    for (int t = 0; t < 16; t++) {
        CP_WAIT0();
        __syncthreads();
        if (t + 1 < 16) KV_LOAD(t + 1, (t + 1) & 1);

        const uint32_t stg  = sb + (uint32_t)(t & 1) * (AST_ELEMS * 2);
        const uint32_t KhiB = stg;
        const uint32_t VhiB = stg + 2 * AST_PLANE * 2;

        // ---- S = Q @ K^T, bf16x3
        float s_[8][4];
        #pragma unroll
        for (int n = 0; n < 8; n++) {
            s_[n][0] = 0.0f; s_[n][1] = 0.0f; s_[n][2] = 0.0f; s_[n][3] = 0.0f;
        }
        #pragma unroll
        for (int j = 0; j < 4; j++) {
            #pragma unroll
            for (int n = 0; n < 8; n++) {
                uint32_t kbh[2], kbl[2];
                uint32_t addr = KhiB + (uint32_t)(n * 8 * APITCH + 16 * j) * 2 + kb_off;
                ldsm2(kbh, addr);
                ldsm2(kbl, addr + AST_PLANE * 2);
                mma_bf16(s_[n], qh[j], kbh);
                mma_bf16(s_[n], qh[j], kbl);
                mma_bf16(s_[n], ql[j], kbh);
            }
        }

        // ---- online softmax
        float mx0 = -INFINITY, mx1 = -INFINITY;
        #pragma unroll
        for (int n = 0; n < 8; n++) {
            mx0 = fmaxf(mx0, fmaxf(s_[n][0], s_[n][1]));
            mx1 = fmaxf(mx1, fmaxf(s_[n][2], s_[n][3]));
        }
        mx0 = fmaxf(mx0, __shfl_xor_sync(0xffffffffu, mx0, 1));
        mx0 = fmaxf(mx0, __shfl_xor_sync(0xffffffffu, mx0, 2));
        mx1 = fmaxf(mx1, __shfl_xor_sync(0xffffffffu, mx1, 1));
        mx1 = fmaxf(mx1, __shfl_xor_sync(0xffffffffu, mx1, 2));
        float mn0 = fmaxf(m0, mx0), mn1 = fmaxf(m1, mx1);
        float al0 = __expf(0.125f * (m0 - mn0));
        float al1 = __expf(0.125f * (m1 - mn1));
        m0 = mn0; m1 = mn1;

        float sum0 = 0.0f, sum1 = 0.0f;
        #pragma unroll
        for (int n = 0; n < 8; n++) {
            s_[n][0] = __expf(0.125f * (s_[n][0] - mn0));
            s_[n][1] = __expf(0.125f * (s_[n][1] - mn0));
            s_[n][2] = __expf(0.125f * (s_[n][2] - mn1));
            s_[n][3] = __expf(0.125f * (s_[n][3] - mn1));
            sum0 += s_[n][0] + s_[n][1];
            sum1 += s_[n][2] + s_[n][3];
        }
        sum0 += __shfl_xor_sync(0xffffffffu, sum0, 1);
        sum0 += __shfl_xor_sync(0xffffffffu, sum0, 2);
        sum1 += __shfl_xor_sync(0xffffffffu, sum1, 1);
        sum1 += __shfl_xor_sync(0xffffffffu, sum1, 2);
        l0 = l0 * al0 + sum0;
        l1 = l1 * al1 + sum1;

        #pragma unroll
        for (int n = 0; n < 8; n++) {
            o[n][0] *= al0; o[n][1] *= al0;
            o[n][2] *= al1; o[n][3] *= al1;
        }

        // ---- O += P @ V
        #pragma unroll
        for (int j = 0; j < 4; j++) {
            uint32_t pah[4], pal[4];
            split_pack(s_[2*j][0],     s_[2*j][1],     pah[0], pal[0]);
            split_pack(s_[2*j][2],     s_[2*j][3],     pah[1], pal[1]);
            split_pack(s_[2*j + 1][0], s_[2*j + 1][1], pah[2], pal[2]);
            split_pack(s_[2*j + 1][2], s_[2*j + 1][3], pah[3], pal[3]);
            #pragma unroll
            for (int n = 0; n < 8; n++) {
                uint32_t vbh[2], vbl[2];
                uint32_t addr = VhiB + (uint32_t)(16 * j * APITCH + 8 * n) * 2 + vb_off;
                ldsm2_t(vbh, addr);
                ldsm2_t(vbl, addr + AST_PLANE * 2);
                mma_bf16(o[n], pah, vbh);
                mma_bf16(o[n], pah, vbl);
                mma_bf16(o[n], pal, vbh);
            }
        }
    }

    // ---- normalize + write hi/lo planes
    const int b_ = bh / Hq, h = bh % Hq;
    const int r0 = q0 + wid * 16 + (lane >> 2);
    const float inv0 = 1.0f / l0;
    const float inv1 = 1.0f / l1;
    #pragma unroll
    for (int n = 0; n < 8; n++) {
        int col = h * 64 + 8 * n + 2 * (lane & 3);
        size_t off0 = (size_t)(b_ * Nq + r0) * Cq + col;
        size_t off1 = (size_t)(b_ * Nq + r0 + 8) * Cq + col;
        uint32_t hi, lo;
        split_pack(o[n][0] * inv0, o[n][1] * inv0, hi, lo);
        *(uint32_t*)(g_ah + off0) = hi;
        *(uint32_t*)(g_al + off0) = lo;
        split_pack(o[n][2] * inv1, o[n][3] * inv1, hi, lo);
        *(uint32_t*)(g_ah + off1) = hi;
        *(uint32_t*)(g_al + off1) = lo;
    }
}

// =====================================================================
extern "C" void kernel_launch(void* const* d_in, const int* in_sizes, int n_in,
                              void* d_out, int out_size)
{
    const float* x      = (const float*)d_in[0];
    const float* W_qkv  = (const float*)d_in[1];
    const float* b_qkv  = (const float*)d_in[2];
    const float* W_proj = (const float*)d_in[3];
    const float* b_proj = (const float*)d_in[4];
    const int*   pos_h  = (const int*)d_in[5];
    const int*   pos_w  = (const int*)d_in[6];
    float*       out    = (float*)d_out;

    cudaFuncSetAttribute(qkv_mm,
                         cudaFuncAttributeMaxDynamicSharedMemorySize,
                         (int)MM2_SMEM);
    cudaFuncSetAttribute(proj_mm,
                         cudaFuncAttributeMaxDynamicSharedMemorySize,
                         (int)MM2_SMEM);
    cudaFuncSetAttribute(attn_mma,
                         cudaFuncAttributeMaxDynamicSharedMemorySize,
                         (int)ATTN_SMEM2);

    convert_x<<<(MROWS * Cq / 2) / 256, 256>>>(x);
    convert_w<<<dim3(2304 / 32, 768 / 32), 256>>>(W_qkv, 3 * Cq, 0);
    convert_w<<<dim3(768 / 32, 768 / 32), 256>>>(W_proj, Cq, 1);
    qkv_mm<<<dim3(18, 128), 256, MM2_SMEM>>>(b_qkv);
    rope_kernel<<<(2 * BH * Nq * 32) / 256, 256>>>(pos_h, pos_w);
    attn_mma<<<dim3(8, 192), 256, ATTN_SMEM2>>>();
    proj_mm<<<dim3(6, 128), 256, MM2_SMEM>>>(b_proj, out);
}

// round 17
// speedup vs baseline: 3.2586x; 1.1363x over previous
#include <cuda_runtime.h>
#include <cuda_bf16.h>
#include <math.h>
#include <stdint.h>

#define Bq   16
#define Nq   1024
#define Cq   768
#define Hq   12
#define HD   64
#define BH   (Bq*Hq)        // 192
#define MROWS (Bq*Nq)       // 16384

// ---- scratch (no allocs allowed): bf16 hi/lo planes everywhere ----
__device__ __nv_bfloat16 g_xh[MROWS * Cq], g_xl[MROWS * Cq];
__device__ __nv_bfloat16 g_qh[BH*Nq*HD], g_ql[BH*Nq*HD];
__device__ __nv_bfloat16 g_kh[BH*Nq*HD], g_kl[BH*Nq*HD];
__device__ __nv_bfloat16 g_vh[BH*Nq*HD], g_vl[BH*Nq*HD];
__device__ __nv_bfloat16 g_ah[MROWS * Cq], g_al[MROWS * Cq];
__device__ __nv_bfloat16 g_wqh[2304 * Cq], g_wql[2304 * Cq];
__device__ __nv_bfloat16 g_wph[Cq * Cq],   g_wpl[Cq * Cq];

__device__ __forceinline__ void split_pack(float x0, float x1,
                                           uint32_t& hi, uint32_t& lo) {
    __nv_bfloat16 h0 = __float2bfloat16_rn(x0);
    __nv_bfloat16 h1 = __float2bfloat16_rn(x1);
    __nv_bfloat16 l0 = __float2bfloat16_rn(x0 - __bfloat162float(h0));
    __nv_bfloat16 l1 = __float2bfloat16_rn(x1 - __bfloat162float(h1));
    hi = (uint32_t)__bfloat16_as_ushort(h0) | ((uint32_t)__bfloat16_as_ushort(h1) << 16);
    lo = (uint32_t)__bfloat16_as_ushort(l0) | ((uint32_t)__bfloat16_as_ushort(l1) << 16);
}

// ---- helpers ----
__device__ __forceinline__ uint32_t smem_u32(const void* p) {
    uint32_t a;
    asm("{ .reg .u64 t; cvta.to.shared.u64 t, %1; cvt.u32.u64 %0, t; }"
        : "=r"(a) : "l"(p));
    return a;
}
__device__ __forceinline__ void cp_async16(uint32_t dst, const void* src) {
    asm volatile("cp.async.cg.shared.global [%0], [%1], 16;"
                 :: "r"(dst), "l"(src));
}
#define CP_COMMIT() asm volatile("cp.async.commit_group;")
#define CP_WAIT0()  asm volatile("cp.async.wait_group 0;")

__device__ __forceinline__ void ldsm4(uint32_t* r, uint32_t a) {
    asm volatile("ldmatrix.sync.aligned.m8n8.x4.shared.b16 {%0,%1,%2,%3}, [%4];"
                 : "=r"(r[0]), "=r"(r[1]), "=r"(r[2]), "=r"(r[3]) : "r"(a));
}
__device__ __forceinline__ void ldsm2(uint32_t* r, uint32_t a) {
    asm volatile("ldmatrix.sync.aligned.m8n8.x2.shared.b16 {%0,%1}, [%2];"
                 : "=r"(r[0]), "=r"(r[1]) : "r"(a));
}
__device__ __forceinline__ void ldsm2_t(uint32_t* r, uint32_t a) {
    asm volatile("ldmatrix.sync.aligned.m8n8.x2.trans.shared.b16 {%0,%1}, [%2];"
                 : "=r"(r[0]), "=r"(r[1]) : "r"(a));
}
__device__ __forceinline__ void mma_bf16(float* c, const uint32_t* a, const uint32_t* b) {
    asm volatile(
        "mma.sync.aligned.m16n8k16.row.col.f32.bf16.bf16.f32 "
        "{%0,%1,%2,%3}, {%4,%5,%6,%7}, {%8,%9}, {%0,%1,%2,%3};"
        : "+f"(c[0]), "+f"(c[1]), "+f"(c[2]), "+f"(c[3])
        : "r"(a[0]), "r"(a[1]), "r"(a[2]), "r"(a[3]), "r"(b[0]), "r"(b[1]));
}

// =====================================================================
// Prologue converts — unchanged.
// =====================================================================
__global__ __launch_bounds__(256) void convert_x(const float* __restrict__ x)
{
    int idx = blockIdx.x * 256 + threadIdx.x;
    float2 v = *(const float2*)(x + 2 * (size_t)idx);
    uint32_t hi, lo;
    split_pack(v.x, v.y, hi, lo);
    ((uint32_t*)g_xh)[idx] = hi;
    ((uint32_t*)g_xl)[idx] = lo;
}

__global__ __launch_bounds__(256) void convert_w(const float* __restrict__ W,
                                                 int NN, int which)
{
    __shared__ float tile[32][33];
    int n0 = blockIdx.x * 32;
    int k0 = blockIdx.y * 32;
    int tx = threadIdx.x & 31;
    int ty = threadIdx.x >> 5;
    #pragma unroll
    for (int i = 0; i < 4; i++)
        tile[ty + 8 * i][tx] = W[(size_t)(k0 + ty + 8 * i) * NN + n0 + tx];
    __syncthreads();
    __nv_bfloat16* dh = which ? g_wph : g_wqh;
    __nv_bfloat16* dl = which ? g_wpl : g_wql;
    #pragma unroll
    for (int i = 0; i < 4; i++) {
        int n = ty + 8 * i;
        float v = tile[tx][n];
        __nv_bfloat16 h = __float2bfloat16_rn(v);
        __nv_bfloat16 l = __float2bfloat16_rn(v - __bfloat162float(h));
        size_t off = (size_t)(n0 + n) * 768 + k0 + tx;
        dh[off] = h;
        dl[off] = l;
    }
}

// =====================================================================
// bf16x3 GEMMs on RAW mma.sync + ldmatrix. cp.async double-buffered.
// Tile 128x128, chunk 32; warp tile 64x32 = 4(m16) x 4(n8).
// Direct register->global epilogue (no smem patch).
// =====================================================================
#define KCH  32
#define PADK 40
#define ROWB (PADK * 2)                 // 80 bytes per row
#define ST_M  (128 * ROWB)              // 10240 bytes per matrix
#define STAGE (4 * ST_M)
#define OFF_AHI 0
#define OFF_ALO (ST_M)
#define OFF_BHI (2 * ST_M)
#define OFF_BLO (3 * ST_M)
#define MM2_SMEM (2 * STAGE)            // 81920 bytes dynamic

__global__ __launch_bounds__(256, 2) void qkv_mm(const float* __restrict__ bias)
{
    extern __shared__ __align__(16) char smem[];
    const uint32_t sb = smem_u32(smem);
    int tid  = threadIdx.x;
    int lane = tid & 31;
    int wid  = tid >> 5;
    int wm   = wid >> 2;       // 0..1
    int wn   = wid & 3;        // 0..3

    const int m0 = blockIdx.y * 128;
    const int n0 = blockIdx.x * 128;
    const __nv_bfloat16* Ah_g = g_xh;
    const __nv_bfloat16* Al_g = g_xl;
    const __nv_bfloat16* Bh_g = g_wqh;
    const __nv_bfloat16* Bl_g = g_wql;

    const int lm  = tid >> 2;
    const int lkq = tid & 3;

    // ldmatrix per-lane offsets (bytes)
    const uint32_t a_off = (uint32_t)((lane & 15) * ROWB + (lane >> 4) * 16);
    const uint32_t b_off = (uint32_t)(((lane & 7) + ((lane >> 4) & 1) * 8) * ROWB
                                      + ((lane >> 3) & 1) * 16);

    float acc[4][4][4] = {};

    #define QKV_LOAD(CH, BUF) do {                                            \
        const int _k0 = (CH) * KCH;                                           \
        uint32_t _d = sb + (BUF) * STAGE;                                     \
        cp_async16(_d + OFF_AHI + lm * 80 + lkq * 16,                         \
                   Ah_g + (size_t)(m0 + lm) * 768 + _k0 + lkq * 8);           \
        cp_async16(_d + OFF_AHI + (lm + 64) * 80 + lkq * 16,                  \
                   Ah_g + (size_t)(m0 + lm + 64) * 768 + _k0 + lkq * 8);      \
        cp_async16(_d + OFF_ALO + lm * 80 + lkq * 16,                         \
                   Al_g + (size_t)(m0 + lm) * 768 + _k0 + lkq * 8);           \
        cp_async16(_d + OFF_ALO + (lm + 64) * 80 + lkq * 16,                  \
                   Al_g + (size_t)(m0 + lm + 64) * 768 + _k0 + lkq * 8);      \
        cp_async16(_d + OFF_BHI + lm * 80 + lkq * 16,                         \
                   Bh_g + (size_t)(n0 + lm) * 768 + _k0 + lkq * 8);           \
        cp_async16(_d + OFF_BHI + (lm + 64) * 80 + lkq * 16,                  \
                   Bh_g + (size_t)(n0 + lm + 64) * 768 + _k0 + lkq * 8);      \
        cp_async16(_d + OFF_BLO + lm * 80 + lkq * 16,                         \
                   Bl_g + (size_t)(n0 + lm) * 768 + _k0 + lkq * 8);           \
        cp_async16(_d + OFF_BLO + (lm + 64) * 80 + lkq * 16,                  \
                   Bl_g + (size_t)(n0 + lm + 64) * 768 + _k0 + lkq * 8);      \
        CP_COMMIT();                                                          \
    } while (0)

    QKV_LOAD(0, 0);

    const int NCH = 768 / KCH;   // 24
    for (int ch = 0; ch < NCH; ch++) {
        CP_WAIT0();
        __syncthreads();
        if (ch + 1 < NCH) QKV_LOAD(ch + 1, (ch + 1) & 1);

        const uint32_t base = sb + (uint32_t)(ch & 1) * STAGE;
        #pragma unroll
        for (int ks = 0; ks < 2; ks++) {
            const uint32_t kkb = ks * 32;         // 16 elems * 2B
            // B fragments: 2 ldsm4 cover nj 0..3, hi and lo
            uint32_t bh_[4][2], bl_[4][2];
            #pragma unroll
            for (int p = 0; p < 2; p++) {
                uint32_t r[4];
                uint32_t addr = base + OFF_BHI
                    + (uint32_t)((wn * 32 + p * 16) * ROWB) + kkb + b_off;
                ldsm4(r, addr);
                bh_[2*p][0] = r[0]; bh_[2*p][1] = r[1];
                bh_[2*p+1][0] = r[2]; bh_[2*p+1][1] = r[3];
                ldsm4(r, addr + (OFF_BLO - OFF_BHI));
                bl_[2*p][0] = r[0]; bl_[2*p][1] = r[1];
                bl_[2*p+1][0] = r[2]; bl_[2*p+1][1] = r[3];
            }
            #pragma unroll
            for (int mi = 0; mi < 4; mi++) {
                uint32_t ah[4], al[4];
                uint32_t addr = base + OFF_AHI
                    + (uint32_t)((wm * 64 + mi * 16) * ROWB) + kkb + a_off;
                ldsm4(ah, addr);
                ldsm4(al, addr + (OFF_ALO - OFF_AHI));
                #pragma unroll
                for (int nj = 0; nj < 4; nj++) {
                    mma_bf16(acc[mi][nj], ah, bh_[nj]);
                    mma_bf16(acc[mi][nj], ah, bl_[nj]);
                    mma_bf16(acc[mi][nj], al, bh_[nj]);
                }
            }
        }
    }

    // ---- direct epilogue: scatter to q/k/v hi/lo planes
    #pragma unroll
    for (int nj = 0; nj < 4; nj++) {
        int col = n0 + wn * 32 + nj * 8 + 2 * (lane & 3);
        float b0 = bias[col], b1 = bias[col + 1];
        int s   = col / Cq;
        int rem = col - s * Cq;
        int h   = rem >> 6, d = rem & 63;
        __nv_bfloat16* dh = (s == 0) ? g_qh : ((s == 1) ? g_kh : g_vh);
        __nv_bfloat16* dl = (s == 0) ? g_ql : ((s == 1) ? g_kl : g_vl);
        #pragma unroll
        for (int mi = 0; mi < 4; mi++) {
            int r = m0 + wm * 64 + mi * 16 + (lane >> 2);
            #pragma unroll
            for (int half = 0; half < 2; half++) {
                int rr = r + half * 8;
                int b_ = rr >> 10, tok = rr & 1023;
                size_t off = (size_t)(((b_ * Hq + h) << 16) + (tok << 6) + d);
                uint32_t hi, lo;
                split_pack(acc[mi][nj][2*half] + b0, acc[mi][nj][2*half+1] + b1, hi, lo);
                *(uint32_t*)(dh + off) = hi;
                *(uint32_t*)(dl + off) = lo;
            }
        }
    }
}

__global__ __launch_bounds__(256, 2) void proj_mm(const float* __restrict__ bias,
                                                  float* __restrict__ out)
{
    extern __shared__ __align__(16) char smem[];
    const uint32_t sb = smem_u32(smem);
    int tid  = threadIdx.x;
    int lane = tid & 31;
    int wid  = tid >> 5;
    int wm   = wid >> 2;
    int wn   = wid & 3;

    const int m0 = blockIdx.y * 128;
    const int n0 = blockIdx.x * 128;
    const __nv_bfloat16* Ah_g = g_ah;
    const __nv_bfloat16* Al_g = g_al;
    const __nv_bfloat16* Bh_g = g_wph;
    const __nv_bfloat16* Bl_g = g_wpl;

    const int lm  = tid >> 2;
    const int lkq = tid & 3;

    const uint32_t a_off = (uint32_t)((lane & 15) * ROWB + (lane >> 4) * 16);
    const uint32_t b_off = (uint32_t)(((lane & 7) + ((lane >> 4) & 1) * 8) * ROWB
                                      + ((lane >> 3) & 1) * 16);

    float acc[4][4][4] = {};

    #define PROJ_LOAD(CH, BUF) do {                                           \
        const int _k0 = (CH) * KCH;                                           \
        uint32_t _d = sb + (BUF) * STAGE;                                     \
        cp_async16(_d + OFF_AHI + lm * 80 + lkq * 16,                         \
                   Ah_g + (size_t)(m0 + lm) * 768 + _k0 + lkq * 8);           \
        cp_async16(_d + OFF_AHI + (lm + 64) * 80 + lkq * 16,                  \
                   Ah_g + (size_t)(m0 + lm + 64) * 768 + _k0 + lkq * 8);      \
        cp_async16(_d + OFF_ALO + lm * 80 + lkq * 16,                         \
                   Al_g + (size_t)(m0 + lm) * 768 + _k0 + lkq * 8);           \
        cp_async16(_d + OFF_ALO + (lm + 64) * 80 + lkq * 16,                  \
                   Al_g + (size_t)(m0 + lm + 64) * 768 + _k0 + lkq * 8);      \
        cp_async16(_d + OFF_BHI + lm * 80 + lkq * 16,                         \
                   Bh_g + (size_t)(n0 + lm) * 768 + _k0 + lkq * 8);           \
        cp_async16(_d + OFF_BHI + (lm + 64) * 80 + lkq * 16,                  \
                   Bh_g + (size_t)(n0 + lm + 64) * 768 + _k0 + lkq * 8);      \
        cp_async16(_d + OFF_BLO + lm * 80 + lkq * 16,                         \
                   Bl_g + (size_t)(n0 + lm) * 768 + _k0 + lkq * 8);           \
        cp_async16(_d + OFF_BLO + (lm + 64) * 80 + lkq * 16,                  \
                   Bl_g + (size_t)(n0 + lm + 64) * 768 + _k0 + lkq * 8);      \
        CP_COMMIT();                                                          \
    } while (0)

    PROJ_LOAD(0, 0);

    const int NCH = 768 / KCH;
    for (int ch = 0; ch < NCH; ch++) {
        CP_WAIT0();
        __syncthreads();
        if (ch + 1 < NCH) PROJ_LOAD(ch + 1, (ch + 1) & 1);

        const uint32_t base = sb + (uint32_t)(ch & 1) * STAGE;
        #pragma unroll
        for (int ks = 0; ks < 2; ks++) {
            const uint32_t kkb = ks * 32;
            uint32_t bh_[4][2], bl_[4][2];
            #pragma unroll
            for (int p = 0; p < 2; p++) {
                uint32_t r[4];
                uint32_t addr = base + OFF_BHI
                    + (uint32_t)((wn * 32 + p * 16) * ROWB) + kkb + b_off;
                ldsm4(r, addr);
                bh_[2*p][0] = r[0]; bh_[2*p][1] = r[1];
                bh_[2*p+1][0] = r[2]; bh_[2*p+1][1] = r[3];
                ldsm4(r, addr + (OFF_BLO - OFF_BHI));
                bl_[2*p][0] = r[0]; bl_[2*p][1] = r[1];
                bl_[2*p+1][0] = r[2]; bl_[2*p+1][1] = r[3];
            }
            #pragma unroll
            for (int mi = 0; mi < 4; mi++) {
                uint32_t ah[4], al[4];
                uint32_t addr = base + OFF_AHI
                    + (uint32_t)((wm * 64 + mi * 16) * ROWB) + kkb + a_off;
                ldsm4(ah, addr);
                ldsm4(al, addr + (OFF_ALO - OFF_AHI));
                #pragma unroll
                for (int nj = 0; nj < 4; nj++) {
                    mma_bf16(acc[mi][nj], ah, bh_[nj]);
                    mma_bf16(acc[mi][nj], ah, bl_[nj]);
                    mma_bf16(acc[mi][nj], al, bh_[nj]);
                }
            }
        }
    }

    // ---- direct epilogue
    #pragma unroll
    for (int nj = 0; nj < 4; nj++) {
        int col = n0 + wn * 32 + nj * 8 + 2 * (lane & 3);
        float b0 = bias[col], b1 = bias[col + 1];
        #pragma unroll
        for (int mi = 0; mi < 4; mi++) {
            int r = m0 + wm * 64 + mi * 16 + (lane >> 2);
            *(float2*)(out + (size_t)r * Cq + col) =
                make_float2(acc[mi][nj][0] + b0, acc[mi][nj][1] + b1);
            *(float2*)(out + (size_t)(r + 8) * Cq + col) =
                make_float2(acc[mi][nj][2] + b0, acc[mi][nj][3] + b1);
        }
    }
}

// =====================================================================
// RoPE on q/k hi/lo planes (in place) — unchanged.
// =====================================================================
__global__ void rope_kernel(const int* __restrict__ pos_h,
                            const int* __restrict__ pos_w)
{
    int idx = blockIdx.x * blockDim.x + threadIdx.x;
    int j    = idx & 15;
    int half = (idx >> 4) & 1;
    int tok  = (idx >> 5) & 1023;
    int rest = idx >> 15;
    if (rest >= 2 * BH) return;
    int bh   = rest % BH;
    int tens = rest / BH;
    int b_ = bh / Hq;
    int pos = half ? pos_w[b_ * Nq + tok] : pos_h[b_ * Nq + tok];
    float fp = (float)pos;
    size_t base = ((size_t)bh << 16) + (tok << 6) + half * 32;
    __nv_bfloat16* ph = (tens ? g_kh : g_qh) + base;
    __nv_bfloat16* pl = (tens ? g_kl : g_ql) + base;
    float t0 = __bfloat162float(ph[j])      + __bfloat162float(pl[j]);
    float t1 = __bfloat162float(ph[j + 16]) + __bfloat162float(pl[j + 16]);
    float L = logf(10000.0f);
    float inv0 = expf(-(float)(j >> 1)       / 16.0f * L);
    float inv1 = expf(-(float)(8 + (j >> 1)) / 16.0f * L);
    float s0, c0, s1, c1;
    sincosf(fp * inv0, &s0, &c0);
    sincosf(fp * inv1, &s1, &c1);
    float r0 = t0 * c0 - t1 * s0;
    float r1 = t1 * c1 + t0 * s1;
    __nv_bfloat16 h0 = __float2bfloat16_rn(r0);
    __nv_bfloat16 h1 = __float2bfloat16_rn(r1);
    ph[j]      = h0;
    pl[j]      = __float2bfloat16_rn(r0 - __bfloat162float(h0));
    ph[j + 16] = h1;
    pl[j + 16] = __float2bfloat16_rn(r1 - __bfloat162float(h1));
}

// =====================================================================
// FA2 flash attention, cp.async double-buffered — unchanged (round 16).
// =====================================================================
#define APITCH 72
#define AST_PLANE (64 * APITCH)
#define AST_ELEMS (4 * AST_PLANE)
#define ATTN_SMEM2 (2 * AST_ELEMS * 2)    // 73728 bytes

__global__ __launch_bounds__(256, 2) void attn_mma()
{
    extern __shared__ __align__(16) __nv_bfloat16 sbuf[];

    const int tid  = threadIdx.x;
    const int lane = tid & 31;
    const int wid  = tid >> 5;
    const int bh   = blockIdx.y;
    const int q0   = blockIdx.x * 128;
    const size_t hb = (size_t)bh << 16;
    const __nv_bfloat16* Qh_g = g_qh + hb;
    const __nv_bfloat16* Ql_g = g_ql + hb;
    const __nv_bfloat16* Kh_g = g_kh + hb;
    const __nv_bfloat16* Kl_g = g_kl + hb;
    const __nv_bfloat16* Vh_g = g_vh + hb;
    const __nv_bfloat16* Vl_g = g_vl + hb;

    const uint32_t sb = smem_u32(sbuf);
    const uint32_t qa_off = (uint32_t)((lane & 15) * APITCH + 8 * (lane >> 4)) * 2;
    const uint32_t kb_off = (uint32_t)((lane & 7) * APITCH + 8 * ((lane >> 3) & 1)) * 2;
    const uint32_t vb_off = (uint32_t)(((lane & 7) + 8 * ((lane >> 3) & 1)) * APITCH) * 2;

    #pragma unroll
    for (int it = 0; it < 4; it++) {
        int idx = tid + it * 256;
        int m = idx >> 3, kq = idx & 7;
        *(uint4*)((char*)sbuf + (m * APITCH + kq * 8) * 2) =
            *(const uint4*)(Qh_g + (size_t)(q0 + m) * 64 + kq * 8);
        *(uint4*)((char*)sbuf + ((2 * AST_PLANE) + m * APITCH + kq * 8) * 2) =
            *(const uint4*)(Ql_g + (size_t)(q0 + m) * 64 + kq * 8);
    }
    __syncthreads();

    uint32_t qh[4][4], ql[4][4];
    {
        uint32_t qbase = sb + (uint32_t)(wid * 16 * APITCH) * 2 + qa_off;
        #pragma unroll
        for (int j = 0; j < 4; j++) {
            ldsm4(qh[j], qbase + (uint32_t)(16 * j) * 2);
            ldsm4(ql[j], qbase + (uint32_t)(2 * AST_PLANE + 16 * j) * 2);
        }
    }
    __syncthreads();

    const int lc  = tid >> 3;
    const int lkq = tid & 7;
    #define KV_LOAD(T, BUF) do {                                              \
        const int _kt0 = (T) * 64;                                            \
        uint32_t _d = sb + (BUF) * (AST_ELEMS * 2);                           \
        size_t _s0 = (size_t)(_kt0 + lc) * 64 + lkq * 8;                      \
        size_t _s1 = (size_t)(_kt0 + lc + 32) * 64 + lkq * 8;                 \
        uint32_t _o0 = (uint32_t)(lc * APITCH + lkq * 8) * 2;                 \
        uint32_t _o1 = (uint32_t)((lc + 32) * APITCH + lkq * 8) * 2;          \
        cp_async16(_d + _o0,                      Kh_g + _s0);                \
        cp_async16(_d + _o1,                      Kh_g + _s1);                \
        cp_async16(_d + _o0 + AST_PLANE * 2,      Kl_g + _s0);                \
        cp_async16(_d + _o1 + AST_PLANE * 2,      Kl_g + _s1);                \
        cp_async16(_d + _o0 + 2 * AST_PLANE * 2,  Vh_g + _s0);                \
        cp_async16(_d + _o1 + 2 * AST_PLANE * 2,  Vh_g + _s1);                \
        cp_async16(_d + _o0 + 3 * AST_PLANE * 2,  Vl_g + _s0);                \
        cp_async16(_d + _o1 + 3 * AST_PLANE * 2,  Vl_g + _s1);                \
        CP_COMMIT();                                                          \
    } while (0)

    KV_LOAD(0, 0);

    float o[8][4] = {};
    float m0 = -INFINITY, m1 = -INFINITY, l0 = 0.0f, l1 = 0.0f;

    for (int t = 0; t < 16; t++) {
        CP_WAIT0();
        __syncthreads();
        if (t + 1 < 16) KV_LOAD(t + 1, (t + 1) & 1);

        const uint32_t stg  = sb + (uint32_t)(t & 1) * (AST_ELEMS * 2);
        const uint32_t KhiB = stg;
        const uint32_t VhiB = stg + 2 * AST_PLANE * 2;

        float s_[8][4];
        #pragma unroll
        for (int n = 0; n < 8; n++) {
            s_[n][0] = 0.0f; s_[n][1] = 0.0f; s_[n][2] = 0.0f; s_[n][3] = 0.0f;
        }
        #pragma unroll
        for (int j = 0; j < 4; j++) {
            #pragma unroll
            for (int n = 0; n < 8; n++) {
                uint32_t kbh[2], kbl[2];
                uint32_t addr = KhiB + (uint32_t)(n * 8 * APITCH + 16 * j) * 2 + kb_off;
                ldsm2(kbh, addr);
                ldsm2(kbl, addr + AST_PLANE * 2);
                mma_bf16(s_[n], qh[j], kbh);
                mma_bf16(s_[n], qh[j], kbl);
                mma_bf16(s_[n], ql[j], kbh);
            }
        }

        float mx0 = -INFINITY, mx1 = -INFINITY;
        #pragma unroll
        for (int n = 0; n < 8; n++) {
            mx0 = fmaxf(mx0, fmaxf(s_[n][0], s_[n][1]));
            mx1 = fmaxf(mx1, fmaxf(s_[n][2], s_[n][3]));
        }
        mx0 = fmaxf(mx0, __shfl_xor_sync(0xffffffffu, mx0, 1));
        mx0 = fmaxf(mx0, __shfl_xor_sync(0xffffffffu, mx0, 2));
        mx1 = fmaxf(mx1, __shfl_xor_sync(0xffffffffu, mx1, 1));
        mx1 = fmaxf(mx1, __shfl_xor_sync(0xffffffffu, mx1, 2));
        float mn0 = fmaxf(m0, mx0), mn1 = fmaxf(m1, mx1);
        float al0 = __expf(0.125f * (m0 - mn0));
        float al1 = __expf(0.125f * (m1 - mn1));
        m0 = mn0; m1 = mn1;

        float sum0 = 0.0f, sum1 = 0.0f;
        #pragma unroll
        for (int n = 0; n < 8; n++) {
            s_[n][0] = __expf(0.125f * (s_[n][0] - mn0));
            s_[n][1] = __expf(0.125f * (s_[n][1] - mn0));
            s_[n][2] = __expf(0.125f * (s_[n][2] - mn1));
            s_[n][3] = __expf(0.125f * (s_[n][3] - mn1));
            sum0 += s_[n][0] + s_[n][1];
            sum1 += s_[n][2] + s_[n][3];
        }
        sum0 += __shfl_xor_sync(0xffffffffu, sum0, 1);
        sum0 += __shfl_xor_sync(0xffffffffu, sum0, 2);
        sum1 += __shfl_xor_sync(0xffffffffu, sum1, 1);
        sum1 += __shfl_xor_sync(0xffffffffu, sum1, 2);
        l0 = l0 * al0 + sum0;
        l1 = l1 * al1 + sum1;

        #pragma unroll
        for (int n = 0; n < 8; n++) {
            o[n][0] *= al0; o[n][1] *= al0;
            o[n][2] *= al1; o[n][3] *= al1;
        }

        #pragma unroll
        for (int j = 0; j < 4; j++) {
            uint32_t pah[4], pal[4];
            split_pack(s_[2*j][0],     s_[2*j][1],     pah[0], pal[0]);
            split_pack(s_[2*j][2],     s_[2*j][3],     pah[1], pal[1]);
            split_pack(s_[2*j + 1][0], s_[2*j + 1][1], pah[2], pal[2]);
            split_pack(s_[2*j + 1][2], s_[2*j + 1][3], pah[3], pal[3]);
            #pragma unroll
            for (int n = 0; n < 8; n++) {
                uint32_t vbh[2], vbl[2];
                uint32_t addr = VhiB + (uint32_t)(16 * j * APITCH + 8 * n) * 2 + vb_off;
                ldsm2_t(vbh, addr);
                ldsm2_t(vbl, addr + AST_PLANE * 2);
                mma_bf16(o[n], pah, vbh);
                mma_bf16(o[n], pah, vbl);
                mma_bf16(o[n], pal, vbh);
            }
        }
    }

    const int b_ = bh / Hq, h = bh % Hq;
    const int r0 = q0 + wid * 16 + (lane >> 2);
    const float inv0 = 1.0f / l0;
    const float inv1 = 1.0f / l1;
    #pragma unroll
    for (int n = 0; n < 8; n++) {
        int col = h * 64 + 8 * n + 2 * (lane & 3);
        size_t off0 = (size_t)(b_ * Nq + r0) * Cq + col;
        size_t off1 = (size_t)(b_ * Nq + r0 + 8) * Cq + col;
        uint32_t hi, lo;
        split_pack(o[n][0] * inv0, o[n][1] * inv0, hi, lo);
        *(uint32_t*)(g_ah + off0) = hi;
        *(uint32_t*)(g_al + off0) = lo;
        split_pack(o[n][2] * inv1, o[n][3] * inv1, hi, lo);
        *(uint32_t*)(g_ah + off1) = hi;
        *(uint32_t*)(g_al + off1) = lo;
    }
}

// =====================================================================
extern "C" void kernel_launch(void* const* d_in, const int* in_sizes, int n_in,
                              void* d_out, int out_size)
{
    const float* x      = (const float*)d_in[0];
    const float* W_qkv  = (const float*)d_in[1];
    const float* b_qkv  = (const float*)d_in[2];
    const float* W_proj = (const float*)d_in[3];
    const float* b_proj = (const float*)d_in[4];
    const int*   pos_h  = (const int*)d_in[5];
    const int*   pos_w  = (const int*)d_in[6];
    float*       out    = (float*)d_out;

    cudaFuncSetAttribute(qkv_mm,
                         cudaFuncAttributeMaxDynamicSharedMemorySize,
                         (int)MM2_SMEM);
    cudaFuncSetAttribute(proj_mm,
                         cudaFuncAttributeMaxDynamicSharedMemorySize,
                         (int)MM2_SMEM);
    cudaFuncSetAttribute(attn_mma,
                         cudaFuncAttributeMaxDynamicSharedMemorySize,
                         (int)ATTN_SMEM2);

    convert_x<<<(MROWS * Cq / 2) / 256, 256>>>(x);
    convert_w<<<dim3(2304 / 32, 768 / 32), 256>>>(W_qkv, 3 * Cq, 0);
    convert_w<<<dim3(768 / 32, 768 / 32), 256>>>(W_proj, Cq, 1);
    qkv_mm<<<dim3(18, 128), 256, MM2_SMEM>>>(b_qkv);
    rope_kernel<<<(2 * BH * Nq * 32) / 256, 256>>>(pos_h, pos_w);
    attn_mma<<<dim3(8, 192), 256, ATTN_SMEM2>>>();
    proj_mm<<<dim3(6, 128), 256, MM2_SMEM>>>(b_proj, out);
}